// round 2
// baseline (speedup 1.0000x reference)
#include <cuda_runtime.h>
#include <cuda_bf16.h>
#include <math.h>

#define HID 1024
#define NH 4
#define DK 256
#define DV 256
#define CHUNK 32
#define TMAX 8192

// ---------------- scratch (static device buffers; no allocation) ----------------
__device__ float g_tmp  [TMAX*HID];
__device__ float g_q    [TMAX*HID];
__device__ float g_k    [TMAX*HID];
__device__ float g_v    [TMAX*HID];
__device__ float g_kb   [TMAX*HID];
__device__ float g_u    [TMAX*HID];
__device__ float g_w    [TMAX*HID];
__device__ float g_del  [TMAX*HID];
__device__ float g_ls   [TMAX*HID];
__device__ float g_ll   [TMAX*HID];
__device__ float g_g1   [TMAX*HID];
__device__ float g_om   [TMAX*HID];
__device__ float g_aloc [TMAX*NH*CHUNK];   // 32x32 per chunk per (b,h)
__device__ float g_beta [TMAX*NH];
__device__ float g_stats[TMAX*NH*16];
__device__ float g_probs[TMAX*NH*4];

// ---------------- SGEMM 128x128x8, fp32, 256 threads, 8x8 per thread ------------
__global__ __launch_bounds__(256) void sgemm128(
    const float* __restrict__ A, const float* __restrict__ B,
    float* __restrict__ C, int M, int N, int K)
{
    __shared__ float As[8][128];
    __shared__ float Bs[8][128];
    const int tid  = threadIdx.x;
    const int row0 = blockIdx.y * 128;
    const int col0 = blockIdx.x * 128;
    const int tx = tid & 15, ty = tid >> 4;
    const int aRow = tid >> 1, aCol = (tid & 1) * 4;
    const int bRow = tid >> 5, bCol = (tid & 31) * 4;
    float acc[8][8];
#pragma unroll
    for (int i = 0; i < 8; i++)
#pragma unroll
        for (int j = 0; j < 8; j++) acc[i][j] = 0.f;

    for (int k0 = 0; k0 < K; k0 += 8) {
        float4 av = *(const float4*)(A + (size_t)(row0 + aRow) * K + k0 + aCol);
        As[aCol+0][aRow] = av.x; As[aCol+1][aRow] = av.y;
        As[aCol+2][aRow] = av.z; As[aCol+3][aRow] = av.w;
        *(float4*)(&Bs[bRow][bCol]) =
            *(const float4*)(B + (size_t)(k0 + bRow) * N + col0 + bCol);
        __syncthreads();
#pragma unroll
        for (int kk = 0; kk < 8; ++kk) {
            float4 a0 = *(float4*)(&As[kk][ty*8]);
            float4 a1 = *(float4*)(&As[kk][ty*8+4]);
            float4 b0 = *(float4*)(&Bs[kk][tx*8]);
            float4 b1 = *(float4*)(&Bs[kk][tx*8+4]);
            float ar[8] = {a0.x,a0.y,a0.z,a0.w,a1.x,a1.y,a1.z,a1.w};
            float br[8] = {b0.x,b0.y,b0.z,b0.w,b1.x,b1.y,b1.z,b1.w};
#pragma unroll
            for (int i = 0; i < 8; i++)
#pragma unroll
                for (int j = 0; j < 8; j++) acc[i][j] += ar[i]*br[j];
        }
        __syncthreads();
    }
#pragma unroll
    for (int i = 0; i < 8; i++) {
        float* crow = C + (size_t)(row0 + ty*8 + i) * N + col0 + tx*8;
        *(float4*)crow     = make_float4(acc[i][0],acc[i][1],acc[i][2],acc[i][3]);
        *(float4*)(crow+4) = make_float4(acc[i][4],acc[i][5],acc[i][6],acc[i][7]);
    }
}

// ---------------- causal depthwise conv (+ optional SiLU) -----------------------
__global__ void conv_kernel(const float* __restrict__ x, const float* __restrict__ w,
                            float* __restrict__ y, int L, int K, int apply_silu, int total)
{
    int idx = blockIdx.x * blockDim.x + threadIdx.x;
    if (idx >= total) return;
    int c = idx % HID;
    int t = idx / HID;
    int b = t / L, l = t % L;
    float acc = 0.f;
#pragma unroll 4
    for (int kk = 0; kk < K; ++kk) {
        int ll = l - (K - 1) + kk;
        if (ll >= 0) acc += x[((size_t)(b*L + ll))*HID + c] * w[c*K + kk];
    }
    if (apply_silu) acc = acc / (1.f + expf(-acc));
    y[idx] = acc;
}

// ---------------- beta = sigmoid(hs @ Wb), warp per (t,h) -----------------------
__global__ void beta_kernel(const float* __restrict__ hs, const float* __restrict__ Wb,
                            float* __restrict__ beta, int T)
{
    int gw = (blockIdx.x * blockDim.x + threadIdx.x) >> 5;
    int lane = threadIdx.x & 31;
    if (gw >= T * NH) return;
    int t = gw / NH, h = gw % NH;
    float s = 0.f;
    for (int r = lane; r < HID; r += 32) s += hs[(size_t)t*HID + r] * Wb[r*NH + h];
#pragma unroll
    for (int off = 16; off; off >>= 1) s += __shfl_down_sync(0xffffffff, s, off);
    if (lane == 0) beta[t*NH + h] = 1.f / (1.f + expf(-s));
}

// ---------------- l2norm(q), l2norm(k), kb = k_hat * beta -----------------------
__global__ __launch_bounds__(256) void l2norm_kernel(
    float* __restrict__ Q, float* __restrict__ Kp, float* __restrict__ KB,
    const float* __restrict__ beta)
{
    int th = blockIdx.x;
    int t = th >> 2, h = th & 3;
    int d = threadIdx.x;
    size_t base = (size_t)t*HID + h*DK;
    float qv = Q[base + d], kv = Kp[base + d];
    __shared__ float sq[256], sk[256];
    sq[d] = qv*qv; sk[d] = kv*kv;
    __syncthreads();
    for (int s = 128; s > 0; s >>= 1) {
        if (d < s) { sq[d] += sq[d+s]; sk[d] += sk[d+s]; }
        __syncthreads();
    }
    float rq = rsqrtf(sq[0] + 1e-6f);
    float rk = rsqrtf(sk[0] + 1e-6f);
    float bb = beta[t*NH + h];
    Q[base + d]  = qv * rq;
    float kn = kv * rk;
    Kp[base + d] = kn;
    KB[base + d] = kn * bb;
}

// ---------------- per-chunk: attn inversion + u, w, attn_loc --------------------
__global__ __launch_bounds__(256) void chunk_kernel(
    const float* __restrict__ Qn, const float* __restrict__ Kn,
    const float* __restrict__ KB, const float* __restrict__ V,
    const float* __restrict__ beta, float* __restrict__ U,
    float* __restrict__ Wbuf, float* __restrict__ Aloc, int L)
{
    extern __shared__ float sm[];
    float* q_s  = sm;                 // 32*257
    float* kn_s = q_s  + 32*257;
    float* kb_s = kn_s + 32*257;
    float* A    = kb_s + 32*257;      // 32*33
    int nch = L / CHUNK;
    int cid = blockIdx.x;
    int ch = cid % nch;
    int h  = (cid / nch) & (NH - 1);
    int b  = cid / (nch * NH);
    int l0 = ch * CHUNK;
    int tid = threadIdx.x;
    size_t base = ((size_t)(b*L + l0)) * HID + h*DK;

    for (int r = 0; r < 32; ++r) {
        size_t g = base + (size_t)r*HID + tid;
        q_s [r*257 + tid] = Qn[g];
        kn_s[r*257 + tid] = Kn[g];
        kb_s[r*257 + tid] = KB[g];
    }
    __syncthreads();

    size_t abase = (size_t)cid * (CHUNK*CHUNK);
#pragma unroll
    for (int r = 0; r < 4; ++r) {
        int e = r*256 + tid;
        int i = e >> 5, j = e & 31;
        float sA = 0.f, sL = 0.f;
        if (i > j)
            for (int d = 0; d < 256; ++d) sA += kb_s[i*257+d] * kn_s[j*257+d];
        if (j <= i)
            for (int d = 0; d < 256; ++d) sL += q_s[i*257+d] * kn_s[j*257+d];
        A[i*33 + j] = (i > j) ? -sA : 0.f;
        Aloc[abase + e] = (j <= i) ? sL : 0.f;
    }
    __syncthreads();

    // exact sequential row-inversion recurrence (one warp)
    if (tid < 32) {
        int j = tid;
        for (int i = 1; i < 32; ++i) {
            float s = 0.f;
            if (j < i) {
#pragma unroll
                for (int t2 = 0; t2 < 32; ++t2) s += A[i*33 + t2] * A[t2*33 + j];
            }
            __syncwarp();
            if (j < i) A[i*33 + j] += s;
            __syncwarp();
        }
        A[j*33 + j] += 1.f;   // attn_inv = result + I
    }
    __syncthreads();

    // v * beta into q_s (reuse)
    for (int r = 0; r < 32; ++r) {
        float bb = beta[(b*L + l0 + r)*NH + h];
        q_s[r*257 + tid] = V[base + (size_t)r*HID + tid] * bb;
    }
    __syncthreads();

    // u = Ainv @ (v*beta), w = Ainv @ kb   (thread = column d)
    for (int i = 0; i < 32; ++i) {
        float su = 0.f, sw = 0.f;
#pragma unroll
        for (int t2 = 0; t2 < 32; ++t2) {
            float a = A[i*33 + t2];
            su += a * q_s [t2*257 + tid];
            sw += a * kb_s[t2*257 + tid];
        }
        U   [base + (size_t)i*HID + tid] = su;
        Wbuf[base + (size_t)i*HID + tid] = sw;
    }
}

// ---------------- sequential chunk scan; S slice kept in registers --------------
#define SPITCH 33
__global__ __launch_bounds__(256) void scan_kernel(
    const float* __restrict__ Qn, const float* __restrict__ Kn,
    const float* __restrict__ U,  const float* __restrict__ Wbuf,
    const float* __restrict__ Aloc, float* __restrict__ Dout, int L)
{
    extern __shared__ float sm[];
    float* Ssm = sm;                  // 256*33
    float* q_s = Ssm + 256*SPITCH;    // 32*257
    float* k_s = q_s + 32*257;
    float* w_s = k_s + 32*257;
    float* al  = w_s + 32*257;        // 32*33
    float* ul  = al  + 32*33;         // 32*33

    int cb = blockIdx.x;              // dv column block (32 cols)
    int bh = blockIdx.y;
    int b = bh >> 2, h = bh & 3;
    int tid = threadIdx.x;
    int c  = tid & 31;
    int iw = tid >> 5;                // 0..7
    int nch = L / CHUNK;

    float Sreg[32];                   // S[d][c] for d = r*8+iw
#pragma unroll
    for (int r = 0; r < 32; ++r) Sreg[r] = 0.f;

    for (int ch = 0; ch < nch; ++ch) {
        int l0 = ch * CHUNK;
        size_t base = ((size_t)(b*L + l0)) * HID + h*DK;

        // refresh S image in smem
#pragma unroll
        for (int r = 0; r < 32; ++r) Ssm[(r*8 + iw)*SPITCH + c] = Sreg[r];
        for (int r = 0; r < 32; ++r) {
            size_t g = base + (size_t)r*HID + tid;
            q_s[r*257 + tid] = Qn[g];
            k_s[r*257 + tid] = Kn[g];
            w_s[r*257 + tid] = Wbuf[g];
        }
        size_t abase = (size_t)((b*NH + h)*nch + ch) * 1024;
#pragma unroll
        for (int r = 0; r < 4; ++r)
            al[(r*8 + iw)*33 + c] = Aloc[abase + r*256 + tid];

        float uacc[4];
#pragma unroll
        for (int r = 0; r < 4; ++r)
            uacc[r] = U[((size_t)(b*L + l0 + (r*8 + iw)))*HID + h*DV + cb*32 + c];
        __syncthreads();

        // u_loc = u0 - w @ S
        for (int d = 0; d < 256; ++d) {
            float Sv = Ssm[d*SPITCH + c];
#pragma unroll
            for (int r = 0; r < 4; ++r) uacc[r] -= w_s[(r*8 + iw)*257 + d] * Sv;
        }
#pragma unroll
        for (int r = 0; r < 4; ++r) ul[(r*8 + iw)*33 + c] = uacc[r];

        // o part1: q @ S (old S)
        float oacc[4] = {0.f, 0.f, 0.f, 0.f};
        for (int d = 0; d < 256; ++d) {
            float Sv = Ssm[d*SPITCH + c];
#pragma unroll
            for (int r = 0; r < 4; ++r) oacc[r] += q_s[(r*8 + iw)*257 + d] * Sv;
        }
        __syncthreads();

        // o part2: attn_loc @ u_loc
        for (int t2 = 0; t2 < 32; ++t2) {
            float uv = ul[t2*33 + c];
#pragma unroll
            for (int r = 0; r < 4; ++r) oacc[r] += al[(r*8 + iw)*33 + t2] * uv;
        }
#pragma unroll
        for (int r = 0; r < 4; ++r)
            Dout[((size_t)(b*L + l0 + (r*8 + iw)))*HID + h*DV + cb*32 + c] = oacc[r];

        // S += k^T @ u_loc (registers)
        for (int t2 = 0; t2 < 32; ++t2) {
            float uv = ul[t2*33 + c];
#pragma unroll
            for (int r = 0; r < 32; ++r) Sreg[r] += k_s[t2*257 + (r*8 + iw)] * uv;
        }
        __syncthreads();
    }
}

// ---------------- stats: mean, var, abs-mean, l2 per signal ---------------------
__global__ __launch_bounds__(256) void stats_kernel(
    const float* __restrict__ LS, const float* __restrict__ LL,
    const float* __restrict__ DEL, const float* __restrict__ V,
    float* __restrict__ ST)
{
    int th = blockIdx.x;
    int t = th >> 2, h = th & 3;
    int d = threadIdx.x;
    size_t base = (size_t)t*HID + h*DV + d;
    __shared__ float s1[256], s2[256], s3[256];
    const float* ptrs[4] = {LS, LL, DEL, V};
    for (int sig = 0; sig < 4; ++sig) {
        float x = ptrs[sig][base];
        s1[d] = x; s2[d] = x*x; s3[d] = fabsf(x);
        __syncthreads();
        for (int s = 128; s > 0; s >>= 1) {
            if (d < s) { s1[d] += s1[d+s]; s2[d] += s2[d+s]; s3[d] += s3[d+s]; }
            __syncthreads();
        }
        if (d == 0) {
            float sumsq = s2[0];
            float mean = s1[0] / 256.f;
            float var  = sumsq / 256.f - mean*mean;
            float am   = s3[0] / 256.f;
            float l2   = sqrtf(sumsq);
            float* o = ST + (size_t)th*16 + sig*4;
            o[0] = mean; o[1] = var; o[2] = am; o[3] = l2;
        }
        __syncthreads();
    }
}

// ---------------- gate MLP tail + softmax + floor -------------------------------
__global__ __launch_bounds__(256) void gate_kernel(
    const float* __restrict__ G1, const float* __restrict__ ST,
    const float* __restrict__ w1, const float* __restrict__ b1,
    const float* __restrict__ w2, const float* __restrict__ b2,
    const float* __restrict__ lt, float* __restrict__ P)
{
    int th = blockIdx.x;
    int t = th >> 2, h = th & 3;
    int tid = threadIdx.x;
    __shared__ float st[16];
    if (tid < 16) st[tid] = ST[(size_t)th*16 + tid];
    __syncthreads();
    float p0 = 0.f, p1 = 0.f, p2 = 0.f, p3 = 0.f;
    for (int j = tid; j < 1024; j += 256) {
        float x = G1[(size_t)t*1024 + j] + b1[j];
#pragma unroll
        for (int s = 0; s < 16; ++s) x += st[s] * w1[(size_t)(1024 + s)*1024 + j];
        float g = 0.5f * x * (1.f + erff(x * 0.70710678118654752f));
        p0 += g * w2[j*4 + 0]; p1 += g * w2[j*4 + 1];
        p2 += g * w2[j*4 + 2]; p3 += g * w2[j*4 + 3];
    }
    __shared__ float red[1024];
    red[tid] = p0; red[256+tid] = p1; red[512+tid] = p2; red[768+tid] = p3;
    __syncthreads();
    for (int s = 128; s > 0; s >>= 1) {
        if (tid < s) {
            red[tid]     += red[tid+s];     red[256+tid] += red[256+tid+s];
            red[512+tid] += red[512+tid+s]; red[768+tid] += red[768+tid+s];
        }
        __syncthreads();
    }
    if (tid == 0) {
        float inv_t = expf(-lt[h]);
        float l[4];
#pragma unroll
        for (int cc = 0; cc < 4; ++cc) l[cc] = (red[cc*256] + b2[cc]) * inv_t;
        float m = fmaxf(fmaxf(l[0], l[1]), fmaxf(l[2], l[3]));
        float e[4], ssum = 0.f;
#pragma unroll
        for (int cc = 0; cc < 4; ++cc) { e[cc] = expf(l[cc] - m); ssum += e[cc]; }
#pragma unroll
        for (int cc = 0; cc < 4; ++cc)
            P[(size_t)th*4 + cc] = 0.05f + 0.8f * (e[cc] / ssum);
    }
}

// ---------------- mix 4 branches + per-head RMSNorm ------------------------------
__global__ __launch_bounds__(256) void mix_kernel(
    const float* __restrict__ LS, const float* __restrict__ LL,
    const float* __restrict__ DEL, const float* __restrict__ V,
    const float* __restrict__ P, const float* __restrict__ onw,
    float* __restrict__ OM)
{
    int th = blockIdx.x;
    int t = th >> 2, h = th & 3;
    int d = threadIdx.x;
    size_t base = (size_t)t*HID + h*DV + d;
    float p0 = P[th*4], p1 = P[th*4+1], p2 = P[th*4+2], p3 = P[th*4+3];
    float o = p0*LS[base] + p1*LL[base] + p2*DEL[base] + p3*V[base];
    __shared__ float s2[256];
    s2[d] = o*o;
    __syncthreads();
    for (int s = 128; s > 0; s >>= 1) {
        if (d < s) s2[d] += s2[d+s];
        __syncthreads();
    }
    float ms = s2[0] / 256.f;
    OM[base] = o * rsqrtf(ms + 1e-5f) * onw[d];
}

// ---------------- launch ---------------------------------------------------------
extern "C" void kernel_launch(void* const* d_in, const int* in_sizes, int n_in,
                              void* d_out, int out_size)
{
    const float* hs = (const float*)d_in[0];
    const float* Wq = (const float*)d_in[1];
    const float* Wk = (const float*)d_in[2];
    const float* Wv = (const float*)d_in[3];
    const float* Wb = (const float*)d_in[4];
    const float* cq = (const float*)d_in[5];
    const float* ck = (const float*)d_in[6];
    const float* cv = (const float*)d_in[7];
    const float* fs = (const float*)d_in[8];
    const float* fl = (const float*)d_in[9];
    const float* w1 = (const float*)d_in[10];
    const float* b1 = (const float*)d_in[11];
    const float* w2 = (const float*)d_in[12];
    const float* b2 = (const float*)d_in[13];
    const float* lt = (const float*)d_in[14];
    const float* onw= (const float*)d_in[15];
    const float* Wo = (const float*)d_in[16];

    const int T = in_sizes[0] / HID;   // B*L = 8192
    const int B = 2;
    const int L = T / B;

    float *tmp, *q, *k, *v, *kb, *u, *w, *del, *ls, *ll, *g1, *om, *aloc, *beta, *st, *pr;
    cudaGetSymbolAddress((void**)&tmp,  g_tmp);
    cudaGetSymbolAddress((void**)&q,    g_q);
    cudaGetSymbolAddress((void**)&k,    g_k);
    cudaGetSymbolAddress((void**)&v,    g_v);
    cudaGetSymbolAddress((void**)&kb,   g_kb);
    cudaGetSymbolAddress((void**)&u,    g_u);
    cudaGetSymbolAddress((void**)&w,    g_w);
    cudaGetSymbolAddress((void**)&del,  g_del);
    cudaGetSymbolAddress((void**)&ls,   g_ls);
    cudaGetSymbolAddress((void**)&ll,   g_ll);
    cudaGetSymbolAddress((void**)&g1,   g_g1);
    cudaGetSymbolAddress((void**)&om,   g_om);
    cudaGetSymbolAddress((void**)&aloc, g_aloc);
    cudaGetSymbolAddress((void**)&beta, g_beta);
    cudaGetSymbolAddress((void**)&st,   g_stats);
    cudaGetSymbolAddress((void**)&pr,   g_probs);

    dim3 gg(HID/128, T/128);
    int nconv = (T*HID + 255) / 256;

    // projections + short conv + silu
    sgemm128<<<gg, 256>>>(hs, Wq, tmp, T, HID, HID);
    conv_kernel<<<nconv, 256>>>(tmp, cq, q, L, 4, 1, T*HID);
    sgemm128<<<gg, 256>>>(hs, Wk, tmp, T, HID, HID);
    conv_kernel<<<nconv, 256>>>(tmp, ck, k, L, 4, 1, T*HID);
    sgemm128<<<gg, 256>>>(hs, Wv, tmp, T, HID, HID);
    conv_kernel<<<nconv, 256>>>(tmp, cv, v, L, 4, 1, T*HID);

    beta_kernel<<<(T*NH + 7) / 8, 256>>>(hs, Wb, beta, T);
    l2norm_kernel<<<T*NH, 256>>>(q, k, kb, beta);

    size_t chunk_smem = (size_t)(3*32*257 + 32*33) * 4;
    cudaFuncSetAttribute(chunk_kernel, cudaFuncAttributeMaxDynamicSharedMemorySize, (int)chunk_smem);
    chunk_kernel<<<B*NH*(L/CHUNK), 256, chunk_smem>>>(q, k, kb, v, beta, u, w, aloc, L);

    size_t scan_smem = (size_t)(256*SPITCH + 3*32*257 + 2*32*33) * 4;
    cudaFuncSetAttribute(scan_kernel, cudaFuncAttributeMaxDynamicSharedMemorySize, (int)scan_smem);
    scan_kernel<<<dim3(DV/32, B*NH), 256, scan_smem>>>(q, k, u, w, aloc, del, L);

    // FIR branches
    conv_kernel<<<nconv, 256>>>(v, fs, ls, L, 5, 0, T*HID);
    conv_kernel<<<nconv, 256>>>(v, fl, ll, L, 64, 0, T*HID);

    stats_kernel<<<T*NH, 256>>>(ls, ll, del, v, st);

    // gate: shared hs @ w1[:1024] once, per-head tail in gate_kernel
    sgemm128<<<gg, 256>>>(hs, w1, g1, T, HID, HID);
    gate_kernel<<<T*NH, 256>>>(g1, st, w1, b1, w2, b2, lt, pr);

    mix_kernel<<<T*NH, 256>>>(ls, ll, del, v, pr, onw, om);

    sgemm128<<<gg, 256>>>(om, Wo, (float*)d_out, T, HID, HID);
}

// round 4
// speedup vs baseline: 1.2005x; 1.2005x over previous
#include <cuda_runtime.h>
#include <cuda_bf16.h>
#include <math.h>
#include <stdint.h>

#define HID 1024
#define NH 4
#define DK 256
#define DV 256
#define CHUNK 32
#define TMAX 8192

// ---------------- scratch (static device buffers; no allocation) ----------------
__device__ float g_tmp  [TMAX*HID];
__device__ float g_q    [TMAX*HID];
__device__ float g_k    [TMAX*HID];
__device__ float g_v    [TMAX*HID];
__device__ float g_kb   [TMAX*HID];
__device__ float g_u    [TMAX*HID];
__device__ float g_w    [TMAX*HID];
__device__ float g_del  [TMAX*HID];
__device__ float g_ls   [TMAX*HID];
__device__ float g_ll   [TMAX*HID];
__device__ float g_g1   [TMAX*HID];
__device__ float g_om   [TMAX*HID];
__device__ float g_aloc [TMAX*NH*CHUNK];
__device__ float g_beta [TMAX*NH];
__device__ float g_stats[TMAX*NH*16];
__device__ float g_probs[TMAX*NH*4];
__device__ __nv_bfloat16 g_a2 [TMAX*2*HID];   // [M, 2K] hi|lo
__device__ __nv_bfloat16 g_bth[HID*HID];      // B^T hi  [N,K]
__device__ __nv_bfloat16 g_btl[HID*HID];      // B^T lo  [N,K]

__device__ __forceinline__ uint32_t smem_u32(const void* p) {
    uint32_t a;
    asm("{ .reg .u64 t; cvta.to.shared.u64 t, %1; cvt.u32.u64 %0, t; }" : "=r"(a) : "l"(p));
    return a;
}
__device__ __forceinline__ void cp16(uint32_t dst, const void* src) {
    asm volatile("cp.async.cg.shared.global [%0], [%1], 16;" :: "r"(dst), "l"(src));
}

// ---------------- precision-split prep kernels ----------------
__global__ void asplit_kernel(const float* __restrict__ X,
                              __nv_bfloat16* __restrict__ A2, int K, int total) {
    int idx = blockIdx.x * blockDim.x + threadIdx.x;
    if (idx >= total) return;
    int m = idx / K, kk = idx - m * K;
    float v = X[idx];
    __nv_bfloat16 hi = __float2bfloat16(v);
    float r = v - __bfloat162float(hi);
    A2[(size_t)m * 2 * K + kk]     = hi;
    A2[(size_t)m * 2 * K + K + kk] = __float2bfloat16(r);
}

__global__ void bsplit_kernel(const float* __restrict__ W,
                              __nv_bfloat16* __restrict__ Bh,
                              __nv_bfloat16* __restrict__ Bl, int K, int N) {
    __shared__ float t[32][33];
    int bn = blockIdx.x * 32, bk = blockIdx.y * 32;
    int x = threadIdx.x, y = threadIdx.y;
    for (int i = y; i < 32; i += 8) t[i][x] = W[(size_t)(bk + i) * N + bn + x];
    __syncthreads();
    for (int i = y; i < 32; i += 8) {
        float v = t[x][i];
        __nv_bfloat16 hi = __float2bfloat16(v);
        float r = v - __bfloat162float(hi);
        Bh[(size_t)(bn + i) * K + bk + x] = hi;
        Bl[(size_t)(bn + i) * K + bk + x] = __float2bfloat16(r);
    }
}

// ---------------- bf16 mma.sync GEMM: C[M,N] = A[M,K] @ W[K,N] ------------------
// A2: [M, 2K] (hi | lo) row-major; Bh/Bl: B^T [N, K] row-major.
// 3 segments over virtual K' = 3K: (Ah,Bh), (Al,Bh), (Ah,Bl).
#define BM 128
#define BN 128
#define BK 32
#define APITCH 40   // bf16 elements; 80B rows -> conflict-free ldmatrix

__global__ __launch_bounds__(256) void gemm_mma(
    const __nv_bfloat16* __restrict__ A2, const __nv_bfloat16* __restrict__ Bh,
    const __nv_bfloat16* __restrict__ Bl, float* __restrict__ C,
    int M, int N, int K)
{
    __shared__ __nv_bfloat16 As[2][BM * APITCH];
    __shared__ __nv_bfloat16 Bs[2][BN * APITCH];

    const int tid = threadIdx.x;
    const int wid = tid >> 5, lane = tid & 31;
    const int m0 = blockIdx.y * BM, n0 = blockIdx.x * BN;
    const int wm = (wid >> 2) * 64, wn = (wid & 3) * 32;

    const int KBn = K / BK;        // k-steps per segment
    const int NB = 3 * KBn;
    const size_t sA = (size_t)2 * K;

    // loader lambda (macro-style)
    auto load_stage = [&](int kb, int buf) {
        int seg = kb / KBn;
        int kk = (kb - seg * KBn) * BK;
        const __nv_bfloat16* Ap = A2 + (seg == 1 ? (size_t)K : 0) + kk;
        const __nv_bfloat16* Bp = ((seg == 2) ? Bl : Bh) + kk;
        uint32_t a_s = smem_u32(&As[buf][0]);
        uint32_t b_s = smem_u32(&Bs[buf][0]);
#pragma unroll
        for (int i = 0; i < 2; ++i) {
            int idx = i * 256 + tid;
            int row = idx >> 2, ch = idx & 3;
            cp16(a_s + (uint32_t)(row * APITCH + ch * 8) * 2,
                 Ap + (size_t)(m0 + row) * sA + ch * 8);
            cp16(b_s + (uint32_t)(row * APITCH + ch * 8) * 2,
                 Bp + (size_t)(n0 + row) * K + ch * 8);
        }
    };

    float acc[4][4][4];
#pragma unroll
    for (int mt = 0; mt < 4; ++mt)
#pragma unroll
        for (int nt = 0; nt < 4; ++nt)
#pragma unroll
            for (int e = 0; e < 4; ++e) acc[mt][nt][e] = 0.f;

    load_stage(0, 0);
    asm volatile("cp.async.commit_group;" ::: "memory");

    for (int kb = 0; kb < NB; ++kb) {
        int buf = kb & 1;
        if (kb + 1 < NB) load_stage(kb + 1, buf ^ 1);
        asm volatile("cp.async.commit_group;" ::: "memory");
        asm volatile("cp.async.wait_group 1;" ::: "memory");
        __syncthreads();

        uint32_t a_s = smem_u32(&As[buf][0]);
        uint32_t b_s = smem_u32(&Bs[buf][0]);
#pragma unroll
        for (int kp = 0; kp < 2; ++kp) {
            uint32_t a[4][4], b[4][2];
            // A fragments: 4 m-tiles
            {
                int r_off = (lane & 7) + ((lane >> 3) & 1) * 8;
                int c_off = kp * 16 + (lane >> 4) * 8;
#pragma unroll
                for (int mt = 0; mt < 4; ++mt) {
                    uint32_t addr = a_s + (uint32_t)((wm + mt * 16 + r_off) * APITCH + c_off) * 2;
                    asm volatile("ldmatrix.sync.aligned.m8n8.x4.shared.b16 {%0,%1,%2,%3}, [%4];"
                        : "=r"(a[mt][0]), "=r"(a[mt][1]), "=r"(a[mt][2]), "=r"(a[mt][3])
                        : "r"(addr));
                }
            }
            // B fragments: 2 x4 loads cover 4 n-tiles
            {
                int n_off = (lane & 7) + (lane >> 4) * 8;
                int c_off = kp * 16 + ((lane >> 3) & 1) * 8;
#pragma unroll
                for (int nb = 0; nb < 2; ++nb) {
                    uint32_t r0, r1, r2, r3;
                    uint32_t addr = b_s + (uint32_t)((wn + nb * 16 + n_off) * APITCH + c_off) * 2;
                    asm volatile("ldmatrix.sync.aligned.m8n8.x4.shared.b16 {%0,%1,%2,%3}, [%4];"
                        : "=r"(r0), "=r"(r1), "=r"(r2), "=r"(r3) : "r"(addr));
                    b[nb * 2][0] = r0;     b[nb * 2][1] = r1;
                    b[nb * 2 + 1][0] = r2; b[nb * 2 + 1][1] = r3;
                }
            }
#pragma unroll
            for (int mt = 0; mt < 4; ++mt)
#pragma unroll
                for (int nt = 0; nt < 4; ++nt) {
                    asm volatile(
                        "mma.sync.aligned.m16n8k16.row.col.f32.bf16.bf16.f32 "
                        "{%0,%1,%2,%3}, {%4,%5,%6,%7}, {%8,%9}, {%0,%1,%2,%3};"
                        : "+f"(acc[mt][nt][0]), "+f"(acc[mt][nt][1]),
                          "+f"(acc[mt][nt][2]), "+f"(acc[mt][nt][3])
                        : "r"(a[mt][0]), "r"(a[mt][1]), "r"(a[mt][2]), "r"(a[mt][3]),
                          "r"(b[nt][0]), "r"(b[nt][1]));
                }
        }
        __syncthreads();
    }

    // epilogue: direct float2 stores
    int g = lane >> 2, tg = lane & 3;
#pragma unroll
    for (int mt = 0; mt < 4; ++mt) {
#pragma unroll
        for (int nt = 0; nt < 4; ++nt) {
            int row = m0 + wm + mt * 16 + g;
            int col = n0 + wn + nt * 8 + tg * 2;
            *(float2*)(C + (size_t)row * N + col) =
                make_float2(acc[mt][nt][0], acc[mt][nt][1]);
            *(float2*)(C + (size_t)(row + 8) * N + col) =
                make_float2(acc[mt][nt][2], acc[mt][nt][3]);
        }
    }
}

// ---------------- causal depthwise conv (+ optional SiLU) -----------------------
__global__ void conv_kernel(const float* __restrict__ x, const float* __restrict__ w,
                            float* __restrict__ y, int L, int K, int apply_silu, int total)
{
    int idx = blockIdx.x * blockDim.x + threadIdx.x;
    if (idx >= total) return;
    int c = idx % HID;
    int t = idx / HID;
    int b = t / L, l = t % L;
    float acc = 0.f;
#pragma unroll 4
    for (int kk = 0; kk < K; ++kk) {
        int ll = l - (K - 1) + kk;
        if (ll >= 0) acc += x[((size_t)(b*L + ll))*HID + c] * w[c*K + kk];
    }
    if (apply_silu) acc = acc / (1.f + expf(-acc));
    y[idx] = acc;
}

// ---------------- beta = sigmoid(hs @ Wb), warp per (t,h) -----------------------
__global__ void beta_kernel(const float* __restrict__ hs, const float* __restrict__ Wb,
                            float* __restrict__ beta, int T)
{
    int gw = (blockIdx.x * blockDim.x + threadIdx.x) >> 5;
    int lane = threadIdx.x & 31;
    if (gw >= T * NH) return;
    int t = gw / NH, h = gw % NH;
    float s = 0.f;
    for (int r = lane; r < HID; r += 32) s += hs[(size_t)t*HID + r] * Wb[r*NH + h];
#pragma unroll
    for (int off = 16; off; off >>= 1) s += __shfl_down_sync(0xffffffff, s, off);
    if (lane == 0) beta[t*NH + h] = 1.f / (1.f + expf(-s));
}

// ---------------- l2norm(q), l2norm(k), kb = k_hat * beta -----------------------
__global__ __launch_bounds__(256) void l2norm_kernel(
    float* __restrict__ Q, float* __restrict__ Kp, float* __restrict__ KB,
    const float* __restrict__ beta)
{
    int th = blockIdx.x;
    int t = th >> 2, h = th & 3;
    int d = threadIdx.x;
    size_t base = (size_t)t*HID + h*DK;
    float qv = Q[base + d], kv = Kp[base + d];
    __shared__ float sq[256], sk[256];
    sq[d] = qv*qv; sk[d] = kv*kv;
    __syncthreads();
    for (int s = 128; s > 0; s >>= 1) {
        if (d < s) { sq[d] += sq[d+s]; sk[d] += sk[d+s]; }
        __syncthreads();
    }
    float rq = rsqrtf(sq[0] + 1e-6f);
    float rk = rsqrtf(sk[0] + 1e-6f);
    float bb = beta[t*NH + h];
    Q[base + d]  = qv * rq;
    float kn = kv * rk;
    Kp[base + d] = kn;
    KB[base + d] = kn * bb;
}

// ---------------- per-chunk: attn inversion + u, w, attn_loc --------------------
__global__ __launch_bounds__(256) void chunk_kernel(
    const float* __restrict__ Qn, const float* __restrict__ Kn,
    const float* __restrict__ KB, const float* __restrict__ V,
    const float* __restrict__ beta, float* __restrict__ U,
    float* __restrict__ Wbuf, float* __restrict__ Aloc, int L)
{
    extern __shared__ float sm[];
    float* q_s  = sm;
    float* kn_s = q_s  + 32*257;
    float* kb_s = kn_s + 32*257;
    float* A    = kb_s + 32*257;
    int nch = L / CHUNK;
    int cid = blockIdx.x;
    int ch = cid % nch;
    int h  = (cid / nch) & (NH - 1);
    int b  = cid / (nch * NH);
    int l0 = ch * CHUNK;
    int tid = threadIdx.x;
    size_t base = ((size_t)(b*L + l0)) * HID + h*DK;

    for (int r = 0; r < 32; ++r) {
        size_t g = base + (size_t)r*HID + tid;
        q_s [r*257 + tid] = Qn[g];
        kn_s[r*257 + tid] = Kn[g];
        kb_s[r*257 + tid] = KB[g];
    }
    __syncthreads();

    size_t abase = (size_t)cid * (CHUNK*CHUNK);
#pragma unroll
    for (int r = 0; r < 4; ++r) {
        int e = r*256 + tid;
        int i = e >> 5, j = e & 31;
        float sA = 0.f, sL = 0.f;
        if (i > j)
            for (int d = 0; d < 256; ++d) sA += kb_s[i*257+d] * kn_s[j*257+d];
        if (j <= i)
            for (int d = 0; d < 256; ++d) sL += q_s[i*257+d] * kn_s[j*257+d];
        A[i*33 + j] = (i > j) ? -sA : 0.f;
        Aloc[abase + e] = (j <= i) ? sL : 0.f;
    }
    __syncthreads();

    if (tid < 32) {
        int j = tid;
        for (int i = 1; i < 32; ++i) {
            float s = 0.f;
            if (j < i) {
#pragma unroll
                for (int t2 = 0; t2 < 32; ++t2) s += A[i*33 + t2] * A[t2*33 + j];
            }
            __syncwarp();
            if (j < i) A[i*33 + j] += s;
            __syncwarp();
        }
        A[j*33 + j] += 1.f;
    }
    __syncthreads();

    for (int r = 0; r < 32; ++r) {
        float bb = beta[(b*L + l0 + r)*NH + h];
        q_s[r*257 + tid] = V[base + (size_t)r*HID + tid] * bb;
    }
    __syncthreads();

    for (int i = 0; i < 32; ++i) {
        float su = 0.f, sw = 0.f;
#pragma unroll
        for (int t2 = 0; t2 < 32; ++t2) {
            float a = A[i*33 + t2];
            su += a * q_s [t2*257 + tid];
            sw += a * kb_s[t2*257 + tid];
        }
        U   [base + (size_t)i*HID + tid] = su;
        Wbuf[base + (size_t)i*HID + tid] = sw;
    }
}

// ---------------- sequential chunk scan; S slice kept in registers --------------
#define SPITCH 33
__global__ __launch_bounds__(256) void scan_kernel(
    const float* __restrict__ Qn, const float* __restrict__ Kn,
    const float* __restrict__ U,  const float* __restrict__ Wbuf,
    const float* __restrict__ Aloc, float* __restrict__ Dout, int L)
{
    extern __shared__ float sm[];
    float* Ssm = sm;
    float* q_s = Ssm + 256*SPITCH;
    float* k_s = q_s + 32*257;
    float* w_s = k_s + 32*257;
    float* al  = w_s + 32*257;
    float* ul  = al  + 32*33;

    int cb = blockIdx.x;
    int bh = blockIdx.y;
    int b = bh >> 2, h = bh & 3;
    int tid = threadIdx.x;
    int c  = tid & 31;
    int iw = tid >> 5;
    int nch = L / CHUNK;

    float Sreg[32];
#pragma unroll
    for (int r = 0; r < 32; ++r) Sreg[r] = 0.f;

    for (int ch = 0; ch < nch; ++ch) {
        int l0 = ch * CHUNK;
        size_t base = ((size_t)(b*L + l0)) * HID + h*DK;

#pragma unroll
        for (int r = 0; r < 32; ++r) Ssm[(r*8 + iw)*SPITCH + c] = Sreg[r];
        for (int r = 0; r < 32; ++r) {
            size_t g = base + (size_t)r*HID + tid;
            q_s[r*257 + tid] = Qn[g];
            k_s[r*257 + tid] = Kn[g];
            w_s[r*257 + tid] = Wbuf[g];
        }
        size_t abase = (size_t)((b*NH + h)*nch + ch) * 1024;
#pragma unroll
        for (int r = 0; r < 4; ++r)
            al[(r*8 + iw)*33 + c] = Aloc[abase + r*256 + tid];

        float uacc[4];
#pragma unroll
        for (int r = 0; r < 4; ++r)
            uacc[r] = U[((size_t)(b*L + l0 + (r*8 + iw)))*HID + h*DV + cb*32 + c];
        __syncthreads();

        for (int d = 0; d < 256; ++d) {
            float Sv = Ssm[d*SPITCH + c];
#pragma unroll
            for (int r = 0; r < 4; ++r) uacc[r] -= w_s[(r*8 + iw)*257 + d] * Sv;
        }
#pragma unroll
        for (int r = 0; r < 4; ++r) ul[(r*8 + iw)*33 + c] = uacc[r];

        float oacc[4] = {0.f, 0.f, 0.f, 0.f};
        for (int d = 0; d < 256; ++d) {
            float Sv = Ssm[d*SPITCH + c];
#pragma unroll
            for (int r = 0; r < 4; ++r) oacc[r] += q_s[(r*8 + iw)*257 + d] * Sv;
        }
        __syncthreads();

        for (int t2 = 0; t2 < 32; ++t2) {
            float uv = ul[t2*33 + c];
#pragma unroll
            for (int r = 0; r < 4; ++r) oacc[r] += al[(r*8 + iw)*33 + t2] * uv;
        }
#pragma unroll
        for (int r = 0; r < 4; ++r)
            Dout[((size_t)(b*L + l0 + (r*8 + iw)))*HID + h*DV + cb*32 + c] = oacc[r];

        for (int t2 = 0; t2 < 32; ++t2) {
            float uv = ul[t2*33 + c];
#pragma unroll
            for (int r = 0; r < 32; ++r) Sreg[r] += k_s[t2*257 + (r*8 + iw)] * uv;
        }
        __syncthreads();
    }
}

// ---------------- stats ----------------------------------------------------------
__global__ __launch_bounds__(256) void stats_kernel(
    const float* __restrict__ LS, const float* __restrict__ LL,
    const float* __restrict__ DEL, const float* __restrict__ V,
    float* __restrict__ ST)
{
    int th = blockIdx.x;
    int t = th >> 2, h = th & 3;
    int d = threadIdx.x;
    size_t base = (size_t)t*HID + h*DV + d;
    __shared__ float s1[256], s2[256], s3[256];
    const float* ptrs[4] = {LS, LL, DEL, V};
    for (int sig = 0; sig < 4; ++sig) {
        float x = ptrs[sig][base];
        s1[d] = x; s2[d] = x*x; s3[d] = fabsf(x);
        __syncthreads();
        for (int s = 128; s > 0; s >>= 1) {
            if (d < s) { s1[d] += s1[d+s]; s2[d] += s2[d+s]; s3[d] += s3[d+s]; }
            __syncthreads();
        }
        if (d == 0) {
            float sumsq = s2[0];
            float mean = s1[0] / 256.f;
            float var  = sumsq / 256.f - mean*mean;
            float am   = s3[0] / 256.f;
            float l2   = sqrtf(sumsq);
            float* o = ST + (size_t)th*16 + sig*4;
            o[0] = mean; o[1] = var; o[2] = am; o[3] = l2;
        }
        __syncthreads();
    }
}

// ---------------- gate MLP tail + softmax + floor -------------------------------
__global__ __launch_bounds__(256) void gate_kernel(
    const float* __restrict__ G1, const float* __restrict__ ST,
    const float* __restrict__ w1, const float* __restrict__ b1,
    const float* __restrict__ w2, const float* __restrict__ b2,
    const float* __restrict__ lt, float* __restrict__ P)
{
    int th = blockIdx.x;
    int t = th >> 2, h = th & 3;
    int tid = threadIdx.x;
    __shared__ float st[16];
    if (tid < 16) st[tid] = ST[(size_t)th*16 + tid];
    __syncthreads();
    float p0 = 0.f, p1 = 0.f, p2 = 0.f, p3 = 0.f;
    for (int j = tid; j < 1024; j += 256) {
        float x = G1[(size_t)t*1024 + j] + b1[j];
#pragma unroll
        for (int s = 0; s < 16; ++s) x += st[s] * w1[(size_t)(1024 + s)*1024 + j];
        float g = 0.5f * x * (1.f + erff(x * 0.70710678118654752f));
        p0 += g * w2[j*4 + 0]; p1 += g * w2[j*4 + 1];
        p2 += g * w2[j*4 + 2]; p3 += g * w2[j*4 + 3];
    }
    __shared__ float red[1024];
    red[tid] = p0; red[256+tid] = p1; red[512+tid] = p2; red[768+tid] = p3;
    __syncthreads();
    for (int s = 128; s > 0; s >>= 1) {
        if (tid < s) {
            red[tid]     += red[tid+s];     red[256+tid] += red[256+tid+s];
            red[512+tid] += red[512+tid+s]; red[768+tid] += red[768+tid+s];
        }
        __syncthreads();
    }
    if (tid == 0) {
        float inv_t = expf(-lt[h]);
        float l[4];
#pragma unroll
        for (int cc = 0; cc < 4; ++cc) l[cc] = (red[cc*256] + b2[cc]) * inv_t;
        float m = fmaxf(fmaxf(l[0], l[1]), fmaxf(l[2], l[3]));
        float e[4], ssum = 0.f;
#pragma unroll
        for (int cc = 0; cc < 4; ++cc) { e[cc] = expf(l[cc] - m); ssum += e[cc]; }
#pragma unroll
        for (int cc = 0; cc < 4; ++cc)
            P[(size_t)th*4 + cc] = 0.05f + 0.8f * (e[cc] / ssum);
    }
}

// ---------------- mix + RMSNorm ---------------------------------------------------
__global__ __launch_bounds__(256) void mix_kernel(
    const float* __restrict__ LS, const float* __restrict__ LL,
    const float* __restrict__ DEL, const float* __restrict__ V,
    const float* __restrict__ P, const float* __restrict__ onw,
    float* __restrict__ OM)
{
    int th = blockIdx.x;
    int t = th >> 2, h = th & 3;
    int d = threadIdx.x;
    size_t base = (size_t)t*HID + h*DV + d;
    float p0 = P[th*4], p1 = P[th*4+1], p2 = P[th*4+2], p3 = P[th*4+3];
    float o = p0*LS[base] + p1*LL[base] + p2*DEL[base] + p3*V[base];
    __shared__ float s2[256];
    s2[d] = o*o;
    __syncthreads();
    for (int s = 128; s > 0; s >>= 1) {
        if (d < s) s2[d] += s2[d+s];
        __syncthreads();
    }
    float ms = s2[0] / 256.f;
    OM[base] = o * rsqrtf(ms + 1e-5f) * onw[d];
}

// ---------------- launch ----------------------------------------------------------
extern "C" void kernel_launch(void* const* d_in, const int* in_sizes, int n_in,
                              void* d_out, int out_size)
{
    const float* hs = (const float*)d_in[0];
    const float* Wq = (const float*)d_in[1];
    const float* Wk = (const float*)d_in[2];
    const float* Wv = (const float*)d_in[3];
    const float* Wb = (const float*)d_in[4];
    const float* cq = (const float*)d_in[5];
    const float* ck = (const float*)d_in[6];
    const float* cv = (const float*)d_in[7];
    const float* fs = (const float*)d_in[8];
    const float* fl = (const float*)d_in[9];
    const float* w1 = (const float*)d_in[10];
    const float* b1 = (const float*)d_in[11];
    const float* w2 = (const float*)d_in[12];
    const float* b2 = (const float*)d_in[13];
    const float* lt = (const float*)d_in[14];
    const float* onw= (const float*)d_in[15];
    const float* Wo = (const float*)d_in[16];

    const int T = in_sizes[0] / HID;   // B*L = 8192
    const int B = 2;
    const int L = T / B;

    float *tmp, *q, *k, *v, *kb, *u, *w, *del, *ls, *ll, *g1, *om, *aloc, *beta, *st, *pr;
    __nv_bfloat16 *a2, *bth, *btl;
    cudaGetSymbolAddress((void**)&tmp,  g_tmp);
    cudaGetSymbolAddress((void**)&q,    g_q);
    cudaGetSymbolAddress((void**)&k,    g_k);
    cudaGetSymbolAddress((void**)&v,    g_v);
    cudaGetSymbolAddress((void**)&kb,   g_kb);
    cudaGetSymbolAddress((void**)&u,    g_u);
    cudaGetSymbolAddress((void**)&w,    g_w);
    cudaGetSymbolAddress((void**)&del,  g_del);
    cudaGetSymbolAddress((void**)&ls,   g_ls);
    cudaGetSymbolAddress((void**)&ll,   g_ll);
    cudaGetSymbolAddress((void**)&g1,   g_g1);
    cudaGetSymbolAddress((void**)&om,   g_om);
    cudaGetSymbolAddress((void**)&aloc, g_aloc);
    cudaGetSymbolAddress((void**)&beta, g_beta);
    cudaGetSymbolAddress((void**)&st,   g_stats);
    cudaGetSymbolAddress((void**)&pr,   g_probs);
    cudaGetSymbolAddress((void**)&a2,   g_a2);
    cudaGetSymbolAddress((void**)&bth,  g_bth);
    cudaGetSymbolAddress((void**)&btl,  g_btl);

    dim3 gg(HID/BN, T/BM);            // 8 x 64
    dim3 bt_grid(HID/32, HID/32);
    dim3 bt_blk(32, 8);
    int nconv = (T*HID + 255) / 256;
    int nsplit = (T*HID + 255) / 256;

    // A split of hs (used by q,k,v and gate GEMMs)
    asplit_kernel<<<nsplit, 256>>>(hs, a2, HID, T*HID);

    // q
    bsplit_kernel<<<bt_grid, bt_blk>>>(Wq, bth, btl, HID, HID);
    gemm_mma<<<gg, 256>>>(a2, bth, btl, tmp, T, HID, HID);
    conv_kernel<<<nconv, 256>>>(tmp, cq, q, L, 4, 1, T*HID);
    // k
    bsplit_kernel<<<bt_grid, bt_blk>>>(Wk, bth, btl, HID, HID);
    gemm_mma<<<gg, 256>>>(a2, bth, btl, tmp, T, HID, HID);
    conv_kernel<<<nconv, 256>>>(tmp, ck, k, L, 4, 1, T*HID);
    // v
    bsplit_kernel<<<bt_grid, bt_blk>>>(Wv, bth, btl, HID, HID);
    gemm_mma<<<gg, 256>>>(a2, bth, btl, tmp, T, HID, HID);
    conv_kernel<<<nconv, 256>>>(tmp, cv, v, L, 4, 1, T*HID);

    beta_kernel<<<(T*NH + 7) / 8, 256>>>(hs, Wb, beta, T);
    l2norm_kernel<<<T*NH, 256>>>(q, k, kb, beta);

    size_t chunk_smem = (size_t)(3*32*257 + 32*33) * 4;
    cudaFuncSetAttribute(chunk_kernel, cudaFuncAttributeMaxDynamicSharedMemorySize, (int)chunk_smem);
    chunk_kernel<<<B*NH*(L/CHUNK), 256, chunk_smem>>>(q, k, kb, v, beta, u, w, aloc, L);

    size_t scan_smem = (size_t)(256*SPITCH + 3*32*257 + 2*32*33) * 4;
    cudaFuncSetAttribute(scan_kernel, cudaFuncAttributeMaxDynamicSharedMemorySize, (int)scan_smem);
    scan_kernel<<<dim3(DV/32, B*NH), 256, scan_smem>>>(q, k, u, w, aloc, del, L);

    // FIR branches
    conv_kernel<<<nconv, 256>>>(v, fs, ls, L, 5, 0, T*HID);
    conv_kernel<<<nconv, 256>>>(v, fl, ll, L, 64, 0, T*HID);

    stats_kernel<<<T*NH, 256>>>(ls, ll, del, v, st);

    // gate: shared hs @ w1[:1024] (a2 still holds split hs)
    bsplit_kernel<<<bt_grid, bt_blk>>>(w1, bth, btl, HID, HID);
    gemm_mma<<<gg, 256>>>(a2, bth, btl, g1, T, HID, HID);
    gate_kernel<<<T*NH, 256>>>(g1, st, w1, b1, w2, b2, lt, pr);

    mix_kernel<<<T*NH, 256>>>(ls, ll, del, v, pr, onw, om);

    // out = om @ Wo
    asplit_kernel<<<nsplit, 256>>>(om, a2, HID, T*HID);
    bsplit_kernel<<<bt_grid, bt_blk>>>(Wo, bth, btl, HID, HID);
    gemm_mma<<<gg, 256>>>(a2, bth, btl, (float*)d_out, T, HID, HID);
}

// round 6
// speedup vs baseline: 1.4245x; 1.1866x over previous
#include <cuda_runtime.h>
#include <cuda_bf16.h>
#include <math.h>
#include <stdint.h>

#define HID 1024
#define NH 4
#define DK 256
#define DV 256
#define CHUNK 32
#define TMAX 8192
#define QP 260     // float pitch, conflict-free float4 per-lane
#define KTP 36     // pitch for 32-wide transposed tiles

// ---------------- scratch (static device buffers; no allocation) ----------------
__device__ float g_tmp  [TMAX*HID];
__device__ float g_q    [TMAX*HID];
__device__ float g_k    [TMAX*HID];
__device__ float g_v    [TMAX*HID];
__device__ float g_kb   [TMAX*HID];
__device__ float g_u    [TMAX*HID];
__device__ float g_w    [TMAX*HID];
__device__ float g_del  [TMAX*HID];
__device__ float g_ls   [TMAX*HID];
__device__ float g_ll   [TMAX*HID];
__device__ float g_g1   [TMAX*HID];
__device__ float g_om   [TMAX*HID];
__device__ float g_aloc [TMAX*NH*CHUNK];
__device__ float g_beta [TMAX*NH];
__device__ float g_stats[TMAX*NH*16];
__device__ float g_probs[TMAX*NH*4];
__device__ __nv_bfloat16 g_a2 [TMAX*2*HID];   // split hs / om
__device__ __nv_bfloat16 g_bth[HID*HID];      // B^T hi
__device__ __nv_bfloat16 g_btl[HID*HID];      // B^T lo

__device__ __forceinline__ uint32_t smem_u32(const void* p) {
    uint32_t a;
    asm("{ .reg .u64 t; cvta.to.shared.u64 t, %1; cvt.u32.u64 %0, t; }" : "=r"(a) : "l"(p));
    return a;
}
__device__ __forceinline__ void cp16(uint32_t dst, const void* src) {
    asm volatile("cp.async.cg.shared.global [%0], [%1], 16;" :: "r"(dst), "l"(src));
}

// ---------------- precision-split prep kernels ----------------
__global__ void asplit_kernel(const float* __restrict__ X,
                              __nv_bfloat16* __restrict__ A2, int K, int total) {
    int idx = blockIdx.x * blockDim.x + threadIdx.x;
    if (idx >= total) return;
    int m = idx / K, kk = idx - m * K;
    float v = X[idx];
    __nv_bfloat16 hi = __float2bfloat16(v);
    float r = v - __bfloat162float(hi);
    A2[(size_t)m * 2 * K + kk]     = hi;
    A2[(size_t)m * 2 * K + K + kk] = __float2bfloat16(r);
}

__global__ void bsplit_kernel(const float* __restrict__ W,
                              __nv_bfloat16* __restrict__ Bh,
                              __nv_bfloat16* __restrict__ Bl, int K, int N) {
    __shared__ float t[32][33];
    int bn = blockIdx.x * 32, bk = blockIdx.y * 32;
    int x = threadIdx.x, y = threadIdx.y;
    for (int i = y; i < 32; i += 8) t[i][x] = W[(size_t)(bk + i) * N + bn + x];
    __syncthreads();
    for (int i = y; i < 32; i += 8) {
        float v = t[x][i];
        __nv_bfloat16 hi = __float2bfloat16(v);
        float r = v - __bfloat162float(hi);
        Bh[(size_t)(bn + i) * K + bk + x] = hi;
        Bl[(size_t)(bn + i) * K + bk + x] = __float2bfloat16(r);
    }
}

// ---------------- bf16 mma.sync GEMM (3-term split) -----------------------------
#define BM 128
#define BN 128
#define BK 32
#define APITCH 40

__global__ __launch_bounds__(256) void gemm_mma(
    const __nv_bfloat16* __restrict__ A2, const __nv_bfloat16* __restrict__ Bh,
    const __nv_bfloat16* __restrict__ Bl, float* __restrict__ C,
    int M, int N, int K)
{
    __shared__ __nv_bfloat16 As[2][BM * APITCH];
    __shared__ __nv_bfloat16 Bs[2][BN * APITCH];

    const int tid = threadIdx.x;
    const int wid = tid >> 5, lane = tid & 31;
    const int m0 = blockIdx.y * BM, n0 = blockIdx.x * BN;
    const int wm = (wid >> 2) * 64, wn = (wid & 3) * 32;

    const int KBn = K / BK;
    const int NB = 3 * KBn;
    const size_t sA = (size_t)2 * K;

    auto load_stage = [&](int kb, int buf) {
        int seg = kb / KBn;
        int kk = (kb - seg * KBn) * BK;
        const __nv_bfloat16* Ap = A2 + (seg == 1 ? (size_t)K : 0) + kk;
        const __nv_bfloat16* Bp = ((seg == 2) ? Bl : Bh) + kk;
        uint32_t a_s = smem_u32(&As[buf][0]);
        uint32_t b_s = smem_u32(&Bs[buf][0]);
#pragma unroll
        for (int i = 0; i < 2; ++i) {
            int idx = i * 256 + tid;
            int row = idx >> 2, ch = idx & 3;
            cp16(a_s + (uint32_t)(row * APITCH + ch * 8) * 2,
                 Ap + (size_t)(m0 + row) * sA + ch * 8);
            cp16(b_s + (uint32_t)(row * APITCH + ch * 8) * 2,
                 Bp + (size_t)(n0 + row) * K + ch * 8);
        }
    };

    float acc[4][4][4];
#pragma unroll
    for (int mt = 0; mt < 4; ++mt)
#pragma unroll
        for (int nt = 0; nt < 4; ++nt)
#pragma unroll
            for (int e = 0; e < 4; ++e) acc[mt][nt][e] = 0.f;

    load_stage(0, 0);
    asm volatile("cp.async.commit_group;" ::: "memory");

    for (int kb = 0; kb < NB; ++kb) {
        int buf = kb & 1;
        if (kb + 1 < NB) load_stage(kb + 1, buf ^ 1);
        asm volatile("cp.async.commit_group;" ::: "memory");
        asm volatile("cp.async.wait_group 1;" ::: "memory");
        __syncthreads();

        uint32_t a_s = smem_u32(&As[buf][0]);
        uint32_t b_s = smem_u32(&Bs[buf][0]);
#pragma unroll
        for (int kp = 0; kp < 2; ++kp) {
            uint32_t a[4][4], b[4][2];
            {
                int r_off = (lane & 7) + ((lane >> 3) & 1) * 8;
                int c_off = kp * 16 + (lane >> 4) * 8;
#pragma unroll
                for (int mt = 0; mt < 4; ++mt) {
                    uint32_t addr = a_s + (uint32_t)((wm + mt * 16 + r_off) * APITCH + c_off) * 2;
                    asm volatile("ldmatrix.sync.aligned.m8n8.x4.shared.b16 {%0,%1,%2,%3}, [%4];"
                        : "=r"(a[mt][0]), "=r"(a[mt][1]), "=r"(a[mt][2]), "=r"(a[mt][3])
                        : "r"(addr));
                }
            }
            {
                int n_off = (lane & 7) + (lane >> 4) * 8;
                int c_off = kp * 16 + ((lane >> 3) & 1) * 8;
#pragma unroll
                for (int nb = 0; nb < 2; ++nb) {
                    uint32_t r0, r1, r2, r3;
                    uint32_t addr = b_s + (uint32_t)((wn + nb * 16 + n_off) * APITCH + c_off) * 2;
                    asm volatile("ldmatrix.sync.aligned.m8n8.x4.shared.b16 {%0,%1,%2,%3}, [%4];"
                        : "=r"(r0), "=r"(r1), "=r"(r2), "=r"(r3) : "r"(addr));
                    b[nb * 2][0] = r0;     b[nb * 2][1] = r1;
                    b[nb * 2 + 1][0] = r2; b[nb * 2 + 1][1] = r3;
                }
            }
#pragma unroll
            for (int mt = 0; mt < 4; ++mt)
#pragma unroll
                for (int nt = 0; nt < 4; ++nt) {
                    asm volatile(
                        "mma.sync.aligned.m16n8k16.row.col.f32.bf16.bf16.f32 "
                        "{%0,%1,%2,%3}, {%4,%5,%6,%7}, {%8,%9}, {%0,%1,%2,%3};"
                        : "+f"(acc[mt][nt][0]), "+f"(acc[mt][nt][1]),
                          "+f"(acc[mt][nt][2]), "+f"(acc[mt][nt][3])
                        : "r"(a[mt][0]), "r"(a[mt][1]), "r"(a[mt][2]), "r"(a[mt][3]),
                          "r"(b[nt][0]), "r"(b[nt][1]));
                }
        }
        __syncthreads();
    }

    int g = lane >> 2, tg = lane & 3;
#pragma unroll
    for (int mt = 0; mt < 4; ++mt) {
#pragma unroll
        for (int nt = 0; nt < 4; ++nt) {
            int row = m0 + wm + mt * 16 + g;
            int col = n0 + wn + nt * 8 + tg * 2;
            *(float2*)(C + (size_t)row * N + col) =
                make_float2(acc[mt][nt][0], acc[mt][nt][1]);
            *(float2*)(C + (size_t)(row + 8) * N + col) =
                make_float2(acc[mt][nt][2], acc[mt][nt][3]);
        }
    }
}

// ---------------- causal depthwise conv (+ optional SiLU) -----------------------
__global__ void conv_kernel(const float* __restrict__ x, const float* __restrict__ w,
                            float* __restrict__ y, int L, int K, int apply_silu, int total)
{
    int idx = blockIdx.x * blockDim.x + threadIdx.x;
    if (idx >= total) return;
    int c = idx % HID;
    int t = idx / HID;
    int b = t / L, l = t % L;
    float acc = 0.f;
#pragma unroll 4
    for (int kk = 0; kk < K; ++kk) {
        int ll = l - (K - 1) + kk;
        if (ll >= 0) acc += x[((size_t)(b*L + ll))*HID + c] * w[c*K + kk];
    }
    if (apply_silu) acc = acc / (1.f + expf(-acc));
    y[idx] = acc;
}

// ---------------- beta ------------------------------------------------------------
__global__ void beta_kernel(const float* __restrict__ hs, const float* __restrict__ Wb,
                            float* __restrict__ beta, int T)
{
    int gw = (blockIdx.x * blockDim.x + threadIdx.x) >> 5;
    int lane = threadIdx.x & 31;
    if (gw >= T * NH) return;
    int t = gw / NH, h = gw % NH;
    float s = 0.f;
    for (int r = lane; r < HID; r += 32) s += hs[(size_t)t*HID + r] * Wb[r*NH + h];
#pragma unroll
    for (int off = 16; off; off >>= 1) s += __shfl_down_sync(0xffffffff, s, off);
    if (lane == 0) beta[t*NH + h] = 1.f / (1.f + expf(-s));
}

// ---------------- l2norm + kb -----------------------------------------------------
__global__ __launch_bounds__(256) void l2norm_kernel(
    float* __restrict__ Q, float* __restrict__ Kp, float* __restrict__ KB,
    const float* __restrict__ beta)
{
    int th = blockIdx.x;
    int t = th >> 2, h = th & 3;
    int d = threadIdx.x;
    size_t base = (size_t)t*HID + h*DK;
    float qv = Q[base + d], kv = Kp[base + d];
    __shared__ float sq[256], sk[256];
    sq[d] = qv*qv; sk[d] = kv*kv;
    __syncthreads();
    for (int s = 128; s > 0; s >>= 1) {
        if (d < s) { sq[d] += sq[d+s]; sk[d] += sk[d+s]; }
        __syncthreads();
    }
    float rq = rsqrtf(sq[0] + 1e-6f);
    float rk = rsqrtf(sk[0] + 1e-6f);
    float bb = beta[t*NH + h];
    Q[base + d]  = qv * rq;
    float kn = kv * rk;
    Kp[base + d] = kn;
    KB[base + d] = kn * bb;
}

// ---------------- per-chunk: attn inversion + u, w, attn_loc (v4 + hoist) -------
__global__ __launch_bounds__(256) void chunk_kernel(
    const float* __restrict__ Qn, const float* __restrict__ Kn,
    const float* __restrict__ KB, const float* __restrict__ V,
    const float* __restrict__ beta, float* __restrict__ U,
    float* __restrict__ Wbuf, float* __restrict__ Aloc, int L)
{
    extern __shared__ float sm[];
    float* q_s  = sm;                 // 32*QP
    float* kn_s = q_s  + 32*QP;
    float* kb_s = kn_s + 32*QP;
    float* A    = kb_s + 32*QP;       // 32*KTP
    int nch = L / CHUNK;
    int cid = blockIdx.x;
    int ch = cid % nch;
    int h  = (cid / nch) & (NH - 1);
    int b  = cid / (nch * NH);
    int l0 = ch * CHUNK;
    int tid = threadIdx.x;
    int lane = tid & 31;
    int iw = tid >> 5;
    size_t base = ((size_t)(b*L + l0)) * HID + h*DK;

    for (int r = 0; r < 32; ++r) {
        size_t g = base + (size_t)r*HID + tid;
        q_s [r*QP + tid] = Qn[g];
        kn_s[r*QP + tid] = Kn[g];
        kb_s[r*QP + tid] = KB[g];
    }
    __syncthreads();

    size_t abase = (size_t)cid * (CHUNK*CHUNK);
#pragma unroll
    for (int r = 0; r < 4; ++r) {
        int i = r*8 + iw, j = lane;
        float sA = 0.f, sL = 0.f;
#pragma unroll 8
        for (int dq = 0; dq < 64; ++dq) {
            float4 kn = *(float4*)&kn_s[j*QP + dq*4];
            float4 kb = *(float4*)&kb_s[i*QP + dq*4];
            float4 qv = *(float4*)&q_s [i*QP + dq*4];
            sA += kb.x*kn.x + kb.y*kn.y + kb.z*kn.z + kb.w*kn.w;
            sL += qv.x*kn.x + qv.y*kn.y + qv.z*kn.z + qv.w*kn.w;
        }
        A[i*KTP + j] = (i > j) ? -sA : 0.f;
        Aloc[abase + i*32 + j] = (j <= i) ? sL : 0.f;
    }
    __syncthreads();

    // sequential row-inversion (one warp)
    if (tid < 32) {
        int j = tid;
        for (int i = 1; i < 32; ++i) {
            float s = 0.f;
            if (j < i) {
#pragma unroll
                for (int t2 = 0; t2 < 32; ++t2) s += A[i*KTP + t2] * A[t2*KTP + j];
            }
            __syncwarp();
            if (j < i) A[i*KTP + j] += s;
            __syncwarp();
        }
        A[j*KTP + j] += 1.f;
    }
    __syncthreads();

    // v*beta into q_s (reuse)
    for (int r = 0; r < 32; ++r) {
        float bb = beta[(b*L + l0 + r)*NH + h];
        q_s[r*QP + tid] = V[base + (size_t)r*HID + tid] * bb;
    }
    __syncthreads();

    // hoist columns: d = tid fixed
    float vc[32], kc[32];
#pragma unroll
    for (int t2 = 0; t2 < 32; ++t2) {
        vc[t2] = q_s [t2*QP + tid];
        kc[t2] = kb_s[t2*QP + tid];
    }

    for (int i = 0; i < 32; ++i) {
        float su = 0.f, sw = 0.f;
#pragma unroll
        for (int qq = 0; qq < 8; ++qq) {
            float4 a = *(float4*)&A[i*KTP + qq*4];
            su += a.x*vc[qq*4] + a.y*vc[qq*4+1] + a.z*vc[qq*4+2] + a.w*vc[qq*4+3];
            sw += a.x*kc[qq*4] + a.y*kc[qq*4+1] + a.z*kc[qq*4+2] + a.w*kc[qq*4+3];
        }
        U   [base + (size_t)i*HID + tid] = su;
        Wbuf[base + (size_t)i*HID + tid] = sw;
    }
}

// ---------------- sequential chunk scan (v4 + transposed S + hoisted u_loc) -----
__global__ __launch_bounds__(256) void scan_kernel(
    const float* __restrict__ Qn, const float* __restrict__ Kn,
    const float* __restrict__ U,  const float* __restrict__ Wbuf,
    const float* __restrict__ Aloc, float* __restrict__ Dout, int L)
{
    extern __shared__ float sm[];
    float* Ssm_t = sm;                    // 32 x QP   (S^T: [c][d])
    float* q_s   = Ssm_t + 32*QP;         // 32 x QP   ([i][d])
    float* w_s   = q_s   + 32*QP;         // 32 x QP
    float* k_t   = w_s   + 32*QP;         // 256 x KTP ([d][t2])
    float* al    = k_t   + 256*KTP;       // 32 x KTP  ([i][t2])
    float* ul_t  = al    + 32*KTP;        // 32 x KTP  ([c][t2])

    int cb = blockIdx.x;
    int bh = blockIdx.y;
    int b = bh >> 2, h = bh & 3;
    int tid = threadIdx.x;
    int c  = tid & 31;
    int iw = tid >> 5;
    int nch = L / CHUNK;

    float Sreg[32];                       // S[d=r*8+iw][c]
#pragma unroll
    for (int r = 0; r < 32; ++r) Sreg[r] = 0.f;

    for (int ch = 0; ch < nch; ++ch) {
        int l0 = ch * CHUNK;
        size_t base = ((size_t)(b*L + l0)) * HID + h*DK;

        // S image transposed
#pragma unroll
        for (int r = 0; r < 32; ++r) Ssm_t[c*QP + r*8 + iw] = Sreg[r];
        // tiles
        for (int r = 0; r < 32; ++r) {
            size_t g = base + (size_t)r*HID + tid;
            q_s[r*QP + tid] = Qn[g];
            w_s[r*QP + tid] = Wbuf[g];
            k_t[tid*KTP + r] = Kn[g];
        }
        size_t abase = (size_t)((b*NH + h)*nch + ch) * 1024;
#pragma unroll
        for (int r = 0; r < 4; ++r)
            al[(r*8 + iw)*KTP + c] = Aloc[abase + (r*8 + iw)*32 + c];

        float uacc[4];
#pragma unroll
        for (int r = 0; r < 4; ++r)
            uacc[r] = U[((size_t)(b*L + l0 + (r*8 + iw)))*HID + h*DV + cb*32 + c];
        __syncthreads();

        // u_loc = u0 - w @ S  (rows i=r*8+iw, col c)
#pragma unroll 4
        for (int dq = 0; dq < 64; ++dq) {
            float4 sv = *(float4*)&Ssm_t[c*QP + dq*4];
#pragma unroll
            for (int r = 0; r < 4; ++r) {
                float4 wv = *(float4*)&w_s[(r*8 + iw)*QP + dq*4];
                uacc[r] -= wv.x*sv.x + wv.y*sv.y + wv.z*sv.z + wv.w*sv.w;
            }
        }
#pragma unroll
        for (int r = 0; r < 4; ++r) ul_t[c*KTP + r*8 + iw] = uacc[r];

        // o1 = q @ S (old S)
        float oacc[4] = {0.f, 0.f, 0.f, 0.f};
#pragma unroll 4
        for (int dq = 0; dq < 64; ++dq) {
            float4 sv = *(float4*)&Ssm_t[c*QP + dq*4];
#pragma unroll
            for (int r = 0; r < 4; ++r) {
                float4 qv = *(float4*)&q_s[(r*8 + iw)*QP + dq*4];
                oacc[r] += qv.x*sv.x + qv.y*sv.y + qv.z*sv.z + qv.w*sv.w;
            }
        }
        __syncthreads();

        // hoist u_loc column c
        float ulreg[32];
#pragma unroll
        for (int qq = 0; qq < 8; ++qq) {
            float4 t4 = *(float4*)&ul_t[c*KTP + qq*4];
            ulreg[qq*4] = t4.x; ulreg[qq*4+1] = t4.y;
            ulreg[qq*4+2] = t4.z; ulreg[qq*4+3] = t4.w;
        }

        // o2 = attn_loc @ u_loc
#pragma unroll
        for (int qq = 0; qq < 8; ++qq) {
#pragma unroll
            for (int r = 0; r < 4; ++r) {
                float4 av = *(float4*)&al[(r*8 + iw)*KTP + qq*4];
                oacc[r] += av.x*ulreg[qq*4] + av.y*ulreg[qq*4+1]
                         + av.z*ulreg[qq*4+2] + av.w*ulreg[qq*4+3];
            }
        }
#pragma unroll
        for (int r = 0; r < 4; ++r)
            Dout[((size_t)(b*L + l0 + (r*8 + iw)))*HID + h*DV + cb*32 + c] = oacc[r];

        // S += k^T @ u_loc
#pragma unroll
        for (int qq = 0; qq < 8; ++qq) {
#pragma unroll
            for (int r = 0; r < 32; ++r) {
                float4 kv = *(float4*)&k_t[(r*8 + iw)*KTP + qq*4];
                Sreg[r] += kv.x*ulreg[qq*4] + kv.y*ulreg[qq*4+1]
                         + kv.z*ulreg[qq*4+2] + kv.w*ulreg[qq*4+3];
            }
        }
        __syncthreads();
    }
}

// ---------------- stats ----------------------------------------------------------
__global__ __launch_bounds__(256) void stats_kernel(
    const float* __restrict__ LS, const float* __restrict__ LL,
    const float* __restrict__ DEL, const float* __restrict__ V,
    float* __restrict__ ST)
{
    int th = blockIdx.x;
    int d = threadIdx.x;
    size_t base = (size_t)th*256 + d;
    __shared__ float s1[256], s2[256], s3[256];
    const float* ptrs[4] = {LS, LL, DEL, V};
    for (int sig = 0; sig < 4; ++sig) {
        float x = ptrs[sig][base];
        s1[d] = x; s2[d] = x*x; s3[d] = fabsf(x);
        __syncthreads();
        for (int s = 128; s > 0; s >>= 1) {
            if (d < s) { s1[d] += s1[d+s]; s2[d] += s2[d+s]; s3[d] += s3[d+s]; }
            __syncthreads();
        }
        if (d == 0) {
            float sumsq = s2[0];
            float mean = s1[0] / 256.f;
            float var  = sumsq / 256.f - mean*mean;
            float am   = s3[0] / 256.f;
            float l2   = sqrtf(sumsq);
            float* o = ST + (size_t)th*16 + sig*4;
            o[0] = mean; o[1] = var; o[2] = am; o[3] = l2;
        }
        __syncthreads();
    }
}

// ---------------- gate MLP tail + softmax + floor -------------------------------
__global__ __launch_bounds__(256) void gate_kernel(
    const float* __restrict__ G1, const float* __restrict__ ST,
    const float* __restrict__ w1, const float* __restrict__ b1,
    const float* __restrict__ w2, const float* __restrict__ b2,
    const float* __restrict__ lt, float* __restrict__ P)
{
    int th = blockIdx.x;
    int t = th >> 2, h = th & 3;
    int tid = threadIdx.x;
    __shared__ float st[16];
    if (tid < 16) st[tid] = ST[(size_t)th*16 + tid];
    __syncthreads();
    float p0 = 0.f, p1 = 0.f, p2 = 0.f, p3 = 0.f;
    for (int j = tid; j < 1024; j += 256) {
        float x = G1[(size_t)t*1024 + j] + b1[j];
#pragma unroll
        for (int s = 0; s < 16; ++s) x += st[s] * w1[(size_t)(1024 + s)*1024 + j];
        float g = 0.5f * x * (1.f + erff(x * 0.70710678118654752f));
        p0 += g * w2[j*4 + 0]; p1 += g * w2[j*4 + 1];
        p2 += g * w2[j*4 + 2]; p3 += g * w2[j*4 + 3];
    }
    __shared__ float red[1024];
    red[tid] = p0; red[256+tid] = p1; red[512+tid] = p2; red[768+tid] = p3;
    __syncthreads();
    for (int s = 128; s > 0; s >>= 1) {
        if (tid < s) {
            red[tid]     += red[tid+s];     red[256+tid] += red[256+tid+s];
            red[512+tid] += red[512+tid+s]; red[768+tid] += red[768+tid+s];
        }
        __syncthreads();
    }
    if (tid == 0) {
        float inv_t = expf(-lt[h]);
        float l[4];
#pragma unroll
        for (int cc = 0; cc < 4; ++cc) l[cc] = (red[cc*256] + b2[cc]) * inv_t;
        float m = fmaxf(fmaxf(l[0], l[1]), fmaxf(l[2], l[3]));
        float e[4], ssum = 0.f;
#pragma unroll
        for (int cc = 0; cc < 4; ++cc) { e[cc] = expf(l[cc] - m); ssum += e[cc]; }
#pragma unroll
        for (int cc = 0; cc < 4; ++cc)
            P[(size_t)th*4 + cc] = 0.05f + 0.8f * (e[cc] / ssum);
    }
}

// ---------------- mix + RMSNorm ---------------------------------------------------
__global__ __launch_bounds__(256) void mix_kernel(
    const float* __restrict__ LS, const float* __restrict__ LL,
    const float* __restrict__ DEL, const float* __restrict__ V,
    const float* __restrict__ P, const float* __restrict__ onw,
    float* __restrict__ OM)
{
    int th = blockIdx.x;
    int d = threadIdx.x;
    size_t base = (size_t)th*256 + d;
    float p0 = P[th*4], p1 = P[th*4+1], p2 = P[th*4+2], p3 = P[th*4+3];
    float o = p0*LS[base] + p1*LL[base] + p2*DEL[base] + p3*V[base];
    __shared__ float s2[256];
    s2[d] = o*o;
    __syncthreads();
    for (int s = 128; s > 0; s >>= 1) {
        if (d < s) s2[d] += s2[d+s];
        __syncthreads();
    }
    float ms = s2[0] / 256.f;
    OM[base] = o * rsqrtf(ms + 1e-5f) * onw[d];
}

// ---------------- launch ----------------------------------------------------------
extern "C" void kernel_launch(void* const* d_in, const int* in_sizes, int n_in,
                              void* d_out, int out_size)
{
    const float* hs = (const float*)d_in[0];
    const float* Wq = (const float*)d_in[1];
    const float* Wk = (const float*)d_in[2];
    const float* Wv = (const float*)d_in[3];
    const float* Wb = (const float*)d_in[4];
    const float* cq = (const float*)d_in[5];
    const float* ck = (const float*)d_in[6];
    const float* cv = (const float*)d_in[7];
    const float* fs = (const float*)d_in[8];
    const float* fl = (const float*)d_in[9];
    const float* w1 = (const float*)d_in[10];
    const float* b1 = (const float*)d_in[11];
    const float* w2 = (const float*)d_in[12];
    const float* b2 = (const float*)d_in[13];
    const float* lt = (const float*)d_in[14];
    const float* onw= (const float*)d_in[15];
    const float* Wo = (const float*)d_in[16];

    const int T = in_sizes[0] / HID;
    const int B = 2;
    const int L = T / B;

    float *tmp, *q, *k, *v, *kb, *u, *w, *del, *ls, *ll, *g1, *om, *aloc, *beta, *st, *pr;
    __nv_bfloat16 *a2, *bth, *btl;
    cudaGetSymbolAddress((void**)&tmp,  g_tmp);
    cudaGetSymbolAddress((void**)&q,    g_q);
    cudaGetSymbolAddress((void**)&k,    g_k);
    cudaGetSymbolAddress((void**)&v,    g_v);
    cudaGetSymbolAddress((void**)&kb,   g_kb);
    cudaGetSymbolAddress((void**)&u,    g_u);
    cudaGetSymbolAddress((void**)&w,    g_w);
    cudaGetSymbolAddress((void**)&del,  g_del);
    cudaGetSymbolAddress((void**)&ls,   g_ls);
    cudaGetSymbolAddress((void**)&ll,   g_ll);
    cudaGetSymbolAddress((void**)&g1,   g_g1);
    cudaGetSymbolAddress((void**)&om,   g_om);
    cudaGetSymbolAddress((void**)&aloc, g_aloc);
    cudaGetSymbolAddress((void**)&beta, g_beta);
    cudaGetSymbolAddress((void**)&st,   g_stats);
    cudaGetSymbolAddress((void**)&pr,   g_probs);
    cudaGetSymbolAddress((void**)&a2,   g_a2);
    cudaGetSymbolAddress((void**)&bth,  g_bth);
    cudaGetSymbolAddress((void**)&btl,  g_btl);

    dim3 gg(HID/BN, T/BM);
    dim3 bt_grid(HID/32, HID/32);
    dim3 bt_blk(32, 8);
    int nconv = (T*HID + 255) / 256;
    int nsplit = (T*HID + 255) / 256;

    size_t chunk_smem = (size_t)(3*32*QP + 32*KTP) * 4;
    size_t scan_smem  = (size_t)(3*32*QP + 256*KTP + 2*32*KTP) * 4;
    cudaFuncSetAttribute(chunk_kernel, cudaFuncAttributeMaxDynamicSharedMemorySize, (int)chunk_smem);
    cudaFuncSetAttribute(scan_kernel,  cudaFuncAttributeMaxDynamicSharedMemorySize, (int)scan_smem);

    // split hs once (shared by q,k,v,gate GEMMs)
    asplit_kernel<<<nsplit, 256>>>(hs, a2, HID, T*HID);

    // q
    bsplit_kernel<<<bt_grid, bt_blk>>>(Wq, bth, btl, HID, HID);
    gemm_mma<<<gg, 256>>>(a2, bth, btl, tmp, T, HID, HID);
    conv_kernel<<<nconv, 256>>>(tmp, cq, q, L, 4, 1, T*HID);
    // k
    bsplit_kernel<<<bt_grid, bt_blk>>>(Wk, bth, btl, HID, HID);
    gemm_mma<<<gg, 256>>>(a2, bth, btl, tmp, T, HID, HID);
    conv_kernel<<<nconv, 256>>>(tmp, ck, k, L, 4, 1, T*HID);
    // v
    bsplit_kernel<<<bt_grid, bt_blk>>>(Wv, bth, btl, HID, HID);
    gemm_mma<<<gg, 256>>>(a2, bth, btl, tmp, T, HID, HID);
    conv_kernel<<<nconv, 256>>>(tmp, cv, v, L, 4, 1, T*HID);

    beta_kernel<<<(T*NH + 7) / 8, 256>>>(hs, Wb, beta, T);
    l2norm_kernel<<<T*NH, 256>>>(q, k, kb, beta);

    chunk_kernel<<<B*NH*(L/CHUNK), 256, chunk_smem>>>(q, k, kb, v, beta, u, w, aloc, L);
    scan_kernel<<<dim3(DV/32, B*NH), 256, scan_smem>>>(q, k, u, w, aloc, del, L);

    // FIR branches
    conv_kernel<<<nconv, 256>>>(v, fs, ls, L, 5, 0, T*HID);
    conv_kernel<<<nconv, 256>>>(v, fl, ll, L, 64, 0, T*HID);

    stats_kernel<<<T*NH, 256>>>(ls, ll, del, v, st);

    // gate GEMM
    bsplit_kernel<<<bt_grid, bt_blk>>>(w1, bth, btl, HID, HID);
    gemm_mma<<<gg, 256>>>(a2, bth, btl, g1, T, HID, HID);
    gate_kernel<<<T*NH, 256>>>(g1, st, w1, b1, w2, b2, lt, pr);

    mix_kernel<<<T*NH, 256>>>(ls, ll, del, v, pr, onw, om);

    // out = om @ Wo
    asplit_kernel<<<nsplit, 256>>>(om, a2, HID, T*HID);
    bsplit_kernel<<<bt_grid, bt_blk>>>(Wo, bth, btl, HID, HID);
    gemm_mma<<<gg, 256>>>(a2, bth, btl, (float*)d_out, T, HID, HID);
}

// round 7
// speedup vs baseline: 1.6746x; 1.1755x over previous
#include <cuda_runtime.h>
#include <cuda_bf16.h>
#include <math.h>
#include <stdint.h>

#define HID 1024
#define NH 4
#define DK 256
#define DV 256
#define CHUNK 32
#define TMAX 8192
#define QP 260     // float pitch, conflict-free float4 per-lane
#define KTP 36     // pitch for 32-wide transposed tiles
#define NC 16      // scan: dv columns per CTA

// ---------------- scratch (static device buffers; no allocation) ----------------
__device__ float g_tmp3 [TMAX*3*HID];
__device__ float g_q    [TMAX*HID];
__device__ float g_k    [TMAX*HID];
__device__ float g_v    [TMAX*HID];
__device__ float g_kb   [TMAX*HID];
__device__ float g_u    [TMAX*HID];
__device__ float g_w    [TMAX*HID];
__device__ float g_del  [TMAX*HID];
__device__ float g_ls   [TMAX*HID];
__device__ float g_ll   [TMAX*HID];
__device__ float g_g1   [TMAX*HID];
__device__ float g_om   [TMAX*HID];
__device__ float g_aloc [TMAX*NH*CHUNK];
__device__ float g_beta [TMAX*NH];
__device__ float g_stats[TMAX*NH*16];
__device__ float g_probs[TMAX*NH*4];
__device__ __nv_bfloat16 g_a2 [TMAX*2*HID];     // split hs / om
__device__ __nv_bfloat16 g_bth[3*HID*HID];      // B^T hi (up to 3 projections)
__device__ __nv_bfloat16 g_btl[3*HID*HID];      // B^T lo

__device__ __forceinline__ uint32_t smem_u32(const void* p) {
    uint32_t a;
    asm("{ .reg .u64 t; cvta.to.shared.u64 t, %1; cvt.u32.u64 %0, t; }" : "=r"(a) : "l"(p));
    return a;
}
__device__ __forceinline__ void cp16(uint32_t dst, const void* src) {
    asm volatile("cp.async.cg.shared.global [%0], [%1], 16;" :: "r"(dst), "l"(src));
}

// ---------------- precision-split prep kernels ----------------
__global__ void asplit_kernel(const float* __restrict__ X,
                              __nv_bfloat16* __restrict__ A2, int K, int total) {
    int idx = blockIdx.x * blockDim.x + threadIdx.x;
    if (idx >= total) return;
    int m = idx / K, kk = idx - m * K;
    float v = X[idx];
    __nv_bfloat16 hi = __float2bfloat16(v);
    float r = v - __bfloat162float(hi);
    A2[(size_t)m * 2 * K + kk]     = hi;
    A2[(size_t)m * 2 * K + K + kk] = __float2bfloat16(r);
}

__global__ void bsplit_kernel(const float* __restrict__ W,
                              __nv_bfloat16* __restrict__ Bh,
                              __nv_bfloat16* __restrict__ Bl, int K, int N) {
    __shared__ float t[32][33];
    int bn = blockIdx.x * 32, bk = blockIdx.y * 32;
    int x = threadIdx.x, y = threadIdx.y;
    for (int i = y; i < 32; i += 8) t[i][x] = W[(size_t)(bk + i) * N + bn + x];
    __syncthreads();
    for (int i = y; i < 32; i += 8) {
        float v = t[x][i];
        __nv_bfloat16 hi = __float2bfloat16(v);
        float r = v - __bfloat162float(hi);
        Bh[(size_t)(bn + i) * K + bk + x] = hi;
        Bl[(size_t)(bn + i) * K + bk + x] = __float2bfloat16(r);
    }
}

// ---------------- bf16 mma.sync GEMM (3-term split), BK=64 ----------------------
#define BM 128
#define BN 128
#define BK 64
#define APITCH 72    // bf16 elements; 144B rows, (9r+c)%8 quads conflict-free
#define ASTAGE (BM * APITCH * 2)            // bytes per A tile
#define GSTAGE (2 * ASTAGE)                 // bytes per stage (A+B)

__global__ __launch_bounds__(256) void gemm_mma(
    const __nv_bfloat16* __restrict__ A2, const __nv_bfloat16* __restrict__ Bh,
    const __nv_bfloat16* __restrict__ Bl, float* __restrict__ C,
    int M, int N, int K)
{
    extern __shared__ __align__(16) char gsm[];
    uint32_t sb = smem_u32(gsm);

    const int tid = threadIdx.x;
    const int wid = tid >> 5, lane = tid & 31;
    const int m0 = blockIdx.y * BM, n0 = blockIdx.x * BN;
    const int wm = (wid >> 2) * 64, wn = (wid & 3) * 32;

    const int KBn = K / BK;        // 16
    const int NB = 3 * KBn;        // 48
    const size_t sA = (size_t)2 * K;

    auto load_stage = [&](int kb, int buf) {
        int seg = kb / KBn;
        int kk = (kb - seg * KBn) * BK;
        const __nv_bfloat16* Ap = A2 + (seg == 1 ? (size_t)K : 0) + kk;
        const __nv_bfloat16* Bp = ((seg == 2) ? Bl : Bh) + kk;
        uint32_t a_s = sb + (uint32_t)buf * GSTAGE;
        uint32_t b_s = a_s + ASTAGE;
#pragma unroll
        for (int i = 0; i < 4; ++i) {
            int idx = i * 256 + tid;
            int row = idx >> 3, ch = idx & 7;
            cp16(a_s + (uint32_t)(row * APITCH + ch * 8) * 2,
                 Ap + (size_t)(m0 + row) * sA + ch * 8);
            cp16(b_s + (uint32_t)(row * APITCH + ch * 8) * 2,
                 Bp + (size_t)(n0 + row) * K + ch * 8);
        }
    };

    float acc[4][4][4];
#pragma unroll
    for (int mt = 0; mt < 4; ++mt)
#pragma unroll
        for (int nt = 0; nt < 4; ++nt)
#pragma unroll
            for (int e = 0; e < 4; ++e) acc[mt][nt][e] = 0.f;

    load_stage(0, 0);
    asm volatile("cp.async.commit_group;" ::: "memory");

    for (int kb = 0; kb < NB; ++kb) {
        int buf = kb & 1;
        if (kb + 1 < NB) load_stage(kb + 1, buf ^ 1);
        asm volatile("cp.async.commit_group;" ::: "memory");
        asm volatile("cp.async.wait_group 1;" ::: "memory");
        __syncthreads();

        uint32_t a_s = sb + (uint32_t)buf * GSTAGE;
        uint32_t b_s = a_s + ASTAGE;
#pragma unroll
        for (int kp = 0; kp < 4; ++kp) {
            uint32_t a[4][4], b[4][2];
            {
                int r_off = lane & 15;
                int c_off = kp * 16 + (lane >> 4) * 8;
#pragma unroll
                for (int mt = 0; mt < 4; ++mt) {
                    uint32_t addr = a_s + (uint32_t)((wm + mt * 16 + r_off) * APITCH + c_off) * 2;
                    asm volatile("ldmatrix.sync.aligned.m8n8.x4.shared.b16 {%0,%1,%2,%3}, [%4];"
                        : "=r"(a[mt][0]), "=r"(a[mt][1]), "=r"(a[mt][2]), "=r"(a[mt][3])
                        : "r"(addr));
                }
            }
            {
                int n_off = (lane & 7) + (lane >> 4) * 8;
                int c_off = kp * 16 + ((lane >> 3) & 1) * 8;
#pragma unroll
                for (int nb = 0; nb < 2; ++nb) {
                    uint32_t r0, r1, r2, r3;
                    uint32_t addr = b_s + (uint32_t)((wn + nb * 16 + n_off) * APITCH + c_off) * 2;
                    asm volatile("ldmatrix.sync.aligned.m8n8.x4.shared.b16 {%0,%1,%2,%3}, [%4];"
                        : "=r"(r0), "=r"(r1), "=r"(r2), "=r"(r3) : "r"(addr));
                    b[nb * 2][0] = r0;     b[nb * 2][1] = r1;
                    b[nb * 2 + 1][0] = r2; b[nb * 2 + 1][1] = r3;
                }
            }
#pragma unroll
            for (int mt = 0; mt < 4; ++mt)
#pragma unroll
                for (int nt = 0; nt < 4; ++nt) {
                    asm volatile(
                        "mma.sync.aligned.m16n8k16.row.col.f32.bf16.bf16.f32 "
                        "{%0,%1,%2,%3}, {%4,%5,%6,%7}, {%8,%9}, {%0,%1,%2,%3};"
                        : "+f"(acc[mt][nt][0]), "+f"(acc[mt][nt][1]),
                          "+f"(acc[mt][nt][2]), "+f"(acc[mt][nt][3])
                        : "r"(a[mt][0]), "r"(a[mt][1]), "r"(a[mt][2]), "r"(a[mt][3]),
                          "r"(b[nt][0]), "r"(b[nt][1]));
                }
        }
        __syncthreads();
    }

    int g = lane >> 2, tg = lane & 3;
#pragma unroll
    for (int mt = 0; mt < 4; ++mt) {
#pragma unroll
        for (int nt = 0; nt < 4; ++nt) {
            int row = m0 + wm + mt * 16 + g;
            int col = n0 + wn + nt * 8 + tg * 2;
            *(float2*)(C + (size_t)row * N + col) =
                make_float2(acc[mt][nt][0], acc[mt][nt][1]);
            *(float2*)(C + (size_t)(row + 8) * N + col) =
                make_float2(acc[mt][nt][2], acc[mt][nt][3]);
        }
    }
}

// ---------------- fused QKV causal conv + SiLU ----------------------------------
__global__ void conv_qkv_kernel(const float* __restrict__ x3,
                                const float* __restrict__ cq, const float* __restrict__ ck,
                                const float* __restrict__ cv,
                                float* __restrict__ q, float* __restrict__ k,
                                float* __restrict__ v, int L, int total)
{
    int idx = blockIdx.x * blockDim.x + threadIdx.x;
    if (idx >= total) return;
    int c3 = idx % 3072;
    int t = idx / 3072;
    int b = t / L, l = t % L;
    int proj = c3 >> 10, c = c3 & 1023;
    const float* w = (proj == 0) ? cq : ((proj == 1) ? ck : cv);
    float* y = (proj == 0) ? q : ((proj == 1) ? k : v);
    float acc = 0.f;
#pragma unroll
    for (int kk = 0; kk < 4; ++kk) {
        int ll = l - 3 + kk;
        if (ll >= 0) acc += x3[((size_t)(b*L + ll))*3072 + c3] * w[c*4 + kk];
    }
    acc = acc / (1.f + expf(-acc));
    y[(size_t)t*HID + c] = acc;
}

// ---------------- FIR conv (no act) ----------------------------------------------
__global__ void conv_kernel(const float* __restrict__ x, const float* __restrict__ w,
                            float* __restrict__ y, int L, int K, int total)
{
    int idx = blockIdx.x * blockDim.x + threadIdx.x;
    if (idx >= total) return;
    int c = idx % HID;
    int t = idx / HID;
    int b = t / L, l = t % L;
    float acc = 0.f;
#pragma unroll 4
    for (int kk = 0; kk < K; ++kk) {
        int ll = l - (K - 1) + kk;
        if (ll >= 0) acc += x[((size_t)(b*L + ll))*HID + c] * w[c*K + kk];
    }
    y[idx] = acc;
}

// ---------------- beta ------------------------------------------------------------
__global__ void beta_kernel(const float* __restrict__ hs, const float* __restrict__ Wb,
                            float* __restrict__ beta, int T)
{
    int gw = (blockIdx.x * blockDim.x + threadIdx.x) >> 5;
    int lane = threadIdx.x & 31;
    if (gw >= T * NH) return;
    int t = gw / NH, h = gw % NH;
    float s = 0.f;
    for (int r = lane; r < HID; r += 32) s += hs[(size_t)t*HID + r] * Wb[r*NH + h];
#pragma unroll
    for (int off = 16; off; off >>= 1) s += __shfl_down_sync(0xffffffff, s, off);
    if (lane == 0) beta[t*NH + h] = 1.f / (1.f + expf(-s));
}

// ---------------- l2norm + kb -----------------------------------------------------
__global__ __launch_bounds__(256) void l2norm_kernel(
    float* __restrict__ Q, float* __restrict__ Kp, float* __restrict__ KB,
    const float* __restrict__ beta)
{
    int th = blockIdx.x;
    int t = th >> 2, h = th & 3;
    int d = threadIdx.x;
    size_t base = (size_t)t*HID + h*DK;
    float qv = Q[base + d], kv = Kp[base + d];
    __shared__ float sq[256], sk[256];
    sq[d] = qv*qv; sk[d] = kv*kv;
    __syncthreads();
    for (int s = 128; s > 0; s >>= 1) {
        if (d < s) { sq[d] += sq[d+s]; sk[d] += sk[d+s]; }
        __syncthreads();
    }
    float rq = rsqrtf(sq[0] + 1e-6f);
    float rk = rsqrtf(sk[0] + 1e-6f);
    float bb = beta[t*NH + h];
    Q[base + d]  = qv * rq;
    float kn = kv * rk;
    Kp[base + d] = kn;
    KB[base + d] = kn * bb;
}

// ---------------- per-chunk: attn inversion + u, w, attn_loc --------------------
__global__ __launch_bounds__(256) void chunk_kernel(
    const float* __restrict__ Qn, const float* __restrict__ Kn,
    const float* __restrict__ KB, const float* __restrict__ V,
    const float* __restrict__ beta, float* __restrict__ U,
    float* __restrict__ Wbuf, float* __restrict__ Aloc, int L)
{
    extern __shared__ float sm[];
    float* q_s  = sm;                 // 32*QP
    float* kn_s = q_s  + 32*QP;
    float* kb_s = kn_s + 32*QP;
    float* A    = kb_s + 32*QP;       // 32*KTP
    int nch = L / CHUNK;
    int cid = blockIdx.x;
    int ch = cid % nch;
    int h  = (cid / nch) & (NH - 1);
    int b  = cid / (nch * NH);
    int l0 = ch * CHUNK;
    int tid = threadIdx.x;
    int lane = tid & 31;
    int iw = tid >> 5;
    size_t base = ((size_t)(b*L + l0)) * HID + h*DK;

    for (int r = 0; r < 32; ++r) {
        size_t g = base + (size_t)r*HID + tid;
        q_s [r*QP + tid] = Qn[g];
        kn_s[r*QP + tid] = Kn[g];
        kb_s[r*QP + tid] = KB[g];
    }
    __syncthreads();

    size_t abase = (size_t)cid * (CHUNK*CHUNK);
#pragma unroll
    for (int r = 0; r < 4; ++r) {
        int i = r*8 + iw, j = lane;
        float sA = 0.f, sL = 0.f;
#pragma unroll 8
        for (int dq = 0; dq < 64; ++dq) {
            float4 kn = *(float4*)&kn_s[j*QP + dq*4];
            float4 kb = *(float4*)&kb_s[i*QP + dq*4];
            float4 qv = *(float4*)&q_s [i*QP + dq*4];
            sA += kb.x*kn.x + kb.y*kn.y + kb.z*kn.z + kb.w*kn.w;
            sL += qv.x*kn.x + qv.y*kn.y + qv.z*kn.z + qv.w*kn.w;
        }
        A[i*KTP + j] = (i > j) ? -sA : 0.f;
        Aloc[abase + i*32 + j] = (j <= i) ? sL : 0.f;
    }
    __syncthreads();

    if (tid < 32) {
        int j = tid;
        for (int i = 1; i < 32; ++i) {
            float s = 0.f;
            if (j < i) {
#pragma unroll
                for (int t2 = 0; t2 < 32; ++t2) s += A[i*KTP + t2] * A[t2*KTP + j];
            }
            __syncwarp();
            if (j < i) A[i*KTP + j] += s;
            __syncwarp();
        }
        A[j*KTP + j] += 1.f;
    }
    __syncthreads();

    for (int r = 0; r < 32; ++r) {
        float bb = beta[(b*L + l0 + r)*NH + h];
        q_s[r*QP + tid] = V[base + (size_t)r*HID + tid] * bb;
    }
    __syncthreads();

    float vc[32], kc[32];
#pragma unroll
    for (int t2 = 0; t2 < 32; ++t2) {
        vc[t2] = q_s [t2*QP + tid];
        kc[t2] = kb_s[t2*QP + tid];
    }

    for (int i = 0; i < 32; ++i) {
        float su = 0.f, sw = 0.f;
#pragma unroll
        for (int qq = 0; qq < 8; ++qq) {
            float4 a = *(float4*)&A[i*KTP + qq*4];
            su += a.x*vc[qq*4] + a.y*vc[qq*4+1] + a.z*vc[qq*4+2] + a.w*vc[qq*4+3];
            sw += a.x*kc[qq*4] + a.y*kc[qq*4+1] + a.z*kc[qq*4+2] + a.w*kc[qq*4+3];
        }
        U   [base + (size_t)i*HID + tid] = su;
        Wbuf[base + (size_t)i*HID + tid] = sw;
    }
}

// ---------------- sequential chunk scan: 128 CTAs, 16 cols each -----------------
__global__ __launch_bounds__(256) void scan_kernel(
    const float* __restrict__ Qn, const float* __restrict__ Kn,
    const float* __restrict__ U,  const float* __restrict__ Wbuf,
    const float* __restrict__ Aloc, float* __restrict__ Dout, int L)
{
    extern __shared__ float sm[];
    float* Ssm_t = sm;                    // NC x QP   (S^T: [c][d])
    float* q_s   = Ssm_t + NC*QP;         // 32 x QP
    float* w_s   = q_s   + 32*QP;         // 32 x QP
    float* k_t   = w_s   + 32*QP;         // 256 x KTP ([d][t2])
    float* al    = k_t   + 256*KTP;       // 32 x KTP
    float* ul_t  = al    + 32*KTP;        // NC x KTP  ([c][t2])

    int cb = blockIdx.x;                  // 0..15
    int bh = blockIdx.y;
    int b = bh >> 2, h = bh & 3;
    int tid = threadIdx.x;
    int c  = tid & (NC - 1);
    int gi = tid >> 4;                    // 0..15
    int nch = L / CHUNK;

    float Sreg[16];                       // S[d=r*16+gi][c]
#pragma unroll
    for (int r = 0; r < 16; ++r) Sreg[r] = 0.f;

    for (int ch = 0; ch < nch; ++ch) {
        int l0 = ch * CHUNK;
        size_t base = ((size_t)(b*L + l0)) * HID + h*DK;

        // S image transposed
#pragma unroll
        for (int r = 0; r < 16; ++r) Ssm_t[c*QP + r*16 + gi] = Sreg[r];
        // tiles
        for (int r = 0; r < 32; ++r) {
            size_t g = base + (size_t)r*HID + tid;
            q_s[r*QP + tid] = Qn[g];
            w_s[r*QP + tid] = Wbuf[g];
            k_t[tid*KTP + r] = Kn[g];
        }
        size_t abase = (size_t)((b*NH + h)*nch + ch) * 1024;
#pragma unroll
        for (int e0 = 0; e0 < 4; ++e0) {
            int e = e0*256 + tid;
            al[(e >> 5)*KTP + (e & 31)] = Aloc[abase + e];
        }

        float uacc[2], oacc[2] = {0.f, 0.f};
#pragma unroll
        for (int r2 = 0; r2 < 2; ++r2)
            uacc[r2] = U[((size_t)(b*L + l0 + (r2*16 + gi)))*HID + h*DV + cb*NC + c];
        __syncthreads();

        // fused: u_loc = u0 - w @ S  AND  o1 = q @ S (one sv load each dq)
#pragma unroll 4
        for (int dq = 0; dq < 64; ++dq) {
            float4 sv = *(float4*)&Ssm_t[c*QP + dq*4];
#pragma unroll
            for (int r2 = 0; r2 < 2; ++r2) {
                int i = r2*16 + gi;
                float4 wv = *(float4*)&w_s[i*QP + dq*4];
                float4 qv = *(float4*)&q_s[i*QP + dq*4];
                uacc[r2] -= wv.x*sv.x + wv.y*sv.y + wv.z*sv.z + wv.w*sv.w;
                oacc[r2] += qv.x*sv.x + qv.y*sv.y + qv.z*sv.z + qv.w*sv.w;
            }
        }
#pragma unroll
        for (int r2 = 0; r2 < 2; ++r2) ul_t[c*KTP + r2*16 + gi] = uacc[r2];
        __syncthreads();

        // hoist u_loc column c
        float ulreg[32];
#pragma unroll
        for (int qq = 0; qq < 8; ++qq) {
            float4 t4 = *(float4*)&ul_t[c*KTP + qq*4];
            ulreg[qq*4] = t4.x; ulreg[qq*4+1] = t4.y;
            ulreg[qq*4+2] = t4.z; ulreg[qq*4+3] = t4.w;
        }

        // o2 = attn_loc @ u_loc
#pragma unroll
        for (int qq = 0; qq < 8; ++qq) {
#pragma unroll
            for (int r2 = 0; r2 < 2; ++r2) {
                int i = r2*16 + gi;
                float4 av = *(float4*)&al[i*KTP + qq*4];
                oacc[r2] += av.x*ulreg[qq*4] + av.y*ulreg[qq*4+1]
                          + av.z*ulreg[qq*4+2] + av.w*ulreg[qq*4+3];
            }
        }
#pragma unroll
        for (int r2 = 0; r2 < 2; ++r2)
            Dout[((size_t)(b*L + l0 + (r2*16 + gi)))*HID + h*DV + cb*NC + c] = oacc[r2];

        // S += k^T @ u_loc
#pragma unroll
        for (int qq = 0; qq < 8; ++qq) {
#pragma unroll
            for (int r = 0; r < 16; ++r) {
                float4 kv = *(float4*)&k_t[(r*16 + gi)*KTP + qq*4];
                Sreg[r] += kv.x*ulreg[qq*4] + kv.y*ulreg[qq*4+1]
                         + kv.z*ulreg[qq*4+2] + kv.w*ulreg[qq*4+3];
            }
        }
        __syncthreads();
    }
}

// ---------------- stats ----------------------------------------------------------
__global__ __launch_bounds__(256) void stats_kernel(
    const float* __restrict__ LS, const float* __restrict__ LL,
    const float* __restrict__ DEL, const float* __restrict__ V,
    float* __restrict__ ST)
{
    int th = blockIdx.x;
    int d = threadIdx.x;
    size_t base = (size_t)th*256 + d;
    __shared__ float s1[256], s2[256], s3[256];
    const float* ptrs[4] = {LS, LL, DEL, V};
    for (int sig = 0; sig < 4; ++sig) {
        float x = ptrs[sig][base];
        s1[d] = x; s2[d] = x*x; s3[d] = fabsf(x);
        __syncthreads();
        for (int s = 128; s > 0; s >>= 1) {
            if (d < s) { s1[d] += s1[d+s]; s2[d] += s2[d+s]; s3[d] += s3[d+s]; }
            __syncthreads();
        }
        if (d == 0) {
            float sumsq = s2[0];
            float mean = s1[0] / 256.f;
            float var  = sumsq / 256.f - mean*mean;
            float am   = s3[0] / 256.f;
            float l2   = sqrtf(sumsq);
            float* o = ST + (size_t)th*16 + sig*4;
            o[0] = mean; o[1] = var; o[2] = am; o[3] = l2;
        }
        __syncthreads();
    }
}

// ---------------- gate MLP tail + softmax + floor -------------------------------
__global__ __launch_bounds__(256) void gate_kernel(
    const float* __restrict__ G1, const float* __restrict__ ST,
    const float* __restrict__ w1, const float* __restrict__ b1,
    const float* __restrict__ w2, const float* __restrict__ b2,
    const float* __restrict__ lt, float* __restrict__ P)
{
    int th = blockIdx.x;
    int t = th >> 2, h = th & 3;
    int tid = threadIdx.x;
    __shared__ float st[16];
    if (tid < 16) st[tid] = ST[(size_t)th*16 + tid];
    __syncthreads();
    float p0 = 0.f, p1 = 0.f, p2 = 0.f, p3 = 0.f;
    for (int j = tid; j < 1024; j += 256) {
        float x = G1[(size_t)t*1024 + j] + b1[j];
#pragma unroll
        for (int s = 0; s < 16; ++s) x += st[s] * w1[(size_t)(1024 + s)*1024 + j];
        float g = 0.5f * x * (1.f + erff(x * 0.70710678118654752f));
        p0 += g * w2[j*4 + 0]; p1 += g * w2[j*4 + 1];
        p2 += g * w2[j*4 + 2]; p3 += g * w2[j*4 + 3];
    }
    __shared__ float red[1024];
    red[tid] = p0; red[256+tid] = p1; red[512+tid] = p2; red[768+tid] = p3;
    __syncthreads();
    for (int s = 128; s > 0; s >>= 1) {
        if (tid < s) {
            red[tid]     += red[tid+s];     red[256+tid] += red[256+tid+s];
            red[512+tid] += red[512+tid+s]; red[768+tid] += red[768+tid+s];
        }
        __syncthreads();
    }
    if (tid == 0) {
        float inv_t = expf(-lt[h]);
        float l[4];
#pragma unroll
        for (int cc = 0; cc < 4; ++cc) l[cc] = (red[cc*256] + b2[cc]) * inv_t;
        float m = fmaxf(fmaxf(l[0], l[1]), fmaxf(l[2], l[3]));
        float e[4], ssum = 0.f;
#pragma unroll
        for (int cc = 0; cc < 4; ++cc) { e[cc] = expf(l[cc] - m); ssum += e[cc]; }
#pragma unroll
        for (int cc = 0; cc < 4; ++cc)
            P[(size_t)th*4 + cc] = 0.05f + 0.8f * (e[cc] / ssum);
    }
}

// ---------------- mix + RMSNorm ---------------------------------------------------
__global__ __launch_bounds__(256) void mix_kernel(
    const float* __restrict__ LS, const float* __restrict__ LL,
    const float* __restrict__ DEL, const float* __restrict__ V,
    const float* __restrict__ P, const float* __restrict__ onw,
    float* __restrict__ OM)
{
    int th = blockIdx.x;
    int d = threadIdx.x;
    size_t base = (size_t)th*256 + d;
    float p0 = P[th*4], p1 = P[th*4+1], p2 = P[th*4+2], p3 = P[th*4+3];
    float o = p0*LS[base] + p1*LL[base] + p2*DEL[base] + p3*V[base];
    __shared__ float s2[256];
    s2[d] = o*o;
    __syncthreads();
    for (int s = 128; s > 0; s >>= 1) {
        if (d < s) s2[d] += s2[d+s];
        __syncthreads();
    }
    float ms = s2[0] / 256.f;
    OM[base] = o * rsqrtf(ms + 1e-5f) * onw[d];
}

// ---------------- launch ----------------------------------------------------------
extern "C" void kernel_launch(void* const* d_in, const int* in_sizes, int n_in,
                              void* d_out, int out_size)
{
    const float* hs = (const float*)d_in[0];
    const float* Wq = (const float*)d_in[1];
    const float* Wk = (const float*)d_in[2];
    const float* Wv = (const float*)d_in[3];
    const float* Wb = (const float*)d_in[4];
    const float* cq = (const float*)d_in[5];
    const float* ck = (const float*)d_in[6];
    const float* cv = (const float*)d_in[7];
    const float* fs = (const float*)d_in[8];
    const float* fl = (const float*)d_in[9];
    const float* w1 = (const float*)d_in[10];
    const float* b1 = (const float*)d_in[11];
    const float* w2 = (const float*)d_in[12];
    const float* b2 = (const float*)d_in[13];
    const float* lt = (const float*)d_in[14];
    const float* onw= (const float*)d_in[15];
    const float* Wo = (const float*)d_in[16];

    const int T = in_sizes[0] / HID;
    const int B = 2;
    const int L = T / B;

    float *tmp3, *q, *k, *v, *kb, *u, *w, *del, *ls, *ll, *g1, *om, *aloc, *beta, *st, *pr;
    __nv_bfloat16 *a2, *bth, *btl;
    cudaGetSymbolAddress((void**)&tmp3, g_tmp3);
    cudaGetSymbolAddress((void**)&q,    g_q);
    cudaGetSymbolAddress((void**)&k,    g_k);
    cudaGetSymbolAddress((void**)&v,    g_v);
    cudaGetSymbolAddress((void**)&kb,   g_kb);
    cudaGetSymbolAddress((void**)&u,    g_u);
    cudaGetSymbolAddress((void**)&w,    g_w);
    cudaGetSymbolAddress((void**)&del,  g_del);
    cudaGetSymbolAddress((void**)&ls,   g_ls);
    cudaGetSymbolAddress((void**)&ll,   g_ll);
    cudaGetSymbolAddress((void**)&g1,   g_g1);
    cudaGetSymbolAddress((void**)&om,   g_om);
    cudaGetSymbolAddress((void**)&aloc, g_aloc);
    cudaGetSymbolAddress((void**)&beta, g_beta);
    cudaGetSymbolAddress((void**)&st,   g_stats);
    cudaGetSymbolAddress((void**)&pr,   g_probs);
    cudaGetSymbolAddress((void**)&a2,   g_a2);
    cudaGetSymbolAddress((void**)&bth,  g_bth);
    cudaGetSymbolAddress((void**)&btl,  g_btl);

    dim3 bt_grid(HID/32, HID/32);
    dim3 bt_blk(32, 8);
    int nconv = (T*HID + 255) / 256;
    int nsplit = (T*HID + 255) / 256;

    const int GEMM_SMEM = 2 * GSTAGE;      // 73728 B
    cudaFuncSetAttribute(gemm_mma, cudaFuncAttributeMaxDynamicSharedMemorySize, GEMM_SMEM);

    size_t chunk_smem = (size_t)(3*32*QP + 32*KTP) * 4;
    size_t scan_smem  = (size_t)(NC*QP + 2*32*QP + 256*KTP + 32*KTP + NC*KTP) * 4;
    cudaFuncSetAttribute(chunk_kernel, cudaFuncAttributeMaxDynamicSharedMemorySize, (int)chunk_smem);
    cudaFuncSetAttribute(scan_kernel,  cudaFuncAttributeMaxDynamicSharedMemorySize, (int)scan_smem);

    // split hs once
    asplit_kernel<<<nsplit, 256>>>(hs, a2, HID, T*HID);

    // merged QKV GEMM: B^T = [Wq; Wk; Wv] rows
    bsplit_kernel<<<bt_grid, bt_blk>>>(Wq, bth,               btl,               HID, HID);
    bsplit_kernel<<<bt_grid, bt_blk>>>(Wk, bth + HID*HID,     btl + HID*HID,     HID, HID);
    bsplit_kernel<<<bt_grid, bt_blk>>>(Wv, bth + 2*HID*HID,   btl + 2*HID*HID,   HID, HID);
    {
        dim3 gg(3*HID/BN, T/BM);   // 24 x 64
        gemm_mma<<<gg, 256, GEMM_SMEM>>>(a2, bth, btl, tmp3, T, 3*HID, HID);
    }
    conv_qkv_kernel<<<(T*3*HID + 255)/256, 256>>>(tmp3, cq, ck, cv, q, k, v, L, T*3*HID);

    beta_kernel<<<(T*NH + 7) / 8, 256>>>(hs, Wb, beta, T);
    l2norm_kernel<<<T*NH, 256>>>(q, k, kb, beta);

    chunk_kernel<<<B*NH*(L/CHUNK), 256, chunk_smem>>>(q, k, kb, v, beta, u, w, aloc, L);
    scan_kernel<<<dim3(DV/NC, B*NH), 256, scan_smem>>>(q, k, u, w, aloc, del, L);

    // FIR branches
    conv_kernel<<<nconv, 256>>>(v, fs, ls, L, 5, T*HID);
    conv_kernel<<<nconv, 256>>>(v, fl, ll, L, 64, T*HID);

    stats_kernel<<<T*NH, 256>>>(ls, ll, del, v, st);

    // gate GEMM
    bsplit_kernel<<<bt_grid, bt_blk>>>(w1, bth, btl, HID, HID);
    {
        dim3 gg(HID/BN, T/BM);
        gemm_mma<<<gg, 256, GEMM_SMEM>>>(a2, bth, btl, g1, T, HID, HID);
    }
    gate_kernel<<<T*NH, 256>>>(g1, st, w1, b1, w2, b2, lt, pr);

    mix_kernel<<<T*NH, 256>>>(ls, ll, del, v, pr, onw, om);

    // out = om @ Wo
    asplit_kernel<<<nsplit, 256>>>(om, a2, HID, T*HID);
    bsplit_kernel<<<bt_grid, bt_blk>>>(Wo, bth, btl, HID, HID);
    {
        dim3 gg(HID/BN, T/BM);
        gemm_mma<<<gg, 256, GEMM_SMEM>>>(a2, bth, btl, (float*)d_out, T, HID, HID);
    }
}

// round 8
// speedup vs baseline: 2.8360x; 1.6935x over previous
#include <cuda_runtime.h>
#include <cuda_bf16.h>
#include <math.h>
#include <stdint.h>

#define HID 1024
#define NH 4
#define DK 256
#define DV 256
#define CHUNK 32
#define TMAX 8192
#define QP 260
#define KTP 36
#define NC 16

// ---------------- scratch ----------------
__device__ float g_tmp3 [TMAX*3*HID];
__device__ float g_q    [TMAX*HID];
__device__ float g_k    [TMAX*HID];
__device__ float g_v    [TMAX*HID];
__device__ float g_kb   [TMAX*HID];
__device__ float g_u    [TMAX*HID];
__device__ float g_w    [TMAX*HID];
__device__ float g_del  [TMAX*HID];
__device__ float g_ls   [TMAX*HID];
__device__ float g_ll   [TMAX*HID];
__device__ float g_g1   [TMAX*HID];
__device__ float g_om   [TMAX*HID];
__device__ float g_aloc [TMAX*NH*CHUNK];
__device__ float g_beta [TMAX*NH];
__device__ float g_stats[TMAX*NH*16];
__device__ float g_probs[TMAX*NH*4];
__device__ __nv_bfloat16 g_a2 [TMAX*2*HID];
__device__ __nv_bfloat16 g_bth[3*HID*HID];
__device__ __nv_bfloat16 g_btl[3*HID*HID];

__device__ __forceinline__ uint32_t smem_u32(const void* p) {
    uint32_t a;
    asm("{ .reg .u64 t; cvta.to.shared.u64 t, %1; cvt.u32.u64 %0, t; }" : "=r"(a) : "l"(p));
    return a;
}
__device__ __forceinline__ void cp16(uint32_t dst, const void* src) {
    asm volatile("cp.async.cg.shared.global [%0], [%1], 16;" :: "r"(dst), "l"(src));
}

// ---------------- precision-split prep ----------------
__global__ void asplit_kernel(const float* __restrict__ X,
                              __nv_bfloat16* __restrict__ A2, int K, int total) {
    int idx = blockIdx.x * blockDim.x + threadIdx.x;
    if (idx >= total) return;
    int m = idx / K, kk = idx - m * K;
    float v = X[idx];
    __nv_bfloat16 hi = __float2bfloat16(v);
    float r = v - __bfloat162float(hi);
    A2[(size_t)m * 2 * K + kk]     = hi;
    A2[(size_t)m * 2 * K + K + kk] = __float2bfloat16(r);
}

__global__ void bsplit_kernel(const float* __restrict__ W,
                              __nv_bfloat16* __restrict__ Bh,
                              __nv_bfloat16* __restrict__ Bl, int K, int N) {
    __shared__ float t[32][33];
    int bn = blockIdx.x * 32, bk = blockIdx.y * 32;
    int x = threadIdx.x, y = threadIdx.y;
    for (int i = y; i < 32; i += 8) t[i][x] = W[(size_t)(bk + i) * N + bn + x];
    __syncthreads();
    for (int i = y; i < 32; i += 8) {
        float v = t[x][i];
        __nv_bfloat16 hi = __float2bfloat16(v);
        float r = v - __bfloat162float(hi);
        Bh[(size_t)(bn + i) * K + bk + x] = hi;
        Bl[(size_t)(bn + i) * K + bk + x] = __float2bfloat16(r);
    }
}

// ---------------- bf16 mma.sync GEMM (3-term split), BK=64 ----------------------
#define BM 128
#define BN 128
#define BK 64
#define APITCH 72
#define ASTAGE (BM * APITCH * 2)
#define GSTAGE (2 * ASTAGE)

__global__ __launch_bounds__(256) void gemm_mma(
    const __nv_bfloat16* __restrict__ A2, const __nv_bfloat16* __restrict__ Bh,
    const __nv_bfloat16* __restrict__ Bl, float* __restrict__ C,
    int M, int N, int K)
{
    extern __shared__ __align__(16) char gsm[];
    uint32_t sb = smem_u32(gsm);

    const int tid = threadIdx.x;
    const int wid = tid >> 5, lane = tid & 31;
    const int m0 = blockIdx.y * BM, n0 = blockIdx.x * BN;
    const int wm = (wid >> 2) * 64, wn = (wid & 3) * 32;

    const int KBn = K / BK;
    const int NB = 3 * KBn;
    const size_t sA = (size_t)2 * K;

    auto load_stage = [&](int kb, int buf) {
        int seg = kb / KBn;
        int kk = (kb - seg * KBn) * BK;
        const __nv_bfloat16* Ap = A2 + (seg == 1 ? (size_t)K : 0) + kk;
        const __nv_bfloat16* Bp = ((seg == 2) ? Bl : Bh) + kk;
        uint32_t a_s = sb + (uint32_t)buf * GSTAGE;
        uint32_t b_s = a_s + ASTAGE;
#pragma unroll
        for (int i = 0; i < 4; ++i) {
            int idx = i * 256 + tid;
            int row = idx >> 3, ch = idx & 7;
            cp16(a_s + (uint32_t)(row * APITCH + ch * 8) * 2,
                 Ap + (size_t)(m0 + row) * sA + ch * 8);
            cp16(b_s + (uint32_t)(row * APITCH + ch * 8) * 2,
                 Bp + (size_t)(n0 + row) * K + ch * 8);
        }
    };

    float acc[4][4][4];
#pragma unroll
    for (int mt = 0; mt < 4; ++mt)
#pragma unroll
        for (int nt = 0; nt < 4; ++nt)
#pragma unroll
            for (int e = 0; e < 4; ++e) acc[mt][nt][e] = 0.f;

    load_stage(0, 0);
    asm volatile("cp.async.commit_group;" ::: "memory");

    for (int kb = 0; kb < NB; ++kb) {
        int buf = kb & 1;
        if (kb + 1 < NB) load_stage(kb + 1, buf ^ 1);
        asm volatile("cp.async.commit_group;" ::: "memory");
        asm volatile("cp.async.wait_group 1;" ::: "memory");
        __syncthreads();

        uint32_t a_s = sb + (uint32_t)buf * GSTAGE;
        uint32_t b_s = a_s + ASTAGE;
#pragma unroll
        for (int kp = 0; kp < 4; ++kp) {
            uint32_t a[4][4], b[4][2];
            {
                int r_off = lane & 15;
                int c_off = kp * 16 + (lane >> 4) * 8;
#pragma unroll
                for (int mt = 0; mt < 4; ++mt) {
                    uint32_t addr = a_s + (uint32_t)((wm + mt * 16 + r_off) * APITCH + c_off) * 2;
                    asm volatile("ldmatrix.sync.aligned.m8n8.x4.shared.b16 {%0,%1,%2,%3}, [%4];"
                        : "=r"(a[mt][0]), "=r"(a[mt][1]), "=r"(a[mt][2]), "=r"(a[mt][3])
                        : "r"(addr));
                }
            }
            {
                int n_off = (lane & 7) + (lane >> 4) * 8;
                int c_off = kp * 16 + ((lane >> 3) & 1) * 8;
#pragma unroll
                for (int nb = 0; nb < 2; ++nb) {
                    uint32_t r0, r1, r2, r3;
                    uint32_t addr = b_s + (uint32_t)((wn + nb * 16 + n_off) * APITCH + c_off) * 2;
                    asm volatile("ldmatrix.sync.aligned.m8n8.x4.shared.b16 {%0,%1,%2,%3}, [%4];"
                        : "=r"(r0), "=r"(r1), "=r"(r2), "=r"(r3) : "r"(addr));
                    b[nb * 2][0] = r0;     b[nb * 2][1] = r1;
                    b[nb * 2 + 1][0] = r2; b[nb * 2 + 1][1] = r3;
                }
            }
#pragma unroll
            for (int mt = 0; mt < 4; ++mt)
#pragma unroll
                for (int nt = 0; nt < 4; ++nt) {
                    asm volatile(
                        "mma.sync.aligned.m16n8k16.row.col.f32.bf16.bf16.f32 "
                        "{%0,%1,%2,%3}, {%4,%5,%6,%7}, {%8,%9}, {%0,%1,%2,%3};"
                        : "+f"(acc[mt][nt][0]), "+f"(acc[mt][nt][1]),
                          "+f"(acc[mt][nt][2]), "+f"(acc[mt][nt][3])
                        : "r"(a[mt][0]), "r"(a[mt][1]), "r"(a[mt][2]), "r"(a[mt][3]),
                          "r"(b[nt][0]), "r"(b[nt][1]));
                }
        }
        __syncthreads();
    }

    int g = lane >> 2, tg = lane & 3;
#pragma unroll
    for (int mt = 0; mt < 4; ++mt) {
#pragma unroll
        for (int nt = 0; nt < 4; ++nt) {
            int row = m0 + wm + mt * 16 + g;
            int col = n0 + wn + nt * 8 + tg * 2;
            *(float2*)(C + (size_t)row * N + col) =
                make_float2(acc[mt][nt][0], acc[mt][nt][1]);
            *(float2*)(C + (size_t)(row + 8) * N + col) =
                make_float2(acc[mt][nt][2], acc[mt][nt][3]);
        }
    }
}

// ---------------- fused QKV causal conv + SiLU (float4) -------------------------
__global__ void conv_qkv_kernel(const float* __restrict__ x3,
                                const float* __restrict__ cq, const float* __restrict__ ck,
                                const float* __restrict__ cv,
                                float* __restrict__ q, float* __restrict__ k,
                                float* __restrict__ v, int L, int total4)
{
    int idx = blockIdx.x * blockDim.x + threadIdx.x;
    if (idx >= total4) return;
    int c4 = idx % 768;             // group of 4 channels within 3072
    int t = idx / 768;
    int b = t / L, l = t % L;
    int proj = c4 >> 8;             // 0,1,2
    int c = (c4 & 255) * 4;         // channel within 1024
    const float* w = (proj == 0) ? cq : ((proj == 1) ? ck : cv);
    float* y = (proj == 0) ? q : ((proj == 1) ? k : v);

    float4 xv[4];
#pragma unroll
    for (int kk = 0; kk < 4; ++kk) {
        int ll = l - 3 + kk;
        xv[kk] = (ll >= 0) ? *(const float4*)&x3[((size_t)(b*L + ll))*3072 + c4*4]
                           : make_float4(0.f, 0.f, 0.f, 0.f);
    }
    float4 w0 = *(const float4*)&w[(c+0)*4];
    float4 w1 = *(const float4*)&w[(c+1)*4];
    float4 w2 = *(const float4*)&w[(c+2)*4];
    float4 w3 = *(const float4*)&w[(c+3)*4];
    float4 acc;
    acc.x = xv[0].x*w0.x + xv[1].x*w0.y + xv[2].x*w0.z + xv[3].x*w0.w;
    acc.y = xv[0].y*w1.x + xv[1].y*w1.y + xv[2].y*w1.z + xv[3].y*w1.w;
    acc.z = xv[0].z*w2.x + xv[1].z*w2.y + xv[2].z*w2.z + xv[3].z*w2.w;
    acc.w = xv[0].w*w3.x + xv[1].w*w3.y + xv[2].w*w3.z + xv[3].w*w3.w;
    acc.x = acc.x / (1.f + expf(-acc.x));
    acc.y = acc.y / (1.f + expf(-acc.y));
    acc.z = acc.z / (1.f + expf(-acc.z));
    acc.w = acc.w / (1.f + expf(-acc.w));
    *(float4*)&y[(size_t)t*HID + c] = acc;
}

// ---------------- fused FIR conv (short K=5 + long K=64), smem-tiled ------------
__global__ __launch_bounds__(256) void fir_kernel(
    const float* __restrict__ V, const float* __restrict__ fs,
    const float* __restrict__ fl, float* __restrict__ LS,
    float* __restrict__ LL, int L)
{
    __shared__ float xs[127*64];
    int ct = blockIdx.x;        // channel tile (0..15)
    int tt = blockIdx.y;        // time tile (0..T/64-1)
    int c0 = ct * 64;
    int t0 = tt * 64;
    int b = t0 / L;
    int l0 = t0 - b * L;
    int tid = threadIdx.x;

    for (int idx = tid; idx < 127*64; idx += 256) {
        int row = idx >> 6, c = idx & 63;
        int l = l0 - 63 + row;
        xs[idx] = (l >= 0) ? V[((size_t)(b*L + l))*HID + c0 + c] : 0.f;
    }

    int c = tid & 63;
    int tg = tid >> 6;          // 0..3
    int cg = c0 + c;
    float wl[64];
#pragma unroll
    for (int kk = 0; kk < 64; ++kk) wl[kk] = fl[cg*64 + kk];
    float ws[5];
#pragma unroll
    for (int kk = 0; kk < 5; ++kk) ws[kk] = fs[cg*5 + kk];
    __syncthreads();

    for (int j = 0; j < 16; ++j) {
        int jj = tg*16 + j;
        float accl = 0.f, accs = 0.f;
#pragma unroll
        for (int kk = 0; kk < 64; ++kk) accl += xs[(jj+kk)*64 + c] * wl[kk];
#pragma unroll
        for (int kk = 0; kk < 5; ++kk) accs += xs[(jj+59+kk)*64 + c] * ws[kk];
        size_t o = ((size_t)(t0 + jj))*HID + cg;
        LL[o] = accl;
        LS[o] = accs;
    }
}

// ---------------- beta ------------------------------------------------------------
__global__ void beta_kernel(const float* __restrict__ hs, const float* __restrict__ Wb,
                            float* __restrict__ beta, int T)
{
    int gw = (blockIdx.x * blockDim.x + threadIdx.x) >> 5;
    int lane = threadIdx.x & 31;
    if (gw >= T * NH) return;
    int t = gw / NH, h = gw % NH;
    float s = 0.f;
    for (int r = lane; r < HID; r += 32) s += hs[(size_t)t*HID + r] * Wb[r*NH + h];
#pragma unroll
    for (int off = 16; off; off >>= 1) s += __shfl_down_sync(0xffffffff, s, off);
    if (lane == 0) beta[t*NH + h] = 1.f / (1.f + expf(-s));
}

// ---------------- l2norm + kb -----------------------------------------------------
__global__ __launch_bounds__(256) void l2norm_kernel(
    float* __restrict__ Q, float* __restrict__ Kp, float* __restrict__ KB,
    const float* __restrict__ beta)
{
    int th = blockIdx.x;
    int t = th >> 2, h = th & 3;
    int d = threadIdx.x;
    int lane = d & 31, wid = d >> 5;
    size_t base = (size_t)t*HID + h*DK;
    float qv = Q[base + d], kv = Kp[base + d];
    float a = qv*qv, bb2 = kv*kv;
#pragma unroll
    for (int off = 16; off; off >>= 1) {
        a   += __shfl_down_sync(0xffffffff, a, off);
        bb2 += __shfl_down_sync(0xffffffff, bb2, off);
    }
    __shared__ float part[8][2];
    if (lane == 0) { part[wid][0] = a; part[wid][1] = bb2; }
    __syncthreads();
    float sq = 0.f, sk = 0.f;
#pragma unroll
    for (int wdx = 0; wdx < 8; ++wdx) { sq += part[wdx][0]; sk += part[wdx][1]; }
    float rq = rsqrtf(sq + 1e-6f);
    float rk = rsqrtf(sk + 1e-6f);
    float bb = beta[t*NH + h];
    Q[base + d]  = qv * rq;
    float kn = kv * rk;
    Kp[base + d] = kn;
    KB[base + d] = kn * bb;
}

// ---------------- per-chunk: attn inversion + u, w, attn_loc --------------------
__global__ __launch_bounds__(256) void chunk_kernel(
    const float* __restrict__ Qn, const float* __restrict__ Kn,
    const float* __restrict__ KB, const float* __restrict__ V,
    const float* __restrict__ beta, float* __restrict__ U,
    float* __restrict__ Wbuf, float* __restrict__ Aloc, int L)
{
    extern __shared__ float sm[];
    float* q_s  = sm;
    float* kn_s = q_s  + 32*QP;
    float* kb_s = kn_s + 32*QP;
    float* A    = kb_s + 32*QP;
    int nch = L / CHUNK;
    int cid = blockIdx.x;
    int ch = cid % nch;
    int h  = (cid / nch) & (NH - 1);
    int b  = cid / (nch * NH);
    int l0 = ch * CHUNK;
    int tid = threadIdx.x;
    int lane = tid & 31;
    int iw = tid >> 5;
    size_t base = ((size_t)(b*L + l0)) * HID + h*DK;

    for (int r = 0; r < 32; ++r) {
        size_t g = base + (size_t)r*HID + tid;
        q_s [r*QP + tid] = Qn[g];
        kn_s[r*QP + tid] = Kn[g];
        kb_s[r*QP + tid] = KB[g];
    }
    __syncthreads();

    size_t abase = (size_t)cid * (CHUNK*CHUNK);
#pragma unroll
    for (int r = 0; r < 4; ++r) {
        int i = r*8 + iw, j = lane;
        float sA = 0.f, sL = 0.f;
#pragma unroll 8
        for (int dq = 0; dq < 64; ++dq) {
            float4 kn = *(float4*)&kn_s[j*QP + dq*4];
            float4 kb = *(float4*)&kb_s[i*QP + dq*4];
            float4 qv = *(float4*)&q_s [i*QP + dq*4];
            sA += kb.x*kn.x + kb.y*kn.y + kb.z*kn.z + kb.w*kn.w;
            sL += qv.x*kn.x + qv.y*kn.y + qv.z*kn.z + qv.w*kn.w;
        }
        A[i*KTP + j] = (i > j) ? -sA : 0.f;
        Aloc[abase + i*32 + j] = (j <= i) ? sL : 0.f;
    }
    __syncthreads();

    if (tid < 32) {
        int j = tid;
        for (int i = 1; i < 32; ++i) {
            float s = 0.f;
            if (j < i) {
#pragma unroll
                for (int t2 = 0; t2 < 32; ++t2) s += A[i*KTP + t2] * A[t2*KTP + j];
            }
            __syncwarp();
            if (j < i) A[i*KTP + j] += s;
            __syncwarp();
        }
        A[j*KTP + j] += 1.f;
    }
    __syncthreads();

    for (int r = 0; r < 32; ++r) {
        float bb = beta[(b*L + l0 + r)*NH + h];
        q_s[r*QP + tid] = V[base + (size_t)r*HID + tid] * bb;
    }
    __syncthreads();

    float vc[32], kc[32];
#pragma unroll
    for (int t2 = 0; t2 < 32; ++t2) {
        vc[t2] = q_s [t2*QP + tid];
        kc[t2] = kb_s[t2*QP + tid];
    }

    for (int i = 0; i < 32; ++i) {
        float su = 0.f, sw = 0.f;
#pragma unroll
        for (int qq = 0; qq < 8; ++qq) {
            float4 a = *(float4*)&A[i*KTP + qq*4];
            su += a.x*vc[qq*4] + a.y*vc[qq*4+1] + a.z*vc[qq*4+2] + a.w*vc[qq*4+3];
            sw += a.x*kc[qq*4] + a.y*kc[qq*4+1] + a.z*kc[qq*4+2] + a.w*kc[qq*4+3];
        }
        U   [base + (size_t)i*HID + tid] = su;
        Wbuf[base + (size_t)i*HID + tid] = sw;
    }
}

// ---------------- sequential chunk scan: 128 CTAs, 16 cols each -----------------
__global__ __launch_bounds__(256) void scan_kernel(
    const float* __restrict__ Qn, const float* __restrict__ Kn,
    const float* __restrict__ U,  const float* __restrict__ Wbuf,
    const float* __restrict__ Aloc, float* __restrict__ Dout, int L)
{
    extern __shared__ float sm[];
    float* Ssm_t = sm;
    float* q_s   = Ssm_t + NC*QP;
    float* w_s   = q_s   + 32*QP;
    float* k_t   = w_s   + 32*QP;
    float* al    = k_t   + 256*KTP;
    float* ul_t  = al    + 32*KTP;

    int cb = blockIdx.x;
    int bh = blockIdx.y;
    int b = bh >> 2, h = bh & 3;
    int tid = threadIdx.x;
    int c  = tid & (NC - 1);
    int gi = tid >> 4;
    int nch = L / CHUNK;

    float Sreg[16];
#pragma unroll
    for (int r = 0; r < 16; ++r) Sreg[r] = 0.f;

    for (int ch = 0; ch < nch; ++ch) {
        int l0 = ch * CHUNK;
        size_t base = ((size_t)(b*L + l0)) * HID + h*DK;

#pragma unroll
        for (int r = 0; r < 16; ++r) Ssm_t[c*QP + r*16 + gi] = Sreg[r];
        for (int r = 0; r < 32; ++r) {
            size_t g = base + (size_t)r*HID + tid;
            q_s[r*QP + tid] = Qn[g];
            w_s[r*QP + tid] = Wbuf[g];
            k_t[tid*KTP + r] = Kn[g];
        }
        size_t abase = (size_t)((b*NH + h)*nch + ch) * 1024;
#pragma unroll
        for (int e0 = 0; e0 < 4; ++e0) {
            int e = e0*256 + tid;
            al[(e >> 5)*KTP + (e & 31)] = Aloc[abase + e];
        }

        float uacc[2], oacc[2] = {0.f, 0.f};
#pragma unroll
        for (int r2 = 0; r2 < 2; ++r2)
            uacc[r2] = U[((size_t)(b*L + l0 + (r2*16 + gi)))*HID + h*DV + cb*NC + c];
        __syncthreads();

#pragma unroll 4
        for (int dq = 0; dq < 64; ++dq) {
            float4 sv = *(float4*)&Ssm_t[c*QP + dq*4];
#pragma unroll
            for (int r2 = 0; r2 < 2; ++r2) {
                int i = r2*16 + gi;
                float4 wv = *(float4*)&w_s[i*QP + dq*4];
                float4 qv = *(float4*)&q_s[i*QP + dq*4];
                uacc[r2] -= wv.x*sv.x + wv.y*sv.y + wv.z*sv.z + wv.w*sv.w;
                oacc[r2] += qv.x*sv.x + qv.y*sv.y + qv.z*sv.z + qv.w*sv.w;
            }
        }
#pragma unroll
        for (int r2 = 0; r2 < 2; ++r2) ul_t[c*KTP + r2*16 + gi] = uacc[r2];
        __syncthreads();

        float ulreg[32];
#pragma unroll
        for (int qq = 0; qq < 8; ++qq) {
            float4 t4 = *(float4*)&ul_t[c*KTP + qq*4];
            ulreg[qq*4] = t4.x; ulreg[qq*4+1] = t4.y;
            ulreg[qq*4+2] = t4.z; ulreg[qq*4+3] = t4.w;
        }

#pragma unroll
        for (int qq = 0; qq < 8; ++qq) {
#pragma unroll
            for (int r2 = 0; r2 < 2; ++r2) {
                int i = r2*16 + gi;
                float4 av = *(float4*)&al[i*KTP + qq*4];
                oacc[r2] += av.x*ulreg[qq*4] + av.y*ulreg[qq*4+1]
                          + av.z*ulreg[qq*4+2] + av.w*ulreg[qq*4+3];
            }
        }
#pragma unroll
        for (int r2 = 0; r2 < 2; ++r2)
            Dout[((size_t)(b*L + l0 + (r2*16 + gi)))*HID + h*DV + cb*NC + c] = oacc[r2];

#pragma unroll
        for (int qq = 0; qq < 8; ++qq) {
#pragma unroll
            for (int r = 0; r < 16; ++r) {
                float4 kv = *(float4*)&k_t[(r*16 + gi)*KTP + qq*4];
                Sreg[r] += kv.x*ulreg[qq*4] + kv.y*ulreg[qq*4+1]
                         + kv.z*ulreg[qq*4+2] + kv.w*ulreg[qq*4+3];
            }
        }
        __syncthreads();
    }
}

// ---------------- stats (warp-shuffle) -------------------------------------------
__global__ __launch_bounds__(256) void stats_kernel(
    const float* __restrict__ LS, const float* __restrict__ LL,
    const float* __restrict__ DEL, const float* __restrict__ V,
    float* __restrict__ ST)
{
    int th = blockIdx.x;
    int d = threadIdx.x;
    int lane = d & 31, wid = d >> 5;
    size_t base = (size_t)th*256 + d;
    __shared__ float part[4][8][3];
    const float* ptrs[4] = {LS, LL, DEL, V};
#pragma unroll
    for (int sig = 0; sig < 4; ++sig) {
        float x = ptrs[sig][base];
        float a = x, bq = x*x, cc = fabsf(x);
#pragma unroll
        for (int off = 16; off; off >>= 1) {
            a  += __shfl_down_sync(0xffffffff, a, off);
            bq += __shfl_down_sync(0xffffffff, bq, off);
            cc += __shfl_down_sync(0xffffffff, cc, off);
        }
        if (lane == 0) { part[sig][wid][0] = a; part[sig][wid][1] = bq; part[sig][wid][2] = cc; }
    }
    __syncthreads();
    if (d < 4) {
        float s1 = 0.f, s2 = 0.f, s3 = 0.f;
#pragma unroll
        for (int wdx = 0; wdx < 8; ++wdx) {
            s1 += part[d][wdx][0]; s2 += part[d][wdx][1]; s3 += part[d][wdx][2];
        }
        float mean = s1 / 256.f;
        float var  = s2 / 256.f - mean*mean;
        float am   = s3 / 256.f;
        float l2   = sqrtf(s2);
        float* o = ST + (size_t)th*16 + d*4;
        o[0] = mean; o[1] = var; o[2] = am; o[3] = l2;
    }
}

// ---------------- gate MLP tail + softmax + floor -------------------------------
__global__ __launch_bounds__(256) void gate_kernel(
    const float* __restrict__ G1, const float* __restrict__ ST,
    const float* __restrict__ w1, const float* __restrict__ b1,
    const float* __restrict__ w2, const float* __restrict__ b2,
    const float* __restrict__ lt, float* __restrict__ P)
{
    int th = blockIdx.x;
    int t = th >> 2, h = th & 3;
    int tid = threadIdx.x;
    __shared__ float st[16];
    if (tid < 16) st[tid] = ST[(size_t)th*16 + tid];
    __syncthreads();
    float p0 = 0.f, p1 = 0.f, p2 = 0.f, p3 = 0.f;
    for (int j = tid; j < 1024; j += 256) {
        float x = G1[(size_t)t*1024 + j] + b1[j];
#pragma unroll
        for (int s = 0; s < 16; ++s) x += st[s] * w1[(size_t)(1024 + s)*1024 + j];
        float g = 0.5f * x * (1.f + erff(x * 0.70710678118654752f));
        p0 += g * w2[j*4 + 0]; p1 += g * w2[j*4 + 1];
        p2 += g * w2[j*4 + 2]; p3 += g * w2[j*4 + 3];
    }
    int lane = tid & 31, wid = tid >> 5;
#pragma unroll
    for (int off = 16; off; off >>= 1) {
        p0 += __shfl_down_sync(0xffffffff, p0, off);
        p1 += __shfl_down_sync(0xffffffff, p1, off);
        p2 += __shfl_down_sync(0xffffffff, p2, off);
        p3 += __shfl_down_sync(0xffffffff, p3, off);
    }
    __shared__ float part[8][4];
    if (lane == 0) { part[wid][0]=p0; part[wid][1]=p1; part[wid][2]=p2; part[wid][3]=p3; }
    __syncthreads();
    if (tid == 0) {
        float l[4] = {0.f, 0.f, 0.f, 0.f};
#pragma unroll
        for (int wdx = 0; wdx < 8; ++wdx) {
            l[0] += part[wdx][0]; l[1] += part[wdx][1];
            l[2] += part[wdx][2]; l[3] += part[wdx][3];
        }
        float inv_t = expf(-lt[h]);
#pragma unroll
        for (int cc = 0; cc < 4; ++cc) l[cc] = (l[cc] + b2[cc]) * inv_t;
        float m = fmaxf(fmaxf(l[0], l[1]), fmaxf(l[2], l[3]));
        float e[4], ssum = 0.f;
#pragma unroll
        for (int cc = 0; cc < 4; ++cc) { e[cc] = expf(l[cc] - m); ssum += e[cc]; }
#pragma unroll
        for (int cc = 0; cc < 4; ++cc)
            P[(size_t)th*4 + cc] = 0.05f + 0.8f * (e[cc] / ssum);
    }
}

// ---------------- mix + RMSNorm (warp-shuffle) -----------------------------------
__global__ __launch_bounds__(256) void mix_kernel(
    const float* __restrict__ LS, const float* __restrict__ LL,
    const float* __restrict__ DEL, const float* __restrict__ V,
    const float* __restrict__ P, const float* __restrict__ onw,
    float* __restrict__ OM)
{
    int th = blockIdx.x;
    int d = threadIdx.x;
    int lane = d & 31, wid = d >> 5;
    size_t base = (size_t)th*256 + d;
    float p0 = P[th*4], p1 = P[th*4+1], p2 = P[th*4+2], p3 = P[th*4+3];
    float o = p0*LS[base] + p1*LL[base] + p2*DEL[base] + p3*V[base];
    float sq = o*o;
#pragma unroll
    for (int off = 16; off; off >>= 1) sq += __shfl_down_sync(0xffffffff, sq, off);
    __shared__ float part[8];
    if (lane == 0) part[wid] = sq;
    __syncthreads();
    float ssum = 0.f;
#pragma unroll
    for (int wdx = 0; wdx < 8; ++wdx) ssum += part[wdx];
    float ms = ssum / 256.f;
    OM[base] = o * rsqrtf(ms + 1e-5f) * onw[d];
}

// ---------------- launch ----------------------------------------------------------
extern "C" void kernel_launch(void* const* d_in, const int* in_sizes, int n_in,
                              void* d_out, int out_size)
{
    const float* hs = (const float*)d_in[0];
    const float* Wq = (const float*)d_in[1];
    const float* Wk = (const float*)d_in[2];
    const float* Wv = (const float*)d_in[3];
    const float* Wb = (const float*)d_in[4];
    const float* cq = (const float*)d_in[5];
    const float* ck = (const float*)d_in[6];
    const float* cv = (const float*)d_in[7];
    const float* fs = (const float*)d_in[8];
    const float* fl = (const float*)d_in[9];
    const float* w1 = (const float*)d_in[10];
    const float* b1 = (const float*)d_in[11];
    const float* w2 = (const float*)d_in[12];
    const float* b2 = (const float*)d_in[13];
    const float* lt = (const float*)d_in[14];
    const float* onw= (const float*)d_in[15];
    const float* Wo = (const float*)d_in[16];

    const int T = in_sizes[0] / HID;
    const int B = 2;
    const int L = T / B;

    float *tmp3, *q, *k, *v, *kb, *u, *w, *del, *ls, *ll, *g1, *om, *aloc, *beta, *st, *pr;
    __nv_bfloat16 *a2, *bth, *btl;
    cudaGetSymbolAddress((void**)&tmp3, g_tmp3);
    cudaGetSymbolAddress((void**)&q,    g_q);
    cudaGetSymbolAddress((void**)&k,    g_k);
    cudaGetSymbolAddress((void**)&v,    g_v);
    cudaGetSymbolAddress((void**)&kb,   g_kb);
    cudaGetSymbolAddress((void**)&u,    g_u);
    cudaGetSymbolAddress((void**)&w,    g_w);
    cudaGetSymbolAddress((void**)&del,  g_del);
    cudaGetSymbolAddress((void**)&ls,   g_ls);
    cudaGetSymbolAddress((void**)&ll,   g_ll);
    cudaGetSymbolAddress((void**)&g1,   g_g1);
    cudaGetSymbolAddress((void**)&om,   g_om);
    cudaGetSymbolAddress((void**)&aloc, g_aloc);
    cudaGetSymbolAddress((void**)&beta, g_beta);
    cudaGetSymbolAddress((void**)&st,   g_stats);
    cudaGetSymbolAddress((void**)&pr,   g_probs);
    cudaGetSymbolAddress((void**)&a2,   g_a2);
    cudaGetSymbolAddress((void**)&bth,  g_bth);
    cudaGetSymbolAddress((void**)&btl,  g_btl);

    dim3 bt_grid(HID/32, HID/32);
    dim3 bt_blk(32, 8);
    int nsplit = (T*HID + 255) / 256;

    const int GEMM_SMEM = 2 * GSTAGE;
    cudaFuncSetAttribute(gemm_mma, cudaFuncAttributeMaxDynamicSharedMemorySize, GEMM_SMEM);

    size_t chunk_smem = (size_t)(3*32*QP + 32*KTP) * 4;
    size_t scan_smem  = (size_t)(NC*QP + 2*32*QP + 256*KTP + 32*KTP + NC*KTP) * 4;
    cudaFuncSetAttribute(chunk_kernel, cudaFuncAttributeMaxDynamicSharedMemorySize, (int)chunk_smem);
    cudaFuncSetAttribute(scan_kernel,  cudaFuncAttributeMaxDynamicSharedMemorySize, (int)scan_smem);

    asplit_kernel<<<nsplit, 256>>>(hs, a2, HID, T*HID);

    bsplit_kernel<<<bt_grid, bt_blk>>>(Wq, bth,             btl,             HID, HID);
    bsplit_kernel<<<bt_grid, bt_blk>>>(Wk, bth + HID*HID,   btl + HID*HID,   HID, HID);
    bsplit_kernel<<<bt_grid, bt_blk>>>(Wv, bth + 2*HID*HID, btl + 2*HID*HID, HID, HID);
    {
        dim3 gg(3*HID/BN, T/BM);
        gemm_mma<<<gg, 256, GEMM_SMEM>>>(a2, bth, btl, tmp3, T, 3*HID, HID);
    }
    conv_qkv_kernel<<<(T*768 + 255)/256, 256>>>(tmp3, cq, ck, cv, q, k, v, L, T*768);

    beta_kernel<<<(T*NH + 7) / 8, 256>>>(hs, Wb, beta, T);
    l2norm_kernel<<<T*NH, 256>>>(q, k, kb, beta);

    chunk_kernel<<<B*NH*(L/CHUNK), 256, chunk_smem>>>(q, k, kb, v, beta, u, w, aloc, L);
    scan_kernel<<<dim3(DV/NC, B*NH), 256, scan_smem>>>(q, k, u, w, aloc, del, L);

    // fused FIR (short + long)
    fir_kernel<<<dim3(HID/64, T/64), 256>>>(v, fs, fl, ls, ll, L);

    stats_kernel<<<T*NH, 256>>>(ls, ll, del, v, st);

    bsplit_kernel<<<bt_grid, bt_blk>>>(w1, bth, btl, HID, HID);
    {
        dim3 gg(HID/BN, T/BM);
        gemm_mma<<<gg, 256, GEMM_SMEM>>>(a2, bth, btl, g1, T, HID, HID);
    }
    gate_kernel<<<T*NH, 256>>>(g1, st, w1, b1, w2, b2, lt, pr);

    mix_kernel<<<T*NH, 256>>>(ls, ll, del, v, pr, onw, om);

    asplit_kernel<<<nsplit, 256>>>(om, a2, HID, T*HID);
    bsplit_kernel<<<bt_grid, bt_blk>>>(Wo, bth, btl, HID, HID);
    {
        dim3 gg(HID/BN, T/BM);
        gemm_mma<<<gg, 256, GEMM_SMEM>>>(a2, bth, btl, (float*)d_out, T, HID, HID);
    }
}

// round 9
// speedup vs baseline: 2.9356x; 1.0351x over previous
#include <cuda_runtime.h>
#include <cuda_bf16.h>
#include <math.h>
#include <stdint.h>

#define HID 1024
#define NH 4
#define DK 256
#define DV 256
#define CHUNK 32
#define TMAX 8192
#define QP 260
#define KTP 36
#define NC 16

// ---------------- scratch ----------------
__device__ float g_tmp3 [TMAX*3*HID];
__device__ float g_q    [TMAX*HID];
__device__ float g_k    [TMAX*HID];
__device__ float g_v    [TMAX*HID];
__device__ float g_kb   [TMAX*HID];
__device__ float g_u    [TMAX*HID];
__device__ float g_w    [TMAX*HID];
__device__ float g_del  [TMAX*HID];
__device__ float g_ls   [TMAX*HID];
__device__ float g_ll   [TMAX*HID];
__device__ float g_g1   [TMAX*HID];
__device__ float g_aloc [TMAX*NH*CHUNK];
__device__ float g_beta [TMAX*NH];
__device__ float g_stats[TMAX*NH*16];
__device__ float g_probs[TMAX*NH*4];
__device__ __nv_bfloat16 g_a2 [TMAX*2*HID];   // split hs, later split om
__device__ __nv_bfloat16 g_bth[3*HID*HID];
__device__ __nv_bfloat16 g_btl[3*HID*HID];
__device__ __nv_bfloat16 g_bthg[HID*HID];     // gate/out weights (side stream)
__device__ __nv_bfloat16 g_btlg[HID*HID];
__device__ __nv_bfloat16 g_btho[HID*HID];
__device__ __nv_bfloat16 g_btlo[HID*HID];

__device__ __forceinline__ uint32_t smem_u32(const void* p) {
    uint32_t a;
    asm("{ .reg .u64 t; cvta.to.shared.u64 t, %1; cvt.u32.u64 %0, t; }" : "=r"(a) : "l"(p));
    return a;
}
__device__ __forceinline__ void cp16(uint32_t dst, const void* src) {
    asm volatile("cp.async.cg.shared.global [%0], [%1], 16;" :: "r"(dst), "l"(src));
}

// ---------------- precision-split prep ----------------
__global__ void asplit_kernel(const float* __restrict__ X,
                              __nv_bfloat16* __restrict__ A2, int K, int total) {
    int idx = blockIdx.x * blockDim.x + threadIdx.x;
    if (idx >= total) return;
    int m = idx / K, kk = idx - m * K;
    float v = X[idx];
    __nv_bfloat16 hi = __float2bfloat16(v);
    float r = v - __bfloat162float(hi);
    A2[(size_t)m * 2 * K + kk]     = hi;
    A2[(size_t)m * 2 * K + K + kk] = __float2bfloat16(r);
}

__global__ void bsplit_kernel(const float* __restrict__ W,
                              __nv_bfloat16* __restrict__ Bh,
                              __nv_bfloat16* __restrict__ Bl, int K, int N) {
    __shared__ float t[32][33];
    int bn = blockIdx.x * 32, bk = blockIdx.y * 32;
    int x = threadIdx.x, y = threadIdx.y;
    for (int i = y; i < 32; i += 8) t[i][x] = W[(size_t)(bk + i) * N + bn + x];
    __syncthreads();
    for (int i = y; i < 32; i += 8) {
        float v = t[x][i];
        __nv_bfloat16 hi = __float2bfloat16(v);
        float r = v - __bfloat162float(hi);
        Bh[(size_t)(bn + i) * K + bk + x] = hi;
        Bl[(size_t)(bn + i) * K + bk + x] = __float2bfloat16(r);
    }
}

// ---------------- bf16 mma.sync GEMM (3-term split), BK=64 ----------------------
#define BM 128
#define BN 128
#define BK 64
#define APITCH 72
#define ASTAGE (BM * APITCH * 2)
#define GSTAGE (2 * ASTAGE)

__global__ __launch_bounds__(256) void gemm_mma(
    const __nv_bfloat16* __restrict__ A2, const __nv_bfloat16* __restrict__ Bh,
    const __nv_bfloat16* __restrict__ Bl, float* __restrict__ C,
    int M, int N, int K)
{
    extern __shared__ __align__(16) char gsm[];
    uint32_t sb = smem_u32(gsm);

    const int tid = threadIdx.x;
    const int wid = tid >> 5, lane = tid & 31;
    const int m0 = blockIdx.y * BM, n0 = blockIdx.x * BN;
    const int wm = (wid >> 2) * 64, wn = (wid & 3) * 32;

    const int KBn = K / BK;
    const int NB = 3 * KBn;
    const size_t sA = (size_t)2 * K;

    auto load_stage = [&](int kb, int buf) {
        int seg = kb / KBn;
        int kk = (kb - seg * KBn) * BK;
        const __nv_bfloat16* Ap = A2 + (seg == 1 ? (size_t)K : 0) + kk;
        const __nv_bfloat16* Bp = ((seg == 2) ? Bl : Bh) + kk;
        uint32_t a_s = sb + (uint32_t)buf * GSTAGE;
        uint32_t b_s = a_s + ASTAGE;
#pragma unroll
        for (int i = 0; i < 4; ++i) {
            int idx = i * 256 + tid;
            int row = idx >> 3, ch = idx & 7;
            cp16(a_s + (uint32_t)(row * APITCH + ch * 8) * 2,
                 Ap + (size_t)(m0 + row) * sA + ch * 8);
            cp16(b_s + (uint32_t)(row * APITCH + ch * 8) * 2,
                 Bp + (size_t)(n0 + row) * K + ch * 8);
        }
    };

    float acc[4][4][4];
#pragma unroll
    for (int mt = 0; mt < 4; ++mt)
#pragma unroll
        for (int nt = 0; nt < 4; ++nt)
#pragma unroll
            for (int e = 0; e < 4; ++e) acc[mt][nt][e] = 0.f;

    load_stage(0, 0);
    asm volatile("cp.async.commit_group;" ::: "memory");

    for (int kb = 0; kb < NB; ++kb) {
        int buf = kb & 1;
        if (kb + 1 < NB) load_stage(kb + 1, buf ^ 1);
        asm volatile("cp.async.commit_group;" ::: "memory");
        asm volatile("cp.async.wait_group 1;" ::: "memory");
        __syncthreads();

        uint32_t a_s = sb + (uint32_t)buf * GSTAGE;
        uint32_t b_s = a_s + ASTAGE;
#pragma unroll
        for (int kp = 0; kp < 4; ++kp) {
            uint32_t a[4][4], b[4][2];
            {
                int r_off = lane & 15;
                int c_off = kp * 16 + (lane >> 4) * 8;
#pragma unroll
                for (int mt = 0; mt < 4; ++mt) {
                    uint32_t addr = a_s + (uint32_t)((wm + mt * 16 + r_off) * APITCH + c_off) * 2;
                    asm volatile("ldmatrix.sync.aligned.m8n8.x4.shared.b16 {%0,%1,%2,%3}, [%4];"
                        : "=r"(a[mt][0]), "=r"(a[mt][1]), "=r"(a[mt][2]), "=r"(a[mt][3])
                        : "r"(addr));
                }
            }
            {
                int n_off = (lane & 7) + (lane >> 4) * 8;
                int c_off = kp * 16 + ((lane >> 3) & 1) * 8;
#pragma unroll
                for (int nb = 0; nb < 2; ++nb) {
                    uint32_t r0, r1, r2, r3;
                    uint32_t addr = b_s + (uint32_t)((wn + nb * 16 + n_off) * APITCH + c_off) * 2;
                    asm volatile("ldmatrix.sync.aligned.m8n8.x4.shared.b16 {%0,%1,%2,%3}, [%4];"
                        : "=r"(r0), "=r"(r1), "=r"(r2), "=r"(r3) : "r"(addr));
                    b[nb * 2][0] = r0;     b[nb * 2][1] = r1;
                    b[nb * 2 + 1][0] = r2; b[nb * 2 + 1][1] = r3;
                }
            }
#pragma unroll
            for (int mt = 0; mt < 4; ++mt)
#pragma unroll
                for (int nt = 0; nt < 4; ++nt) {
                    asm volatile(
                        "mma.sync.aligned.m16n8k16.row.col.f32.bf16.bf16.f32 "
                        "{%0,%1,%2,%3}, {%4,%5,%6,%7}, {%8,%9}, {%0,%1,%2,%3};"
                        : "+f"(acc[mt][nt][0]), "+f"(acc[mt][nt][1]),
                          "+f"(acc[mt][nt][2]), "+f"(acc[mt][nt][3])
                        : "r"(a[mt][0]), "r"(a[mt][1]), "r"(a[mt][2]), "r"(a[mt][3]),
                          "r"(b[nt][0]), "r"(b[nt][1]));
                }
        }
        __syncthreads();
    }

    int g = lane >> 2, tg = lane & 3;
#pragma unroll
    for (int mt = 0; mt < 4; ++mt) {
#pragma unroll
        for (int nt = 0; nt < 4; ++nt) {
            int row = m0 + wm + mt * 16 + g;
            int col = n0 + wn + nt * 8 + tg * 2;
            *(float2*)(C + (size_t)row * N + col) =
                make_float2(acc[mt][nt][0], acc[mt][nt][1]);
            *(float2*)(C + (size_t)(row + 8) * N + col) =
                make_float2(acc[mt][nt][2], acc[mt][nt][3]);
        }
    }
}

// ---------------- fused QKV causal conv + SiLU (float4) -------------------------
__global__ void conv_qkv_kernel(const float* __restrict__ x3,
                                const float* __restrict__ cq, const float* __restrict__ ck,
                                const float* __restrict__ cv,
                                float* __restrict__ q, float* __restrict__ k,
                                float* __restrict__ v, int L, int total4)
{
    int idx = blockIdx.x * blockDim.x + threadIdx.x;
    if (idx >= total4) return;
    int c4 = idx % 768;
    int t = idx / 768;
    int b = t / L, l = t % L;
    int proj = c4 >> 8;
    int c = (c4 & 255) * 4;
    const float* w = (proj == 0) ? cq : ((proj == 1) ? ck : cv);
    float* y = (proj == 0) ? q : ((proj == 1) ? k : v);

    float4 xv[4];
#pragma unroll
    for (int kk = 0; kk < 4; ++kk) {
        int ll = l - 3 + kk;
        xv[kk] = (ll >= 0) ? *(const float4*)&x3[((size_t)(b*L + ll))*3072 + c4*4]
                           : make_float4(0.f, 0.f, 0.f, 0.f);
    }
    float4 w0 = *(const float4*)&w[(c+0)*4];
    float4 w1 = *(const float4*)&w[(c+1)*4];
    float4 w2 = *(const float4*)&w[(c+2)*4];
    float4 w3 = *(const float4*)&w[(c+3)*4];
    float4 acc;
    acc.x = xv[0].x*w0.x + xv[1].x*w0.y + xv[2].x*w0.z + xv[3].x*w0.w;
    acc.y = xv[0].y*w1.x + xv[1].y*w1.y + xv[2].y*w1.z + xv[3].y*w1.w;
    acc.z = xv[0].z*w2.x + xv[1].z*w2.y + xv[2].z*w2.z + xv[3].z*w2.w;
    acc.w = xv[0].w*w3.x + xv[1].w*w3.y + xv[2].w*w3.z + xv[3].w*w3.w;
    acc.x = acc.x / (1.f + expf(-acc.x));
    acc.y = acc.y / (1.f + expf(-acc.y));
    acc.z = acc.z / (1.f + expf(-acc.z));
    acc.w = acc.w / (1.f + expf(-acc.w));
    *(float4*)&y[(size_t)t*HID + c] = acc;
}

// ---------------- fused FIR conv (short K=5 + long K=64), smem-tiled ------------
__global__ __launch_bounds__(256) void fir_kernel(
    const float* __restrict__ V, const float* __restrict__ fs,
    const float* __restrict__ fl, float* __restrict__ LS,
    float* __restrict__ LL, int L)
{
    __shared__ float xs[127*64];
    int ct = blockIdx.x;
    int tt = blockIdx.y;
    int c0 = ct * 64;
    int t0 = tt * 64;
    int b = t0 / L;
    int l0 = t0 - b * L;
    int tid = threadIdx.x;

    for (int idx = tid; idx < 127*64; idx += 256) {
        int row = idx >> 6, c = idx & 63;
        int l = l0 - 63 + row;
        xs[idx] = (l >= 0) ? V[((size_t)(b*L + l))*HID + c0 + c] : 0.f;
    }

    int c = tid & 63;
    int tg = tid >> 6;
    int cg = c0 + c;
    float wl[64];
#pragma unroll
    for (int kk = 0; kk < 64; ++kk) wl[kk] = fl[cg*64 + kk];
    float ws[5];
#pragma unroll
    for (int kk = 0; kk < 5; ++kk) ws[kk] = fs[cg*5 + kk];
    __syncthreads();

    for (int j = 0; j < 16; ++j) {
        int jj = tg*16 + j;
        float accl = 0.f, accs = 0.f;
#pragma unroll
        for (int kk = 0; kk < 64; ++kk) accl += xs[(jj+kk)*64 + c] * wl[kk];
#pragma unroll
        for (int kk = 0; kk < 5; ++kk) accs += xs[(jj+59+kk)*64 + c] * ws[kk];
        size_t o = ((size_t)(t0 + jj))*HID + cg;
        LL[o] = accl;
        LS[o] = accs;
    }
}

// ---------------- beta ------------------------------------------------------------
__global__ void beta_kernel(const float* __restrict__ hs, const float* __restrict__ Wb,
                            float* __restrict__ beta, int T)
{
    int gw = (blockIdx.x * blockDim.x + threadIdx.x) >> 5;
    int lane = threadIdx.x & 31;
    if (gw >= T * NH) return;
    int t = gw / NH, h = gw % NH;
    float s = 0.f;
    for (int r = lane; r < HID; r += 32) s += hs[(size_t)t*HID + r] * Wb[r*NH + h];
#pragma unroll
    for (int off = 16; off; off >>= 1) s += __shfl_down_sync(0xffffffff, s, off);
    if (lane == 0) beta[t*NH + h] = 1.f / (1.f + expf(-s));
}

// ---------------- l2norm + kb -----------------------------------------------------
__global__ __launch_bounds__(256) void l2norm_kernel(
    float* __restrict__ Q, float* __restrict__ Kp, float* __restrict__ KB,
    const float* __restrict__ beta)
{
    int th = blockIdx.x;
    int t = th >> 2, h = th & 3;
    int d = threadIdx.x;
    int lane = d & 31, wid = d >> 5;
    size_t base = (size_t)t*HID + h*DK;
    float qv = Q[base + d], kv = Kp[base + d];
    float a = qv*qv, bb2 = kv*kv;
#pragma unroll
    for (int off = 16; off; off >>= 1) {
        a   += __shfl_down_sync(0xffffffff, a, off);
        bb2 += __shfl_down_sync(0xffffffff, bb2, off);
    }
    __shared__ float part[8][2];
    if (lane == 0) { part[wid][0] = a; part[wid][1] = bb2; }
    __syncthreads();
    float sq = 0.f, sk = 0.f;
#pragma unroll
    for (int wdx = 0; wdx < 8; ++wdx) { sq += part[wdx][0]; sk += part[wdx][1]; }
    float rq = rsqrtf(sq + 1e-6f);
    float rk = rsqrtf(sk + 1e-6f);
    float bb = beta[t*NH + h];
    Q[base + d]  = qv * rq;
    float kn = kv * rk;
    Kp[base + d] = kn;
    KB[base + d] = kn * bb;
}

// ---------------- per-chunk: attn inversion + u, w, attn_loc --------------------
__global__ __launch_bounds__(256) void chunk_kernel(
    const float* __restrict__ Qn, const float* __restrict__ Kn,
    const float* __restrict__ KB, const float* __restrict__ V,
    const float* __restrict__ beta, float* __restrict__ U,
    float* __restrict__ Wbuf, float* __restrict__ Aloc, int L)
{
    extern __shared__ float sm[];
    float* q_s  = sm;
    float* kn_s = q_s  + 32*QP;
    float* kb_s = kn_s + 32*QP;
    float* A    = kb_s + 32*QP;
    int nch = L / CHUNK;
    int cid = blockIdx.x;
    int ch = cid % nch;
    int h  = (cid / nch) & (NH - 1);
    int b  = cid / (nch * NH);
    int l0 = ch * CHUNK;
    int tid = threadIdx.x;
    int lane = tid & 31;
    int iw = tid >> 5;
    size_t base = ((size_t)(b*L + l0)) * HID + h*DK;

    for (int r = 0; r < 32; ++r) {
        size_t g = base + (size_t)r*HID + tid;
        q_s [r*QP + tid] = Qn[g];
        kn_s[r*QP + tid] = Kn[g];
        kb_s[r*QP + tid] = KB[g];
    }
    __syncthreads();

    size_t abase = (size_t)cid * (CHUNK*CHUNK);
#pragma unroll
    for (int r = 0; r < 4; ++r) {
        int i = r*8 + iw, j = lane;
        float sA = 0.f, sL = 0.f;
#pragma unroll 8
        for (int dq = 0; dq < 64; ++dq) {
            float4 kn = *(float4*)&kn_s[j*QP + dq*4];
            float4 kb = *(float4*)&kb_s[i*QP + dq*4];
            float4 qv = *(float4*)&q_s [i*QP + dq*4];
            sA += kb.x*kn.x + kb.y*kn.y + kb.z*kn.z + kb.w*kn.w;
            sL += qv.x*kn.x + qv.y*kn.y + qv.z*kn.z + qv.w*kn.w;
        }
        A[i*KTP + j] = (i > j) ? -sA : 0.f;
        Aloc[abase + i*32 + j] = (j <= i) ? sL : 0.f;
    }
    __syncthreads();

    if (tid < 32) {
        int j = tid;
        for (int i = 1; i < 32; ++i) {
            float s = 0.f;
            if (j < i) {
#pragma unroll
                for (int t2 = 0; t2 < 32; ++t2) s += A[i*KTP + t2] * A[t2*KTP + j];
            }
            __syncwarp();
            if (j < i) A[i*KTP + j] += s;
            __syncwarp();
        }
        A[j*KTP + j] += 1.f;
    }
    __syncthreads();

    for (int r = 0; r < 32; ++r) {
        float bb = beta[(b*L + l0 + r)*NH + h];
        q_s[r*QP + tid] = V[base + (size_t)r*HID + tid] * bb;
    }
    __syncthreads();

    float vc[32], kc[32];
#pragma unroll
    for (int t2 = 0; t2 < 32; ++t2) {
        vc[t2] = q_s [t2*QP + tid];
        kc[t2] = kb_s[t2*QP + tid];
    }

    for (int i = 0; i < 32; ++i) {
        float su = 0.f, sw = 0.f;
#pragma unroll
        for (int qq = 0; qq < 8; ++qq) {
            float4 a = *(float4*)&A[i*KTP + qq*4];
            su += a.x*vc[qq*4] + a.y*vc[qq*4+1] + a.z*vc[qq*4+2] + a.w*vc[qq*4+3];
            sw += a.x*kc[qq*4] + a.y*kc[qq*4+1] + a.z*kc[qq*4+2] + a.w*kc[qq*4+3];
        }
        U   [base + (size_t)i*HID + tid] = su;
        Wbuf[base + (size_t)i*HID + tid] = sw;
    }
}

// ---------------- sequential chunk scan: 128 CTAs, 16 cols each -----------------
__global__ __launch_bounds__(256) void scan_kernel(
    const float* __restrict__ Qn, const float* __restrict__ Kn,
    const float* __restrict__ U,  const float* __restrict__ Wbuf,
    const float* __restrict__ Aloc, float* __restrict__ Dout, int L)
{
    extern __shared__ float sm[];
    float* Ssm_t = sm;
    float* q_s   = Ssm_t + NC*QP;
    float* w_s   = q_s   + 32*QP;
    float* k_t   = w_s   + 32*QP;
    float* al    = k_t   + 256*KTP;
    float* ul_t  = al    + 32*KTP;

    int cb = blockIdx.x;
    int bh = blockIdx.y;
    int b = bh >> 2, h = bh & 3;
    int tid = threadIdx.x;
    int c  = tid & (NC - 1);
    int gi = tid >> 4;
    int nch = L / CHUNK;

    float Sreg[16];
#pragma unroll
    for (int r = 0; r < 16; ++r) Sreg[r] = 0.f;

    for (int ch = 0; ch < nch; ++ch) {
        int l0 = ch * CHUNK;
        size_t base = ((size_t)(b*L + l0)) * HID + h*DK;

#pragma unroll
        for (int r = 0; r < 16; ++r) Ssm_t[c*QP + r*16 + gi] = Sreg[r];
        for (int r = 0; r < 32; ++r) {
            size_t g = base + (size_t)r*HID + tid;
            q_s[r*QP + tid] = Qn[g];
            w_s[r*QP + tid] = Wbuf[g];
            k_t[tid*KTP + r] = Kn[g];
        }
        size_t abase = (size_t)((b*NH + h)*nch + ch) * 1024;
#pragma unroll
        for (int e0 = 0; e0 < 4; ++e0) {
            int e = e0*256 + tid;
            al[(e >> 5)*KTP + (e & 31)] = Aloc[abase + e];
        }

        float uacc[2], oacc[2] = {0.f, 0.f};
#pragma unroll
        for (int r2 = 0; r2 < 2; ++r2)
            uacc[r2] = U[((size_t)(b*L + l0 + (r2*16 + gi)))*HID + h*DV + cb*NC + c];
        __syncthreads();

#pragma unroll 4
        for (int dq = 0; dq < 64; ++dq) {
            float4 sv = *(float4*)&Ssm_t[c*QP + dq*4];
#pragma unroll
            for (int r2 = 0; r2 < 2; ++r2) {
                int i = r2*16 + gi;
                float4 wv = *(float4*)&w_s[i*QP + dq*4];
                float4 qv = *(float4*)&q_s[i*QP + dq*4];
                uacc[r2] -= wv.x*sv.x + wv.y*sv.y + wv.z*sv.z + wv.w*sv.w;
                oacc[r2] += qv.x*sv.x + qv.y*sv.y + qv.z*sv.z + qv.w*sv.w;
            }
        }
#pragma unroll
        for (int r2 = 0; r2 < 2; ++r2) ul_t[c*KTP + r2*16 + gi] = uacc[r2];
        __syncthreads();

        float ulreg[32];
#pragma unroll
        for (int qq = 0; qq < 8; ++qq) {
            float4 t4 = *(float4*)&ul_t[c*KTP + qq*4];
            ulreg[qq*4] = t4.x; ulreg[qq*4+1] = t4.y;
            ulreg[qq*4+2] = t4.z; ulreg[qq*4+3] = t4.w;
        }

#pragma unroll
        for (int qq = 0; qq < 8; ++qq) {
#pragma unroll
            for (int r2 = 0; r2 < 2; ++r2) {
                int i = r2*16 + gi;
                float4 av = *(float4*)&al[i*KTP + qq*4];
                oacc[r2] += av.x*ulreg[qq*4] + av.y*ulreg[qq*4+1]
                          + av.z*ulreg[qq*4+2] + av.w*ulreg[qq*4+3];
            }
        }
#pragma unroll
        for (int r2 = 0; r2 < 2; ++r2)
            Dout[((size_t)(b*L + l0 + (r2*16 + gi)))*HID + h*DV + cb*NC + c] = oacc[r2];

#pragma unroll
        for (int qq = 0; qq < 8; ++qq) {
#pragma unroll
            for (int r = 0; r < 16; ++r) {
                float4 kv = *(float4*)&k_t[(r*16 + gi)*KTP + qq*4];
                Sreg[r] += kv.x*ulreg[qq*4] + kv.y*ulreg[qq*4+1]
                         + kv.z*ulreg[qq*4+2] + kv.w*ulreg[qq*4+3];
            }
        }
        __syncthreads();
    }
}

// ---------------- stats (warp-shuffle) -------------------------------------------
__global__ __launch_bounds__(256) void stats_kernel(
    const float* __restrict__ LS, const float* __restrict__ LL,
    const float* __restrict__ DEL, const float* __restrict__ V,
    float* __restrict__ ST)
{
    int th = blockIdx.x;
    int d = threadIdx.x;
    int lane = d & 31, wid = d >> 5;
    size_t base = (size_t)th*256 + d;
    __shared__ float part[4][8][3];
    const float* ptrs[4] = {LS, LL, DEL, V};
#pragma unroll
    for (int sig = 0; sig < 4; ++sig) {
        float x = ptrs[sig][base];
        float a = x, bq = x*x, cc = fabsf(x);
#pragma unroll
        for (int off = 16; off; off >>= 1) {
            a  += __shfl_down_sync(0xffffffff, a, off);
            bq += __shfl_down_sync(0xffffffff, bq, off);
            cc += __shfl_down_sync(0xffffffff, cc, off);
        }
        if (lane == 0) { part[sig][wid][0] = a; part[sig][wid][1] = bq; part[sig][wid][2] = cc; }
    }
    __syncthreads();
    if (d < 4) {
        float s1 = 0.f, s2 = 0.f, s3 = 0.f;
#pragma unroll
        for (int wdx = 0; wdx < 8; ++wdx) {
            s1 += part[d][wdx][0]; s2 += part[d][wdx][1]; s3 += part[d][wdx][2];
        }
        float mean = s1 / 256.f;
        float var  = s2 / 256.f - mean*mean;
        float am   = s3 / 256.f;
        float l2   = sqrtf(s2);
        float* o = ST + (size_t)th*16 + d*4;
        o[0] = mean; o[1] = var; o[2] = am; o[3] = l2;
    }
}

// ---------------- gate MLP tail + softmax + floor -------------------------------
__global__ __launch_bounds__(256) void gate_kernel(
    const float* __restrict__ G1, const float* __restrict__ ST,
    const float* __restrict__ w1, const float* __restrict__ b1,
    const float* __restrict__ w2, const float* __restrict__ b2,
    const float* __restrict__ lt, float* __restrict__ P)
{
    int th = blockIdx.x;
    int t = th >> 2, h = th & 3;
    int tid = threadIdx.x;
    __shared__ float st[16];
    if (tid < 16) st[tid] = ST[(size_t)th*16 + tid];
    __syncthreads();
    float p0 = 0.f, p1 = 0.f, p2 = 0.f, p3 = 0.f;
    for (int j = tid; j < 1024; j += 256) {
        float x = G1[(size_t)t*1024 + j] + b1[j];
#pragma unroll
        for (int s = 0; s < 16; ++s) x += st[s] * w1[(size_t)(1024 + s)*1024 + j];
        float g = 0.5f * x * (1.f + erff(x * 0.70710678118654752f));
        p0 += g * w2[j*4 + 0]; p1 += g * w2[j*4 + 1];
        p2 += g * w2[j*4 + 2]; p3 += g * w2[j*4 + 3];
    }
    int lane = tid & 31, wid = tid >> 5;
#pragma unroll
    for (int off = 16; off; off >>= 1) {
        p0 += __shfl_down_sync(0xffffffff, p0, off);
        p1 += __shfl_down_sync(0xffffffff, p1, off);
        p2 += __shfl_down_sync(0xffffffff, p2, off);
        p3 += __shfl_down_sync(0xffffffff, p3, off);
    }
    __shared__ float part[8][4];
    if (lane == 0) { part[wid][0]=p0; part[wid][1]=p1; part[wid][2]=p2; part[wid][3]=p3; }
    __syncthreads();
    if (tid == 0) {
        float l[4] = {0.f, 0.f, 0.f, 0.f};
#pragma unroll
        for (int wdx = 0; wdx < 8; ++wdx) {
            l[0] += part[wdx][0]; l[1] += part[wdx][1];
            l[2] += part[wdx][2]; l[3] += part[wdx][3];
        }
        float inv_t = expf(-lt[h]);
#pragma unroll
        for (int cc = 0; cc < 4; ++cc) l[cc] = (l[cc] + b2[cc]) * inv_t;
        float m = fmaxf(fmaxf(l[0], l[1]), fmaxf(l[2], l[3]));
        float e[4], ssum = 0.f;
#pragma unroll
        for (int cc = 0; cc < 4; ++cc) { e[cc] = expf(l[cc] - m); ssum += e[cc]; }
#pragma unroll
        for (int cc = 0; cc < 4; ++cc)
            P[(size_t)th*4 + cc] = 0.05f + 0.8f * (e[cc] / ssum);
    }
}

// ---------------- mix + RMSNorm + bf16 split (fused epilogue) -------------------
__global__ __launch_bounds__(256) void mix_kernel(
    const float* __restrict__ LS, const float* __restrict__ LL,
    const float* __restrict__ DEL, const float* __restrict__ V,
    const float* __restrict__ P, const float* __restrict__ onw,
    __nv_bfloat16* __restrict__ A2)
{
    int th = blockIdx.x;        // t*4+h
    int d = threadIdx.x;
    int lane = d & 31, wid = d >> 5;
    size_t base = (size_t)th*256 + d;
    float p0 = P[th*4], p1 = P[th*4+1], p2 = P[th*4+2], p3 = P[th*4+3];
    float o = p0*LS[base] + p1*LL[base] + p2*DEL[base] + p3*V[base];
    float sq = o*o;
#pragma unroll
    for (int off = 16; off; off >>= 1) sq += __shfl_down_sync(0xffffffff, sq, off);
    __shared__ float part[8];
    if (lane == 0) part[wid] = sq;
    __syncthreads();
    float ssum = 0.f;
#pragma unroll
    for (int wdx = 0; wdx < 8; ++wdx) ssum += part[wdx];
    float ms = ssum / 256.f;
    float ov = o * rsqrtf(ms + 1e-5f) * onw[d];
    // write split directly: m = t = th>>2, kk = (th&3)*256 + d
    int t = th >> 2;
    int kk = (th & 3) * 256 + d;
    __nv_bfloat16 hi = __float2bfloat16(ov);
    float r = ov - __bfloat162float(hi);
    A2[(size_t)t * 2048 + kk]        = hi;
    A2[(size_t)t * 2048 + 1024 + kk] = __float2bfloat16(r);
}

// ---------------- launch ----------------------------------------------------------
extern "C" void kernel_launch(void* const* d_in, const int* in_sizes, int n_in,
                              void* d_out, int out_size)
{
    const float* hs = (const float*)d_in[0];
    const float* Wq = (const float*)d_in[1];
    const float* Wk = (const float*)d_in[2];
    const float* Wv = (const float*)d_in[3];
    const float* Wb = (const float*)d_in[4];
    const float* cq = (const float*)d_in[5];
    const float* ck = (const float*)d_in[6];
    const float* cv = (const float*)d_in[7];
    const float* fs = (const float*)d_in[8];
    const float* fl = (const float*)d_in[9];
    const float* w1 = (const float*)d_in[10];
    const float* b1 = (const float*)d_in[11];
    const float* w2 = (const float*)d_in[12];
    const float* b2 = (const float*)d_in[13];
    const float* lt = (const float*)d_in[14];
    const float* onw= (const float*)d_in[15];
    const float* Wo = (const float*)d_in[16];

    const int T = in_sizes[0] / HID;
    const int B = 2;
    const int L = T / B;

    float *tmp3, *q, *k, *v, *kb, *u, *w, *del, *ls, *ll, *g1, *aloc, *beta, *st, *pr;
    __nv_bfloat16 *a2, *bth, *btl, *bthg, *btlg, *btho, *btlo;
    cudaGetSymbolAddress((void**)&tmp3, g_tmp3);
    cudaGetSymbolAddress((void**)&q,    g_q);
    cudaGetSymbolAddress((void**)&k,    g_k);
    cudaGetSymbolAddress((void**)&v,    g_v);
    cudaGetSymbolAddress((void**)&kb,   g_kb);
    cudaGetSymbolAddress((void**)&u,    g_u);
    cudaGetSymbolAddress((void**)&w,    g_w);
    cudaGetSymbolAddress((void**)&del,  g_del);
    cudaGetSymbolAddress((void**)&ls,   g_ls);
    cudaGetSymbolAddress((void**)&ll,   g_ll);
    cudaGetSymbolAddress((void**)&g1,   g_g1);
    cudaGetSymbolAddress((void**)&aloc, g_aloc);
    cudaGetSymbolAddress((void**)&beta, g_beta);
    cudaGetSymbolAddress((void**)&st,   g_stats);
    cudaGetSymbolAddress((void**)&pr,   g_probs);
    cudaGetSymbolAddress((void**)&a2,   g_a2);
    cudaGetSymbolAddress((void**)&bth,  g_bth);
    cudaGetSymbolAddress((void**)&btl,  g_btl);
    cudaGetSymbolAddress((void**)&bthg, g_bthg);
    cudaGetSymbolAddress((void**)&btlg, g_btlg);
    cudaGetSymbolAddress((void**)&btho, g_btho);
    cudaGetSymbolAddress((void**)&btlo, g_btlo);

    // lazy stream/event init (resources only; identical graph every call)
    static cudaStream_t s1 = 0, s2 = 0, s3 = 0;
    static cudaEvent_t evA = 0, evQ = 0, evB = 0, evF = 0, evG = 0;
    if (!s1) {
        cudaStreamCreateWithFlags(&s1, cudaStreamNonBlocking);
        cudaStreamCreateWithFlags(&s2, cudaStreamNonBlocking);
        cudaStreamCreateWithFlags(&s3, cudaStreamNonBlocking);
        cudaEventCreateWithFlags(&evA, cudaEventDisableTiming);
        cudaEventCreateWithFlags(&evQ, cudaEventDisableTiming);
        cudaEventCreateWithFlags(&evB, cudaEventDisableTiming);
        cudaEventCreateWithFlags(&evF, cudaEventDisableTiming);
        cudaEventCreateWithFlags(&evG, cudaEventDisableTiming);
    }

    dim3 bt_grid(HID/32, HID/32);
    dim3 bt_blk(32, 8);
    int nsplit = (T*HID + 255) / 256;

    const int GEMM_SMEM = 2 * GSTAGE;
    cudaFuncSetAttribute(gemm_mma, cudaFuncAttributeMaxDynamicSharedMemorySize, GEMM_SMEM);
    size_t chunk_smem = (size_t)(3*32*QP + 32*KTP) * 4;
    size_t scan_smem  = (size_t)(NC*QP + 2*32*QP + 256*KTP + 32*KTP + NC*KTP) * 4;
    cudaFuncSetAttribute(chunk_kernel, cudaFuncAttributeMaxDynamicSharedMemorySize, (int)chunk_smem);
    cudaFuncSetAttribute(scan_kernel,  cudaFuncAttributeMaxDynamicSharedMemorySize, (int)scan_smem);

    // ---- stream0: split hs, fork ----
    asplit_kernel<<<nsplit, 256>>>(hs, a2, HID, T*HID);
    cudaEventRecord(evA, 0);

    // ---- s3 (fork after evA): beta ----
    cudaStreamWaitEvent(s3, evA, 0);
    beta_kernel<<<(T*NH + 7) / 8, 256, 0, s3>>>(hs, Wb, beta, T);
    cudaEventRecord(evB, s3);

    // ---- s1 (fork after evA): gate GEMM chain + Wo split ----
    cudaStreamWaitEvent(s1, evA, 0);
    bsplit_kernel<<<bt_grid, bt_blk, 0, s1>>>(w1, bthg, btlg, HID, HID);
    {
        dim3 gg(HID/BN, T/BM);
        gemm_mma<<<gg, 256, GEMM_SMEM, s1>>>(a2, bthg, btlg, g1, T, HID, HID);
    }
    bsplit_kernel<<<bt_grid, bt_blk, 0, s1>>>(Wo, btho, btlo, HID, HID);
    cudaEventRecord(evG, s1);

    // ---- stream0: QKV chain ----
    bsplit_kernel<<<bt_grid, bt_blk>>>(Wq, bth,             btl,             HID, HID);
    bsplit_kernel<<<bt_grid, bt_blk>>>(Wk, bth + HID*HID,   btl + HID*HID,   HID, HID);
    bsplit_kernel<<<bt_grid, bt_blk>>>(Wv, bth + 2*HID*HID, btl + 2*HID*HID, HID, HID);
    {
        dim3 gg(3*HID/BN, T/BM);
        gemm_mma<<<gg, 256, GEMM_SMEM>>>(a2, bth, btl, tmp3, T, 3*HID, HID);
    }
    conv_qkv_kernel<<<(T*768 + 255)/256, 256>>>(tmp3, cq, ck, cv, q, k, v, L, T*768);
    cudaEventRecord(evQ, 0);

    // ---- s2 (fork after evQ): FIR ----
    cudaStreamWaitEvent(s2, evQ, 0);
    fir_kernel<<<dim3(HID/64, T/64), 256, 0, s2>>>(v, fs, fl, ls, ll, L);
    cudaEventRecord(evF, s2);

    // ---- stream0: delta path ----
    cudaStreamWaitEvent(0, evB, 0);
    l2norm_kernel<<<T*NH, 256>>>(q, k, kb, beta);
    chunk_kernel<<<B*NH*(L/CHUNK), 256, chunk_smem>>>(q, k, kb, v, beta, u, w, aloc, L);
    scan_kernel<<<dim3(DV/NC, B*NH), 256, scan_smem>>>(q, k, u, w, aloc, del, L);

    // ---- join + epilogue ----
    cudaStreamWaitEvent(0, evF, 0);
    stats_kernel<<<T*NH, 256>>>(ls, ll, del, v, st);
    cudaStreamWaitEvent(0, evG, 0);
    gate_kernel<<<T*NH, 256>>>(g1, st, w1, b1, w2, b2, lt, pr);
    mix_kernel<<<T*NH, 256>>>(ls, ll, del, v, pr, onw, a2);
    {
        dim3 gg(HID/BN, T/BM);
        gemm_mma<<<gg, 256, GEMM_SMEM>>>(a2, btho, btlo, (float*)d_out, T, HID, HID);
    }
}

// round 10
// speedup vs baseline: 2.9559x; 1.0069x over previous
#include <cuda_runtime.h>
#include <cuda_bf16.h>
#include <math.h>
#include <stdint.h>

#define HID 1024
#define NH 4
#define DK 256
#define DV 256
#define CHUNK 32
#define TMAX 8192
#define QP 260
#define KTP 36
#define NC 16

// ---------------- scratch ----------------
__device__ float g_tmp3 [TMAX*3*HID];
__device__ float g_q    [TMAX*HID];
__device__ float g_k    [TMAX*HID];
__device__ float g_v    [TMAX*HID];
__device__ float g_kb   [TMAX*HID];
__device__ float g_u    [TMAX*HID];
__device__ float g_w    [TMAX*HID];
__device__ float g_del  [TMAX*HID];
__device__ float g_ls   [TMAX*HID];
__device__ float g_ll   [TMAX*HID];
__device__ float g_g1   [TMAX*HID];
__device__ float g_aloc [TMAX*NH*CHUNK];
__device__ float g_beta [TMAX*NH];
__device__ float g_stats[TMAX*NH*16];
__device__ float g_probs[TMAX*NH*4];
__device__ __nv_bfloat16 g_a2 [TMAX*2*HID];
__device__ __nv_bfloat16 g_bth[3*HID*HID];
__device__ __nv_bfloat16 g_btl[3*HID*HID];
__device__ __nv_bfloat16 g_bthg[HID*HID];
__device__ __nv_bfloat16 g_btlg[HID*HID];
__device__ __nv_bfloat16 g_btho[HID*HID];
__device__ __nv_bfloat16 g_btlo[HID*HID];

__device__ __forceinline__ uint32_t smem_u32(const void* p) {
    uint32_t a;
    asm("{ .reg .u64 t; cvta.to.shared.u64 t, %1; cvt.u32.u64 %0, t; }" : "=r"(a) : "l"(p));
    return a;
}
__device__ __forceinline__ void cp16(uint32_t dst, const void* src) {
    asm volatile("cp.async.cg.shared.global [%0], [%1], 16;" :: "r"(dst), "l"(src));
}

// ---------------- precision-split prep ----------------
__global__ void asplit_kernel(const float* __restrict__ X,
                              __nv_bfloat16* __restrict__ A2, int K, int total) {
    int idx = blockIdx.x * blockDim.x + threadIdx.x;
    if (idx >= total) return;
    int m = idx / K, kk = idx - m * K;
    float v = X[idx];
    __nv_bfloat16 hi = __float2bfloat16(v);
    float r = v - __bfloat162float(hi);
    A2[(size_t)m * 2 * K + kk]     = hi;
    A2[(size_t)m * 2 * K + K + kk] = __float2bfloat16(r);
}

__global__ void bsplit_kernel(const float* __restrict__ W,
                              __nv_bfloat16* __restrict__ Bh,
                              __nv_bfloat16* __restrict__ Bl, int K, int N) {
    __shared__ float t[32][33];
    int bn = blockIdx.x * 32, bk = blockIdx.y * 32;
    int x = threadIdx.x, y = threadIdx.y;
    for (int i = y; i < 32; i += 8) t[i][x] = W[(size_t)(bk + i) * N + bn + x];
    __syncthreads();
    for (int i = y; i < 32; i += 8) {
        float v = t[x][i];
        __nv_bfloat16 hi = __float2bfloat16(v);
        float r = v - __bfloat162float(hi);
        Bh[(size_t)(bn + i) * K + bk + x] = hi;
        Bl[(size_t)(bn + i) * K + bk + x] = __float2bfloat16(r);
    }
}

// ---------------- bf16 mma.sync GEMM (3-term split), BK=64, 3-stage -------------
#define BM 128
#define BN 128
#define BK 64
#define APITCH 72
#define ASTAGE (BM * APITCH * 2)
#define GSTAGE (2 * ASTAGE)
#define SST 3

__global__ __launch_bounds__(256) void gemm_mma(
    const __nv_bfloat16* __restrict__ A2, const __nv_bfloat16* __restrict__ Bh,
    const __nv_bfloat16* __restrict__ Bl, float* __restrict__ C,
    int M, int N, int K)
{
    extern __shared__ __align__(16) char gsm[];
    uint32_t sb = smem_u32(gsm);

    const int tid = threadIdx.x;
    const int wid = tid >> 5, lane = tid & 31;
    const int m0 = blockIdx.y * BM, n0 = blockIdx.x * BN;
    const int wm = (wid >> 2) * 64, wn = (wid & 3) * 32;

    const int KBn = K / BK;
    const int NB = 3 * KBn;
    const size_t sA = (size_t)2 * K;

    auto load_stage = [&](int kb, int buf) {
        int seg = kb / KBn;
        int kk = (kb - seg * KBn) * BK;
        const __nv_bfloat16* Ap = A2 + (seg == 1 ? (size_t)K : 0) + kk;
        const __nv_bfloat16* Bp = ((seg == 2) ? Bl : Bh) + kk;
        uint32_t a_s = sb + (uint32_t)buf * GSTAGE;
        uint32_t b_s = a_s + ASTAGE;
#pragma unroll
        for (int i = 0; i < 4; ++i) {
            int idx = i * 256 + tid;
            int row = idx >> 3, ch = idx & 7;
            cp16(a_s + (uint32_t)(row * APITCH + ch * 8) * 2,
                 Ap + (size_t)(m0 + row) * sA + ch * 8);
            cp16(b_s + (uint32_t)(row * APITCH + ch * 8) * 2,
                 Bp + (size_t)(n0 + row) * K + ch * 8);
        }
    };

    float acc[4][4][4];
#pragma unroll
    for (int mt = 0; mt < 4; ++mt)
#pragma unroll
        for (int nt = 0; nt < 4; ++nt)
#pragma unroll
            for (int e = 0; e < 4; ++e) acc[mt][nt][e] = 0.f;

    load_stage(0, 0);
    asm volatile("cp.async.commit_group;" ::: "memory");
    load_stage(1, 1);
    asm volatile("cp.async.commit_group;" ::: "memory");

    int buf = 0;
    for (int kb = 0; kb < NB; ++kb) {
        asm volatile("cp.async.wait_group 1;" ::: "memory");
        __syncthreads();
        if (kb + 2 < NB) load_stage(kb + 2, (buf + 2) % SST);
        asm volatile("cp.async.commit_group;" ::: "memory");

        uint32_t a_s = sb + (uint32_t)buf * GSTAGE;
        uint32_t b_s = a_s + ASTAGE;
#pragma unroll
        for (int kp = 0; kp < 4; ++kp) {
            uint32_t a[4][4], b[4][2];
            {
                int r_off = lane & 15;
                int c_off = kp * 16 + (lane >> 4) * 8;
#pragma unroll
                for (int mt = 0; mt < 4; ++mt) {
                    uint32_t addr = a_s + (uint32_t)((wm + mt * 16 + r_off) * APITCH + c_off) * 2;
                    asm volatile("ldmatrix.sync.aligned.m8n8.x4.shared.b16 {%0,%1,%2,%3}, [%4];"
                        : "=r"(a[mt][0]), "=r"(a[mt][1]), "=r"(a[mt][2]), "=r"(a[mt][3])
                        : "r"(addr));
                }
            }
            {
                int n_off = (lane & 7) + (lane >> 4) * 8;
                int c_off = kp * 16 + ((lane >> 3) & 1) * 8;
#pragma unroll
                for (int nb = 0; nb < 2; ++nb) {
                    uint32_t r0, r1, r2, r3;
                    uint32_t addr = b_s + (uint32_t)((wn + nb * 16 + n_off) * APITCH + c_off) * 2;
                    asm volatile("ldmatrix.sync.aligned.m8n8.x4.shared.b16 {%0,%1,%2,%3}, [%4];"
                        : "=r"(r0), "=r"(r1), "=r"(r2), "=r"(r3) : "r"(addr));
                    b[nb * 2][0] = r0;     b[nb * 2][1] = r1;
                    b[nb * 2 + 1][0] = r2; b[nb * 2 + 1][1] = r3;
                }
            }
#pragma unroll
            for (int mt = 0; mt < 4; ++mt)
#pragma unroll
                for (int nt = 0; nt < 4; ++nt) {
                    asm volatile(
                        "mma.sync.aligned.m16n8k16.row.col.f32.bf16.bf16.f32 "
                        "{%0,%1,%2,%3}, {%4,%5,%6,%7}, {%8,%9}, {%0,%1,%2,%3};"
                        : "+f"(acc[mt][nt][0]), "+f"(acc[mt][nt][1]),
                          "+f"(acc[mt][nt][2]), "+f"(acc[mt][nt][3])
                        : "r"(a[mt][0]), "r"(a[mt][1]), "r"(a[mt][2]), "r"(a[mt][3]),
                          "r"(b[nt][0]), "r"(b[nt][1]));
                }
        }
        __syncthreads();
        buf = (buf + 1) % SST;
    }

    int g = lane >> 2, tg = lane & 3;
#pragma unroll
    for (int mt = 0; mt < 4; ++mt) {
#pragma unroll
        for (int nt = 0; nt < 4; ++nt) {
            int row = m0 + wm + mt * 16 + g;
            int col = n0 + wn + nt * 8 + tg * 2;
            *(float2*)(C + (size_t)row * N + col) =
                make_float2(acc[mt][nt][0], acc[mt][nt][1]);
            *(float2*)(C + (size_t)(row + 8) * N + col) =
                make_float2(acc[mt][nt][2], acc[mt][nt][3]);
        }
    }
}

// ---------------- fused QKV conv + SiLU + l2norm + kb ---------------------------
// one CTA per timestep t; 256 threads x 4 channels per projection
__global__ __launch_bounds__(256) void conv_qkvn_kernel(
    const float* __restrict__ x3,
    const float* __restrict__ cq, const float* __restrict__ ck,
    const float* __restrict__ cv, const float* __restrict__ beta,
    float* __restrict__ q, float* __restrict__ k,
    float* __restrict__ kb, float* __restrict__ v, int L)
{
    int t = blockIdx.x;
    int b = t / L, l = t % L;
    int tid = threadIdx.x;
    int lane = tid & 31, wid = tid >> 5;
    int c = tid * 4;                    // channel base within 1024

    const float* wp[3] = {cq, ck, cv};
    float4 outv[3];
#pragma unroll
    for (int proj = 0; proj < 3; ++proj) {
        int cOff = proj * 1024 + c;
        float4 xv[4];
#pragma unroll
        for (int kk = 0; kk < 4; ++kk) {
            int ll = l - 3 + kk;
            xv[kk] = (ll >= 0) ? *(const float4*)&x3[((size_t)(b*L + ll))*3072 + cOff]
                               : make_float4(0.f, 0.f, 0.f, 0.f);
        }
        const float* w = wp[proj];
        float4 w0 = *(const float4*)&w[(c+0)*4];
        float4 w1 = *(const float4*)&w[(c+1)*4];
        float4 w2 = *(const float4*)&w[(c+2)*4];
        float4 w3 = *(const float4*)&w[(c+3)*4];
        float4 acc;
        acc.x = xv[0].x*w0.x + xv[1].x*w0.y + xv[2].x*w0.z + xv[3].x*w0.w;
        acc.y = xv[0].y*w1.x + xv[1].y*w1.y + xv[2].y*w1.z + xv[3].y*w1.w;
        acc.z = xv[0].z*w2.x + xv[1].z*w2.y + xv[2].z*w2.z + xv[3].z*w2.w;
        acc.w = xv[0].w*w3.x + xv[1].w*w3.y + xv[2].w*w3.z + xv[3].w*w3.w;
        acc.x = acc.x / (1.f + expf(-acc.x));
        acc.y = acc.y / (1.f + expf(-acc.y));
        acc.z = acc.z / (1.f + expf(-acc.z));
        acc.w = acc.w / (1.f + expf(-acc.w));
        outv[proj] = acc;
    }
    // v out directly
    *(float4*)&v[(size_t)t*HID + c] = outv[2];

    // per-head sumsq for q,k (head = tid>>6; 64 threads = 2 warps per head)
    float4 qa = outv[0], ka = outv[1];
    float sq = qa.x*qa.x + qa.y*qa.y + qa.z*qa.z + qa.w*qa.w;
    float sk = ka.x*ka.x + ka.y*ka.y + ka.z*ka.z + ka.w*ka.w;
#pragma unroll
    for (int off = 16; off; off >>= 1) {
        sq += __shfl_down_sync(0xffffffff, sq, off);
        sk += __shfl_down_sync(0xffffffff, sk, off);
    }
    __shared__ float pq[8], pk[8];
    if (lane == 0) { pq[wid] = sq; pk[wid] = sk; }
    __syncthreads();
    int h = tid >> 6;
    float sumq = pq[h*2] + pq[h*2+1];
    float sumk = pk[h*2] + pk[h*2+1];
    float rq = rsqrtf(sumq + 1e-6f);
    float rk = rsqrtf(sumk + 1e-6f);
    float bb = beta[t*NH + h];
    float4 qn = make_float4(qa.x*rq, qa.y*rq, qa.z*rq, qa.w*rq);
    float4 kn = make_float4(ka.x*rk, ka.y*rk, ka.z*rk, ka.w*rk);
    float4 kbv = make_float4(kn.x*bb, kn.y*bb, kn.z*bb, kn.w*bb);
    *(float4*)&q [(size_t)t*HID + c] = qn;
    *(float4*)&k [(size_t)t*HID + c] = kn;
    *(float4*)&kb[(size_t)t*HID + c] = kbv;
}

// ---------------- fused FIR conv (short K=5 + long K=64), smem-tiled ------------
__global__ __launch_bounds__(256) void fir_kernel(
    const float* __restrict__ V, const float* __restrict__ fs,
    const float* __restrict__ fl, float* __restrict__ LS,
    float* __restrict__ LL, int L)
{
    __shared__ float xs[127*64];
    int ct = blockIdx.x;
    int tt = blockIdx.y;
    int c0 = ct * 64;
    int t0 = tt * 64;
    int b = t0 / L;
    int l0 = t0 - b * L;
    int tid = threadIdx.x;

    for (int idx = tid; idx < 127*64; idx += 256) {
        int row = idx >> 6, c = idx & 63;
        int l = l0 - 63 + row;
        xs[idx] = (l >= 0) ? V[((size_t)(b*L + l))*HID + c0 + c] : 0.f;
    }

    int c = tid & 63;
    int tg = tid >> 6;
    int cg = c0 + c;
    float wl[64];
#pragma unroll
    for (int kk = 0; kk < 64; ++kk) wl[kk] = fl[cg*64 + kk];
    float ws[5];
#pragma unroll
    for (int kk = 0; kk < 5; ++kk) ws[kk] = fs[cg*5 + kk];
    __syncthreads();

    for (int j = 0; j < 16; ++j) {
        int jj = tg*16 + j;
        float accl = 0.f, accs = 0.f;
#pragma unroll
        for (int kk = 0; kk < 64; ++kk) accl += xs[(jj+kk)*64 + c] * wl[kk];
#pragma unroll
        for (int kk = 0; kk < 5; ++kk) accs += xs[(jj+59+kk)*64 + c] * ws[kk];
        size_t o = ((size_t)(t0 + jj))*HID + cg;
        LL[o] = accl;
        LS[o] = accs;
    }
}

// ---------------- beta ------------------------------------------------------------
__global__ void beta_kernel(const float* __restrict__ hs, const float* __restrict__ Wb,
                            float* __restrict__ beta, int T)
{
    int gw = (blockIdx.x * blockDim.x + threadIdx.x) >> 5;
    int lane = threadIdx.x & 31;
    if (gw >= T * NH) return;
    int t = gw / NH, h = gw % NH;
    float s = 0.f;
    for (int r = lane; r < HID; r += 32) s += hs[(size_t)t*HID + r] * Wb[r*NH + h];
#pragma unroll
    for (int off = 16; off; off >>= 1) s += __shfl_down_sync(0xffffffff, s, off);
    if (lane == 0) beta[t*NH + h] = 1.f / (1.f + expf(-s));
}

// ---------------- per-chunk: attn inversion + u, w, attn_loc --------------------
__global__ __launch_bounds__(256) void chunk_kernel(
    const float* __restrict__ Qn, const float* __restrict__ Kn,
    const float* __restrict__ KB, const float* __restrict__ V,
    const float* __restrict__ beta, float* __restrict__ U,
    float* __restrict__ Wbuf, float* __restrict__ Aloc, int L)
{
    extern __shared__ float sm[];
    float* q_s  = sm;
    float* kn_s = q_s  + 32*QP;
    float* kb_s = kn_s + 32*QP;
    float* A    = kb_s + 32*QP;
    int nch = L / CHUNK;
    int cid = blockIdx.x;
    int ch = cid % nch;
    int h  = (cid / nch) & (NH - 1);
    int b  = cid / (nch * NH);
    int l0 = ch * CHUNK;
    int tid = threadIdx.x;
    int lane = tid & 31;
    int iw = tid >> 5;
    size_t base = ((size_t)(b*L + l0)) * HID + h*DK;

    for (int r = 0; r < 32; ++r) {
        size_t g = base + (size_t)r*HID + tid;
        q_s [r*QP + tid] = Qn[g];
        kn_s[r*QP + tid] = Kn[g];
        kb_s[r*QP + tid] = KB[g];
    }
    __syncthreads();

    size_t abase = (size_t)cid * (CHUNK*CHUNK);
#pragma unroll
    for (int r = 0; r < 4; ++r) {
        int i = r*8 + iw, j = lane;
        float sA = 0.f, sL = 0.f;
#pragma unroll 8
        for (int dq = 0; dq < 64; ++dq) {
            float4 kn = *(float4*)&kn_s[j*QP + dq*4];
            float4 kbv = *(float4*)&kb_s[i*QP + dq*4];
            float4 qv = *(float4*)&q_s [i*QP + dq*4];
            sA += kbv.x*kn.x + kbv.y*kn.y + kbv.z*kn.z + kbv.w*kn.w;
            sL += qv.x*kn.x + qv.y*kn.y + qv.z*kn.z + qv.w*kn.w;
        }
        A[i*KTP + j] = (i > j) ? -sA : 0.f;
        Aloc[abase + i*32 + j] = (j <= i) ? sL : 0.f;
    }
    __syncthreads();

    if (tid < 32) {
        int j = tid;
        for (int i = 1; i < 32; ++i) {
            float s = 0.f;
            if (j < i) {
#pragma unroll
                for (int t2 = 0; t2 < 32; ++t2) s += A[i*KTP + t2] * A[t2*KTP + j];
            }
            __syncwarp();
            if (j < i) A[i*KTP + j] += s;
            __syncwarp();
        }
        A[j*KTP + j] += 1.f;
    }
    __syncthreads();

    for (int r = 0; r < 32; ++r) {
        float bb = beta[(b*L + l0 + r)*NH + h];
        q_s[r*QP + tid] = V[base + (size_t)r*HID + tid] * bb;
    }
    __syncthreads();

    float vc[32], kc[32];
#pragma unroll
    for (int t2 = 0; t2 < 32; ++t2) {
        vc[t2] = q_s [t2*QP + tid];
        kc[t2] = kb_s[t2*QP + tid];
    }

    for (int i = 0; i < 32; ++i) {
        float su = 0.f, sw = 0.f;
#pragma unroll
        for (int qq = 0; qq < 8; ++qq) {
            float4 a = *(float4*)&A[i*KTP + qq*4];
            su += a.x*vc[qq*4] + a.y*vc[qq*4+1] + a.z*vc[qq*4+2] + a.w*vc[qq*4+3];
            sw += a.x*kc[qq*4] + a.y*kc[qq*4+1] + a.z*kc[qq*4+2] + a.w*kc[qq*4+3];
        }
        U   [base + (size_t)i*HID + tid] = su;
        Wbuf[base + (size_t)i*HID + tid] = sw;
    }
}

// ---------------- sequential chunk scan: 128 CTAs, 16 cols each -----------------
__global__ __launch_bounds__(256) void scan_kernel(
    const float* __restrict__ Qn, const float* __restrict__ Kn,
    const float* __restrict__ U,  const float* __restrict__ Wbuf,
    const float* __restrict__ Aloc, float* __restrict__ Dout, int L)
{
    extern __shared__ float sm[];
    float* Ssm_t = sm;
    float* q_s   = Ssm_t + NC*QP;
    float* w_s   = q_s   + 32*QP;
    float* k_t   = w_s   + 32*QP;
    float* al    = k_t   + 256*KTP;
    float* ul_t  = al    + 32*KTP;

    int cb = blockIdx.x;
    int bh = blockIdx.y;
    int b = bh >> 2, h = bh & 3;
    int tid = threadIdx.x;
    int c  = tid & (NC - 1);
    int gi = tid >> 4;
    int nch = L / CHUNK;

    float Sreg[16];
#pragma unroll
    for (int r = 0; r < 16; ++r) Sreg[r] = 0.f;

    for (int ch = 0; ch < nch; ++ch) {
        int l0 = ch * CHUNK;
        size_t base = ((size_t)(b*L + l0)) * HID + h*DK;

#pragma unroll
        for (int r = 0; r < 16; ++r) Ssm_t[c*QP + r*16 + gi] = Sreg[r];
        for (int r = 0; r < 32; ++r) {
            size_t g = base + (size_t)r*HID + tid;
            q_s[r*QP + tid] = Qn[g];
            w_s[r*QP + tid] = Wbuf[g];
            k_t[tid*KTP + r] = Kn[g];
        }
        size_t abase = (size_t)((b*NH + h)*nch + ch) * 1024;
#pragma unroll
        for (int e0 = 0; e0 < 4; ++e0) {
            int e = e0*256 + tid;
            al[(e >> 5)*KTP + (e & 31)] = Aloc[abase + e];
        }

        float uacc[2], oacc[2] = {0.f, 0.f};
#pragma unroll
        for (int r2 = 0; r2 < 2; ++r2)
            uacc[r2] = U[((size_t)(b*L + l0 + (r2*16 + gi)))*HID + h*DV + cb*NC + c];
        __syncthreads();

#pragma unroll 4
        for (int dq = 0; dq < 64; ++dq) {
            float4 sv = *(float4*)&Ssm_t[c*QP + dq*4];
#pragma unroll
            for (int r2 = 0; r2 < 2; ++r2) {
                int i = r2*16 + gi;
                float4 wv = *(float4*)&w_s[i*QP + dq*4];
                float4 qv = *(float4*)&q_s[i*QP + dq*4];
                uacc[r2] -= wv.x*sv.x + wv.y*sv.y + wv.z*sv.z + wv.w*sv.w;
                oacc[r2] += qv.x*sv.x + qv.y*sv.y + qv.z*sv.z + qv.w*sv.w;
            }
        }
#pragma unroll
        for (int r2 = 0; r2 < 2; ++r2) ul_t[c*KTP + r2*16 + gi] = uacc[r2];
        __syncthreads();

        float ulreg[32];
#pragma unroll
        for (int qq = 0; qq < 8; ++qq) {
            float4 t4 = *(float4*)&ul_t[c*KTP + qq*4];
            ulreg[qq*4] = t4.x; ulreg[qq*4+1] = t4.y;
            ulreg[qq*4+2] = t4.z; ulreg[qq*4+3] = t4.w;
        }

#pragma unroll
        for (int qq = 0; qq < 8; ++qq) {
#pragma unroll
            for (int r2 = 0; r2 < 2; ++r2) {
                int i = r2*16 + gi;
                float4 av = *(float4*)&al[i*KTP + qq*4];
                oacc[r2] += av.x*ulreg[qq*4] + av.y*ulreg[qq*4+1]
                          + av.z*ulreg[qq*4+2] + av.w*ulreg[qq*4+3];
            }
        }
#pragma unroll
        for (int r2 = 0; r2 < 2; ++r2)
            Dout[((size_t)(b*L + l0 + (r2*16 + gi)))*HID + h*DV + cb*NC + c] = oacc[r2];

#pragma unroll
        for (int qq = 0; qq < 8; ++qq) {
#pragma unroll
            for (int r = 0; r < 16; ++r) {
                float4 kv = *(float4*)&k_t[(r*16 + gi)*KTP + qq*4];
                Sreg[r] += kv.x*ulreg[qq*4] + kv.y*ulreg[qq*4+1]
                         + kv.z*ulreg[qq*4+2] + kv.w*ulreg[qq*4+3];
            }
        }
        __syncthreads();
    }
}

// ---------------- stats (warp-shuffle) -------------------------------------------
__global__ __launch_bounds__(256) void stats_kernel(
    const float* __restrict__ LS, const float* __restrict__ LL,
    const float* __restrict__ DEL, const float* __restrict__ V,
    float* __restrict__ ST)
{
    int th = blockIdx.x;
    int d = threadIdx.x;
    int lane = d & 31, wid = d >> 5;
    size_t base = (size_t)th*256 + d;
    __shared__ float part[4][8][3];
    const float* ptrs[4] = {LS, LL, DEL, V};
#pragma unroll
    for (int sig = 0; sig < 4; ++sig) {
        float x = ptrs[sig][base];
        float a = x, bq = x*x, cc = fabsf(x);
#pragma unroll
        for (int off = 16; off; off >>= 1) {
            a  += __shfl_down_sync(0xffffffff, a, off);
            bq += __shfl_down_sync(0xffffffff, bq, off);
            cc += __shfl_down_sync(0xffffffff, cc, off);
        }
        if (lane == 0) { part[sig][wid][0] = a; part[sig][wid][1] = bq; part[sig][wid][2] = cc; }
    }
    __syncthreads();
    if (d < 4) {
        float s1 = 0.f, s2 = 0.f, s3 = 0.f;
#pragma unroll
        for (int wdx = 0; wdx < 8; ++wdx) {
            s1 += part[d][wdx][0]; s2 += part[d][wdx][1]; s3 += part[d][wdx][2];
        }
        float mean = s1 / 256.f;
        float var  = s2 / 256.f - mean*mean;
        float am   = s3 / 256.f;
        float l2   = sqrtf(s2);
        float* o = ST + (size_t)th*16 + d*4;
        o[0] = mean; o[1] = var; o[2] = am; o[3] = l2;
    }
}

// ---------------- gate MLP tail + softmax + floor -------------------------------
__global__ __launch_bounds__(256) void gate_kernel(
    const float* __restrict__ G1, const float* __restrict__ ST,
    const float* __restrict__ w1, const float* __restrict__ b1,
    const float* __restrict__ w2, const float* __restrict__ b2,
    const float* __restrict__ lt, float* __restrict__ P)
{
    int th = blockIdx.x;
    int t = th >> 2, h = th & 3;
    int tid = threadIdx.x;
    __shared__ float st[16];
    if (tid < 16) st[tid] = ST[(size_t)th*16 + tid];
    __syncthreads();
    float p0 = 0.f, p1 = 0.f, p2 = 0.f, p3 = 0.f;
    for (int j = tid; j < 1024; j += 256) {
        float x = G1[(size_t)t*1024 + j] + b1[j];
#pragma unroll
        for (int s = 0; s < 16; ++s) x += st[s] * w1[(size_t)(1024 + s)*1024 + j];
        float g = 0.5f * x * (1.f + erff(x * 0.70710678118654752f));
        p0 += g * w2[j*4 + 0]; p1 += g * w2[j*4 + 1];
        p2 += g * w2[j*4 + 2]; p3 += g * w2[j*4 + 3];
    }
    int lane = tid & 31, wid = tid >> 5;
#pragma unroll
    for (int off = 16; off; off >>= 1) {
        p0 += __shfl_down_sync(0xffffffff, p0, off);
        p1 += __shfl_down_sync(0xffffffff, p1, off);
        p2 += __shfl_down_sync(0xffffffff, p2, off);
        p3 += __shfl_down_sync(0xffffffff, p3, off);
    }
    __shared__ float part[8][4];
    if (lane == 0) { part[wid][0]=p0; part[wid][1]=p1; part[wid][2]=p2; part[wid][3]=p3; }
    __syncthreads();
    if (tid == 0) {
        float l[4] = {0.f, 0.f, 0.f, 0.f};
#pragma unroll
        for (int wdx = 0; wdx < 8; ++wdx) {
            l[0] += part[wdx][0]; l[1] += part[wdx][1];
            l[2] += part[wdx][2]; l[3] += part[wdx][3];
        }
        float inv_t = expf(-lt[h]);
#pragma unroll
        for (int cc = 0; cc < 4; ++cc) l[cc] = (l[cc] + b2[cc]) * inv_t;
        float m = fmaxf(fmaxf(l[0], l[1]), fmaxf(l[2], l[3]));
        float e[4], ssum = 0.f;
#pragma unroll
        for (int cc = 0; cc < 4; ++cc) { e[cc] = expf(l[cc] - m); ssum += e[cc]; }
#pragma unroll
        for (int cc = 0; cc < 4; ++cc)
            P[(size_t)th*4 + cc] = 0.05f + 0.8f * (e[cc] / ssum);
    }
}

// ---------------- mix + RMSNorm + bf16 split (fused epilogue) -------------------
__global__ __launch_bounds__(256) void mix_kernel(
    const float* __restrict__ LS, const float* __restrict__ LL,
    const float* __restrict__ DEL, const float* __restrict__ V,
    const float* __restrict__ P, const float* __restrict__ onw,
    __nv_bfloat16* __restrict__ A2)
{
    int th = blockIdx.x;
    int d = threadIdx.x;
    int lane = d & 31, wid = d >> 5;
    size_t base = (size_t)th*256 + d;
    float p0 = P[th*4], p1 = P[th*4+1], p2 = P[th*4+2], p3 = P[th*4+3];
    float o = p0*LS[base] + p1*LL[base] + p2*DEL[base] + p3*V[base];
    float sq = o*o;
#pragma unroll
    for (int off = 16; off; off >>= 1) sq += __shfl_down_sync(0xffffffff, sq, off);
    __shared__ float part[8];
    if (lane == 0) part[wid] = sq;
    __syncthreads();
    float ssum = 0.f;
#pragma unroll
    for (int wdx = 0; wdx < 8; ++wdx) ssum += part[wdx];
    float ms = ssum / 256.f;
    float ov = o * rsqrtf(ms + 1e-5f) * onw[d];
    int t = th >> 2;
    int kk = (th & 3) * 256 + d;
    __nv_bfloat16 hi = __float2bfloat16(ov);
    float r = ov - __bfloat162float(hi);
    A2[(size_t)t * 2048 + kk]        = hi;
    A2[(size_t)t * 2048 + 1024 + kk] = __float2bfloat16(r);
}

// ---------------- launch ----------------------------------------------------------
extern "C" void kernel_launch(void* const* d_in, const int* in_sizes, int n_in,
                              void* d_out, int out_size)
{
    const float* hs = (const float*)d_in[0];
    const float* Wq = (const float*)d_in[1];
    const float* Wk = (const float*)d_in[2];
    const float* Wv = (const float*)d_in[3];
    const float* Wb = (const float*)d_in[4];
    const float* cq = (const float*)d_in[5];
    const float* ck = (const float*)d_in[6];
    const float* cv = (const float*)d_in[7];
    const float* fs = (const float*)d_in[8];
    const float* fl = (const float*)d_in[9];
    const float* w1 = (const float*)d_in[10];
    const float* b1 = (const float*)d_in[11];
    const float* w2 = (const float*)d_in[12];
    const float* b2 = (const float*)d_in[13];
    const float* lt = (const float*)d_in[14];
    const float* onw= (const float*)d_in[15];
    const float* Wo = (const float*)d_in[16];

    const int T = in_sizes[0] / HID;
    const int B = 2;
    const int L = T / B;

    float *tmp3, *q, *k, *v, *kb, *u, *w, *del, *ls, *ll, *g1, *aloc, *beta, *st, *pr;
    __nv_bfloat16 *a2, *bth, *btl, *bthg, *btlg, *btho, *btlo;
    cudaGetSymbolAddress((void**)&tmp3, g_tmp3);
    cudaGetSymbolAddress((void**)&q,    g_q);
    cudaGetSymbolAddress((void**)&k,    g_k);
    cudaGetSymbolAddress((void**)&v,    g_v);
    cudaGetSymbolAddress((void**)&kb,   g_kb);
    cudaGetSymbolAddress((void**)&u,    g_u);
    cudaGetSymbolAddress((void**)&w,    g_w);
    cudaGetSymbolAddress((void**)&del,  g_del);
    cudaGetSymbolAddress((void**)&ls,   g_ls);
    cudaGetSymbolAddress((void**)&ll,   g_ll);
    cudaGetSymbolAddress((void**)&g1,   g_g1);
    cudaGetSymbolAddress((void**)&aloc, g_aloc);
    cudaGetSymbolAddress((void**)&beta, g_beta);
    cudaGetSymbolAddress((void**)&st,   g_stats);
    cudaGetSymbolAddress((void**)&pr,   g_probs);
    cudaGetSymbolAddress((void**)&a2,   g_a2);
    cudaGetSymbolAddress((void**)&bth,  g_bth);
    cudaGetSymbolAddress((void**)&btl,  g_btl);
    cudaGetSymbolAddress((void**)&bthg, g_bthg);
    cudaGetSymbolAddress((void**)&btlg, g_btlg);
    cudaGetSymbolAddress((void**)&btho, g_btho);
    cudaGetSymbolAddress((void**)&btlo, g_btlo);

    static cudaStream_t s1 = 0, s2 = 0, s3 = 0;
    static cudaEvent_t evA = 0, evQ = 0, evB = 0, evF = 0, evG = 0;
    if (!s1) {
        cudaStreamCreateWithFlags(&s1, cudaStreamNonBlocking);
        cudaStreamCreateWithFlags(&s2, cudaStreamNonBlocking);
        cudaStreamCreateWithFlags(&s3, cudaStreamNonBlocking);
        cudaEventCreateWithFlags(&evA, cudaEventDisableTiming);
        cudaEventCreateWithFlags(&evQ, cudaEventDisableTiming);
        cudaEventCreateWithFlags(&evB, cudaEventDisableTiming);
        cudaEventCreateWithFlags(&evF, cudaEventDisableTiming);
        cudaEventCreateWithFlags(&evG, cudaEventDisableTiming);
    }

    dim3 bt_grid(HID/32, HID/32);
    dim3 bt_blk(32, 8);
    int nsplit = (T*HID + 255) / 256;

    const int GEMM_SMEM = SST * GSTAGE;   // 110592 B
    cudaFuncSetAttribute(gemm_mma, cudaFuncAttributeMaxDynamicSharedMemorySize, GEMM_SMEM);
    size_t chunk_smem = (size_t)(3*32*QP + 32*KTP) * 4;
    size_t scan_smem  = (size_t)(NC*QP + 2*32*QP + 256*KTP + 32*KTP + NC*KTP) * 4;
    cudaFuncSetAttribute(chunk_kernel, cudaFuncAttributeMaxDynamicSharedMemorySize, (int)chunk_smem);
    cudaFuncSetAttribute(scan_kernel,  cudaFuncAttributeMaxDynamicSharedMemorySize, (int)scan_smem);

    // ---- stream0: split hs, fork ----
    asplit_kernel<<<nsplit, 256>>>(hs, a2, HID, T*HID);
    cudaEventRecord(evA, 0);

    // ---- s3: beta ----
    cudaStreamWaitEvent(s3, evA, 0);
    beta_kernel<<<(T*NH + 7) / 8, 256, 0, s3>>>(hs, Wb, beta, T);
    cudaEventRecord(evB, s3);

    // ---- s1: gate GEMM chain + Wo split ----
    cudaStreamWaitEvent(s1, evA, 0);
    bsplit_kernel<<<bt_grid, bt_blk, 0, s1>>>(w1, bthg, btlg, HID, HID);
    {
        dim3 gg(HID/BN, T/BM);
        gemm_mma<<<gg, 256, GEMM_SMEM, s1>>>(a2, bthg, btlg, g1, T, HID, HID);
    }
    bsplit_kernel<<<bt_grid, bt_blk, 0, s1>>>(Wo, btho, btlo, HID, HID);
    cudaEventRecord(evG, s1);

    // ---- stream0: QKV chain ----
    bsplit_kernel<<<bt_grid, bt_blk>>>(Wq, bth,             btl,             HID, HID);
    bsplit_kernel<<<bt_grid, bt_blk>>>(Wk, bth + HID*HID,   btl + HID*HID,   HID, HID);
    bsplit_kernel<<<bt_grid, bt_blk>>>(Wv, bth + 2*HID*HID, btl + 2*HID*HID, HID, HID);
    {
        dim3 gg(3*HID/BN, T/BM);
        gemm_mma<<<gg, 256, GEMM_SMEM>>>(a2, bth, btl, tmp3, T, 3*HID, HID);
    }
    cudaStreamWaitEvent(0, evB, 0);
    conv_qkvn_kernel<<<T, 256>>>(tmp3, cq, ck, cv, beta, q, k, kb, v, L);
    cudaEventRecord(evQ, 0);

    // ---- s2: FIR ----
    cudaStreamWaitEvent(s2, evQ, 0);
    fir_kernel<<<dim3(HID/64, T/64), 256, 0, s2>>>(v, fs, fl, ls, ll, L);
    cudaEventRecord(evF, s2);

    // ---- stream0: delta path ----
    chunk_kernel<<<B*NH*(L/CHUNK), 256, chunk_smem>>>(q, k, kb, v, beta, u, w, aloc, L);
    scan_kernel<<<dim3(DV/NC, B*NH), 256, scan_smem>>>(q, k, u, w, aloc, del, L);

    // ---- join + epilogue ----
    cudaStreamWaitEvent(0, evF, 0);
    stats_kernel<<<T*NH, 256>>>(ls, ll, del, v, st);
    cudaStreamWaitEvent(0, evG, 0);
    gate_kernel<<<T*NH, 256>>>(g1, st, w1, b1, w2, b2, lt, pr);
    mix_kernel<<<T*NH, 256>>>(ls, ll, del, v, pr, onw, a2);
    {
        dim3 gg(HID/BN, T/BM);
        gemm_mma<<<gg, 256, GEMM_SMEM>>>(a2, btho, btlo, (float*)d_out, T, HID, HID);
    }
}

// round 11
// speedup vs baseline: 3.1309x; 1.0592x over previous
#include <cuda_runtime.h>
#include <cuda_bf16.h>
#include <math.h>
#include <stdint.h>

#define HID 1024
#define NH 4
#define DK 256
#define DV 256
#define CHUNK 32
#define TMAX 8192
#define QP 260
#define KTP 36
#define NC 16

// ---------------- scratch ----------------
__device__ float g_tmp3 [TMAX*3*HID];
__device__ float g_q    [TMAX*HID];
__device__ float g_k    [TMAX*HID];
__device__ float g_v    [TMAX*HID];
__device__ float g_kb   [TMAX*HID];
__device__ float g_u    [TMAX*HID];
__device__ float g_w    [TMAX*HID];
__device__ float g_del  [TMAX*HID];
__device__ float g_ls   [TMAX*HID];
__device__ float g_ll   [TMAX*HID];
__device__ float g_g1   [TMAX*HID];
__device__ float g_aloc [TMAX*NH*CHUNK];
__device__ float g_beta [TMAX*NH];
__device__ __nv_bfloat16 g_a2 [TMAX*2*HID];
__device__ __nv_bfloat16 g_bth[3*HID*HID];
__device__ __nv_bfloat16 g_btl[3*HID*HID];
__device__ __nv_bfloat16 g_bthg[HID*HID];
__device__ __nv_bfloat16 g_btlg[HID*HID];
__device__ __nv_bfloat16 g_btho[HID*HID];
__device__ __nv_bfloat16 g_btlo[HID*HID];

__device__ __forceinline__ uint32_t smem_u32(const void* p) {
    uint32_t a;
    asm("{ .reg .u64 t; cvta.to.shared.u64 t, %1; cvt.u32.u64 %0, t; }" : "=r"(a) : "l"(p));
    return a;
}
__device__ __forceinline__ void cp16(uint32_t dst, const void* src) {
    asm volatile("cp.async.cg.shared.global [%0], [%1], 16;" :: "r"(dst), "l"(src));
}

// ---------------- precision-split prep ----------------
__global__ void asplit_kernel(const float* __restrict__ X,
                              __nv_bfloat16* __restrict__ A2, int K, int total) {
    int idx = blockIdx.x * blockDim.x + threadIdx.x;
    if (idx >= total) return;
    int m = idx / K, kk = idx - m * K;
    float v = X[idx];
    __nv_bfloat16 hi = __float2bfloat16(v);
    float r = v - __bfloat162float(hi);
    A2[(size_t)m * 2 * K + kk]     = hi;
    A2[(size_t)m * 2 * K + K + kk] = __float2bfloat16(r);
}

__global__ void bsplit_kernel(const float* __restrict__ W,
                              __nv_bfloat16* __restrict__ Bh,
                              __nv_bfloat16* __restrict__ Bl, int K, int N) {
    __shared__ float t[32][33];
    int bn = blockIdx.x * 32, bk = blockIdx.y * 32;
    int x = threadIdx.x, y = threadIdx.y;
    for (int i = y; i < 32; i += 8) t[i][x] = W[(size_t)(bk + i) * N + bn + x];
    __syncthreads();
    for (int i = y; i < 32; i += 8) {
        float v = t[x][i];
        __nv_bfloat16 hi = __float2bfloat16(v);
        float r = v - __bfloat162float(hi);
        Bh[(size_t)(bn + i) * K + bk + x] = hi;
        Bl[(size_t)(bn + i) * K + bk + x] = __float2bfloat16(r);
    }
}

// ---------------- bf16 mma.sync GEMM (3-term split), BK=64, 3-stage -------------
#define BM 128
#define BN 128
#define BK 64
#define APITCH 72
#define ASTAGE (BM * APITCH * 2)
#define GSTAGE (2 * ASTAGE)
#define SST 3

__global__ __launch_bounds__(256) void gemm_mma(
    const __nv_bfloat16* __restrict__ A2, const __nv_bfloat16* __restrict__ Bh,
    const __nv_bfloat16* __restrict__ Bl, float* __restrict__ C,
    int M, int N, int K)
{
    extern __shared__ __align__(16) char gsm[];
    uint32_t sb = smem_u32(gsm);

    const int tid = threadIdx.x;
    const int wid = tid >> 5, lane = tid & 31;
    const int m0 = blockIdx.y * BM, n0 = blockIdx.x * BN;
    const int wm = (wid >> 2) * 64, wn = (wid & 3) * 32;

    const int KBn = K / BK;
    const int NB = 3 * KBn;
    const size_t sA = (size_t)2 * K;

    auto load_stage = [&](int kb, int buf) {
        int seg = kb / KBn;
        int kk = (kb - seg * KBn) * BK;
        const __nv_bfloat16* Ap = A2 + (seg == 1 ? (size_t)K : 0) + kk;
        const __nv_bfloat16* Bp = ((seg == 2) ? Bl : Bh) + kk;
        uint32_t a_s = sb + (uint32_t)buf * GSTAGE;
        uint32_t b_s = a_s + ASTAGE;
#pragma unroll
        for (int i = 0; i < 4; ++i) {
            int idx = i * 256 + tid;
            int row = idx >> 3, ch = idx & 7;
            cp16(a_s + (uint32_t)(row * APITCH + ch * 8) * 2,
                 Ap + (size_t)(m0 + row) * sA + ch * 8);
            cp16(b_s + (uint32_t)(row * APITCH + ch * 8) * 2,
                 Bp + (size_t)(n0 + row) * K + ch * 8);
        }
    };

    float acc[4][4][4];
#pragma unroll
    for (int mt = 0; mt < 4; ++mt)
#pragma unroll
        for (int nt = 0; nt < 4; ++nt)
#pragma unroll
            for (int e = 0; e < 4; ++e) acc[mt][nt][e] = 0.f;

    load_stage(0, 0);
    asm volatile("cp.async.commit_group;" ::: "memory");
    load_stage(1, 1);
    asm volatile("cp.async.commit_group;" ::: "memory");

    int buf = 0;
    for (int kb = 0; kb < NB; ++kb) {
        asm volatile("cp.async.wait_group 1;" ::: "memory");
        __syncthreads();
        if (kb + 2 < NB) load_stage(kb + 2, (buf + 2) % SST);
        asm volatile("cp.async.commit_group;" ::: "memory");

        uint32_t a_s = sb + (uint32_t)buf * GSTAGE;
        uint32_t b_s = a_s + ASTAGE;
#pragma unroll
        for (int kp = 0; kp < 4; ++kp) {
            uint32_t a[4][4], b[4][2];
            {
                int r_off = lane & 15;
                int c_off = kp * 16 + (lane >> 4) * 8;
#pragma unroll
                for (int mt = 0; mt < 4; ++mt) {
                    uint32_t addr = a_s + (uint32_t)((wm + mt * 16 + r_off) * APITCH + c_off) * 2;
                    asm volatile("ldmatrix.sync.aligned.m8n8.x4.shared.b16 {%0,%1,%2,%3}, [%4];"
                        : "=r"(a[mt][0]), "=r"(a[mt][1]), "=r"(a[mt][2]), "=r"(a[mt][3])
                        : "r"(addr));
                }
            }
            {
                int n_off = (lane & 7) + (lane >> 4) * 8;
                int c_off = kp * 16 + ((lane >> 3) & 1) * 8;
#pragma unroll
                for (int nb = 0; nb < 2; ++nb) {
                    uint32_t r0, r1, r2, r3;
                    uint32_t addr = b_s + (uint32_t)((wn + nb * 16 + n_off) * APITCH + c_off) * 2;
                    asm volatile("ldmatrix.sync.aligned.m8n8.x4.shared.b16 {%0,%1,%2,%3}, [%4];"
                        : "=r"(r0), "=r"(r1), "=r"(r2), "=r"(r3) : "r"(addr));
                    b[nb * 2][0] = r0;     b[nb * 2][1] = r1;
                    b[nb * 2 + 1][0] = r2; b[nb * 2 + 1][1] = r3;
                }
            }
#pragma unroll
            for (int mt = 0; mt < 4; ++mt)
#pragma unroll
                for (int nt = 0; nt < 4; ++nt) {
                    asm volatile(
                        "mma.sync.aligned.m16n8k16.row.col.f32.bf16.bf16.f32 "
                        "{%0,%1,%2,%3}, {%4,%5,%6,%7}, {%8,%9}, {%0,%1,%2,%3};"
                        : "+f"(acc[mt][nt][0]), "+f"(acc[mt][nt][1]),
                          "+f"(acc[mt][nt][2]), "+f"(acc[mt][nt][3])
                        : "r"(a[mt][0]), "r"(a[mt][1]), "r"(a[mt][2]), "r"(a[mt][3]),
                          "r"(b[nt][0]), "r"(b[nt][1]));
                }
        }
        __syncthreads();
        buf = (buf + 1) % SST;
    }

    int g = lane >> 2, tg = lane & 3;
#pragma unroll
    for (int mt = 0; mt < 4; ++mt) {
#pragma unroll
        for (int nt = 0; nt < 4; ++nt) {
            int row = m0 + wm + mt * 16 + g;
            int col = n0 + wn + nt * 8 + tg * 2;
            *(float2*)(C + (size_t)row * N + col) =
                make_float2(acc[mt][nt][0], acc[mt][nt][1]);
            *(float2*)(C + (size_t)(row + 8) * N + col) =
                make_float2(acc[mt][nt][2], acc[mt][nt][3]);
        }
    }
}

// ---------------- fused QKV conv + SiLU + l2norm + kb ---------------------------
__global__ __launch_bounds__(256) void conv_qkvn_kernel(
    const float* __restrict__ x3,
    const float* __restrict__ cq, const float* __restrict__ ck,
    const float* __restrict__ cv, const float* __restrict__ beta,
    float* __restrict__ q, float* __restrict__ k,
    float* __restrict__ kb, float* __restrict__ v, int L)
{
    int t = blockIdx.x;
    int b = t / L, l = t % L;
    int tid = threadIdx.x;
    int lane = tid & 31, wid = tid >> 5;
    int c = tid * 4;

    const float* wp[3] = {cq, ck, cv};
    float4 outv[3];
#pragma unroll
    for (int proj = 0; proj < 3; ++proj) {
        int cOff = proj * 1024 + c;
        float4 xv[4];
#pragma unroll
        for (int kk = 0; kk < 4; ++kk) {
            int ll = l - 3 + kk;
            xv[kk] = (ll >= 0) ? *(const float4*)&x3[((size_t)(b*L + ll))*3072 + cOff]
                               : make_float4(0.f, 0.f, 0.f, 0.f);
        }
        const float* w = wp[proj];
        float4 w0 = *(const float4*)&w[(c+0)*4];
        float4 w1 = *(const float4*)&w[(c+1)*4];
        float4 w2 = *(const float4*)&w[(c+2)*4];
        float4 w3 = *(const float4*)&w[(c+3)*4];
        float4 acc;
        acc.x = xv[0].x*w0.x + xv[1].x*w0.y + xv[2].x*w0.z + xv[3].x*w0.w;
        acc.y = xv[0].y*w1.x + xv[1].y*w1.y + xv[2].y*w1.z + xv[3].y*w1.w;
        acc.z = xv[0].z*w2.x + xv[1].z*w2.y + xv[2].z*w2.z + xv[3].z*w2.w;
        acc.w = xv[0].w*w3.x + xv[1].w*w3.y + xv[2].w*w3.z + xv[3].w*w3.w;
        acc.x = acc.x / (1.f + expf(-acc.x));
        acc.y = acc.y / (1.f + expf(-acc.y));
        acc.z = acc.z / (1.f + expf(-acc.z));
        acc.w = acc.w / (1.f + expf(-acc.w));
        outv[proj] = acc;
    }
    *(float4*)&v[(size_t)t*HID + c] = outv[2];

    float4 qa = outv[0], ka = outv[1];
    float sq = qa.x*qa.x + qa.y*qa.y + qa.z*qa.z + qa.w*qa.w;
    float sk = ka.x*ka.x + ka.y*ka.y + ka.z*ka.z + ka.w*ka.w;
#pragma unroll
    for (int off = 16; off; off >>= 1) {
        sq += __shfl_down_sync(0xffffffff, sq, off);
        sk += __shfl_down_sync(0xffffffff, sk, off);
    }
    __shared__ float pq[8], pk[8];
    if (lane == 0) { pq[wid] = sq; pk[wid] = sk; }
    __syncthreads();
    int h = tid >> 6;
    float sumq = pq[h*2] + pq[h*2+1];
    float sumk = pk[h*2] + pk[h*2+1];
    float rq = rsqrtf(sumq + 1e-6f);
    float rk = rsqrtf(sumk + 1e-6f);
    float bb = beta[t*NH + h];
    float4 qn = make_float4(qa.x*rq, qa.y*rq, qa.z*rq, qa.w*rq);
    float4 kn = make_float4(ka.x*rk, ka.y*rk, ka.z*rk, ka.w*rk);
    float4 kbv = make_float4(kn.x*bb, kn.y*bb, kn.z*bb, kn.w*bb);
    *(float4*)&q [(size_t)t*HID + c] = qn;
    *(float4*)&k [(size_t)t*HID + c] = kn;
    *(float4*)&kb[(size_t)t*HID + c] = kbv;
}

// ---------------- fused FIR conv (short K=5 + long K=64), smem-tiled ------------
__global__ __launch_bounds__(256) void fir_kernel(
    const float* __restrict__ V, const float* __restrict__ fs,
    const float* __restrict__ fl, float* __restrict__ LS,
    float* __restrict__ LL, int L)
{
    __shared__ float xs[127*64];
    int ct = blockIdx.x;
    int tt = blockIdx.y;
    int c0 = ct * 64;
    int t0 = tt * 64;
    int b = t0 / L;
    int l0 = t0 - b * L;
    int tid = threadIdx.x;

    for (int idx = tid; idx < 127*64; idx += 256) {
        int row = idx >> 6, c = idx & 63;
        int l = l0 - 63 + row;
        xs[idx] = (l >= 0) ? V[((size_t)(b*L + l))*HID + c0 + c] : 0.f;
    }

    int c = tid & 63;
    int tg = tid >> 6;
    int cg = c0 + c;
    float wl[64];
#pragma unroll
    for (int kk = 0; kk < 64; ++kk) wl[kk] = fl[cg*64 + kk];
    float ws[5];
#pragma unroll
    for (int kk = 0; kk < 5; ++kk) ws[kk] = fs[cg*5 + kk];
    __syncthreads();

    for (int j = 0; j < 16; ++j) {
        int jj = tg*16 + j;
        float accl = 0.f, accs = 0.f;
#pragma unroll
        for (int kk = 0; kk < 64; ++kk) accl += xs[(jj+kk)*64 + c] * wl[kk];
#pragma unroll
        for (int kk = 0; kk < 5; ++kk) accs += xs[(jj+59+kk)*64 + c] * ws[kk];
        size_t o = ((size_t)(t0 + jj))*HID + cg;
        LL[o] = accl;
        LS[o] = accs;
    }
}

// ---------------- beta ------------------------------------------------------------
__global__ void beta_kernel(const float* __restrict__ hs, const float* __restrict__ Wb,
                            float* __restrict__ beta, int T)
{
    int gw = (blockIdx.x * blockDim.x + threadIdx.x) >> 5;
    int lane = threadIdx.x & 31;
    if (gw >= T * NH) return;
    int t = gw / NH, h = gw % NH;
    float s = 0.f;
    for (int r = lane; r < HID; r += 32) s += hs[(size_t)t*HID + r] * Wb[r*NH + h];
#pragma unroll
    for (int off = 16; off; off >>= 1) s += __shfl_down_sync(0xffffffff, s, off);
    if (lane == 0) beta[t*NH + h] = 1.f / (1.f + expf(-s));
}

// ---------------- per-chunk: attn inversion + u, w, attn_loc --------------------
__global__ __launch_bounds__(256) void chunk_kernel(
    const float* __restrict__ Qn, const float* __restrict__ Kn,
    const float* __restrict__ KB, const float* __restrict__ V,
    const float* __restrict__ beta, float* __restrict__ U,
    float* __restrict__ Wbuf, float* __restrict__ Aloc, int L)
{
    extern __shared__ float sm[];
    float* q_s  = sm;
    float* kn_s = q_s  + 32*QP;
    float* kb_s = kn_s + 32*QP;
    float* A    = kb_s + 32*QP;
    int nch = L / CHUNK;
    int cid = blockIdx.x;
    int ch = cid % nch;
    int h  = (cid / nch) & (NH - 1);
    int b  = cid / (nch * NH);
    int l0 = ch * CHUNK;
    int tid = threadIdx.x;
    int lane = tid & 31;
    int iw = tid >> 5;
    size_t base = ((size_t)(b*L + l0)) * HID + h*DK;

    for (int r = 0; r < 32; ++r) {
        size_t g = base + (size_t)r*HID + tid;
        q_s [r*QP + tid] = Qn[g];
        kn_s[r*QP + tid] = Kn[g];
        kb_s[r*QP + tid] = KB[g];
    }
    __syncthreads();

    size_t abase = (size_t)cid * (CHUNK*CHUNK);
#pragma unroll
    for (int r = 0; r < 4; ++r) {
        int i = r*8 + iw, j = lane;
        float sA = 0.f, sL = 0.f;
#pragma unroll 8
        for (int dq = 0; dq < 64; ++dq) {
            float4 kn = *(float4*)&kn_s[j*QP + dq*4];
            float4 kbv = *(float4*)&kb_s[i*QP + dq*4];
            float4 qv = *(float4*)&q_s [i*QP + dq*4];
            sA += kbv.x*kn.x + kbv.y*kn.y + kbv.z*kn.z + kbv.w*kn.w;
            sL += qv.x*kn.x + qv.y*kn.y + qv.z*kn.z + qv.w*kn.w;
        }
        A[i*KTP + j] = (i > j) ? -sA : 0.f;
        Aloc[abase + i*32 + j] = (j <= i) ? sL : 0.f;
    }
    __syncthreads();

    if (tid < 32) {
        int j = tid;
        for (int i = 1; i < 32; ++i) {
            float s = 0.f;
            if (j < i) {
#pragma unroll
                for (int t2 = 0; t2 < 32; ++t2) s += A[i*KTP + t2] * A[t2*KTP + j];
            }
            __syncwarp();
            if (j < i) A[i*KTP + j] += s;
            __syncwarp();
        }
        A[j*KTP + j] += 1.f;
    }
    __syncthreads();

    for (int r = 0; r < 32; ++r) {
        float bb = beta[(b*L + l0 + r)*NH + h];
        q_s[r*QP + tid] = V[base + (size_t)r*HID + tid] * bb;
    }
    __syncthreads();

    float vc[32], kc[32];
#pragma unroll
    for (int t2 = 0; t2 < 32; ++t2) {
        vc[t2] = q_s [t2*QP + tid];
        kc[t2] = kb_s[t2*QP + tid];
    }

    for (int i = 0; i < 32; ++i) {
        float su = 0.f, sw = 0.f;
#pragma unroll
        for (int qq = 0; qq < 8; ++qq) {
            float4 a = *(float4*)&A[i*KTP + qq*4];
            su += a.x*vc[qq*4] + a.y*vc[qq*4+1] + a.z*vc[qq*4+2] + a.w*vc[qq*4+3];
            sw += a.x*kc[qq*4] + a.y*kc[qq*4+1] + a.z*kc[qq*4+2] + a.w*kc[qq*4+3];
        }
        U   [base + (size_t)i*HID + tid] = su;
        Wbuf[base + (size_t)i*HID + tid] = sw;
    }
}

// ---------------- sequential chunk scan: 128 CTAs, 16 cols each -----------------
__global__ __launch_bounds__(256) void scan_kernel(
    const float* __restrict__ Qn, const float* __restrict__ Kn,
    const float* __restrict__ U,  const float* __restrict__ Wbuf,
    const float* __restrict__ Aloc, float* __restrict__ Dout, int L)
{
    extern __shared__ float sm[];
    float* Ssm_t = sm;
    float* q_s   = Ssm_t + NC*QP;
    float* w_s   = q_s   + 32*QP;
    float* k_t   = w_s   + 32*QP;
    float* al    = k_t   + 256*KTP;
    float* ul_t  = al    + 32*KTP;

    int cb = blockIdx.x;
    int bh = blockIdx.y;
    int b = bh >> 2, h = bh & 3;
    int tid = threadIdx.x;
    int c  = tid & (NC - 1);
    int gi = tid >> 4;
    int nch = L / CHUNK;

    float Sreg[16];
#pragma unroll
    for (int r = 0; r < 16; ++r) Sreg[r] = 0.f;

    for (int ch = 0; ch < nch; ++ch) {
        int l0 = ch * CHUNK;
        size_t base = ((size_t)(b*L + l0)) * HID + h*DK;

#pragma unroll
        for (int r = 0; r < 16; ++r) Ssm_t[c*QP + r*16 + gi] = Sreg[r];
        for (int r = 0; r < 32; ++r) {
            size_t g = base + (size_t)r*HID + tid;
            q_s[r*QP + tid] = Qn[g];
            w_s[r*QP + tid] = Wbuf[g];
            k_t[tid*KTP + r] = Kn[g];
        }
        size_t abase = (size_t)((b*NH + h)*nch + ch) * 1024;
#pragma unroll
        for (int e0 = 0; e0 < 4; ++e0) {
            int e = e0*256 + tid;
            al[(e >> 5)*KTP + (e & 31)] = Aloc[abase + e];
        }

        float uacc[2], oacc[2] = {0.f, 0.f};
#pragma unroll
        for (int r2 = 0; r2 < 2; ++r2)
            uacc[r2] = U[((size_t)(b*L + l0 + (r2*16 + gi)))*HID + h*DV + cb*NC + c];
        __syncthreads();

#pragma unroll 4
        for (int dq = 0; dq < 64; ++dq) {
            float4 sv = *(float4*)&Ssm_t[c*QP + dq*4];
#pragma unroll
            for (int r2 = 0; r2 < 2; ++r2) {
                int i = r2*16 + gi;
                float4 wv = *(float4*)&w_s[i*QP + dq*4];
                float4 qv = *(float4*)&q_s[i*QP + dq*4];
                uacc[r2] -= wv.x*sv.x + wv.y*sv.y + wv.z*sv.z + wv.w*sv.w;
                oacc[r2] += qv.x*sv.x + qv.y*sv.y + qv.z*sv.z + qv.w*sv.w;
            }
        }
#pragma unroll
        for (int r2 = 0; r2 < 2; ++r2) ul_t[c*KTP + r2*16 + gi] = uacc[r2];
        __syncthreads();

        float ulreg[32];
#pragma unroll
        for (int qq = 0; qq < 8; ++qq) {
            float4 t4 = *(float4*)&ul_t[c*KTP + qq*4];
            ulreg[qq*4] = t4.x; ulreg[qq*4+1] = t4.y;
            ulreg[qq*4+2] = t4.z; ulreg[qq*4+3] = t4.w;
        }

#pragma unroll
        for (int qq = 0; qq < 8; ++qq) {
#pragma unroll
            for (int r2 = 0; r2 < 2; ++r2) {
                int i = r2*16 + gi;
                float4 av = *(float4*)&al[i*KTP + qq*4];
                oacc[r2] += av.x*ulreg[qq*4] + av.y*ulreg[qq*4+1]
                          + av.z*ulreg[qq*4+2] + av.w*ulreg[qq*4+3];
            }
        }
#pragma unroll
        for (int r2 = 0; r2 < 2; ++r2)
            Dout[((size_t)(b*L + l0 + (r2*16 + gi)))*HID + h*DV + cb*NC + c] = oacc[r2];

#pragma unroll
        for (int qq = 0; qq < 8; ++qq) {
#pragma unroll
            for (int r = 0; r < 16; ++r) {
                float4 kv = *(float4*)&k_t[(r*16 + gi)*KTP + qq*4];
                Sreg[r] += kv.x*ulreg[qq*4] + kv.y*ulreg[qq*4+1]
                         + kv.z*ulreg[qq*4+2] + kv.w*ulreg[qq*4+3];
            }
        }
        __syncthreads();
    }
}

// ---------------- fused stats + gate MLP + softmax + mix + RMSNorm + split ------
// grid = T; block = 256. thread: h = tid>>6, 4 channels (tid&63)*4 within head.
__global__ __launch_bounds__(256) void gsm_kernel(
    const float* __restrict__ LS, const float* __restrict__ LL,
    const float* __restrict__ DEL, const float* __restrict__ V,
    const float* __restrict__ G1,
    const float* __restrict__ w1, const float* __restrict__ b1,
    const float* __restrict__ w2, const float* __restrict__ b2,
    const float* __restrict__ lt, const float* __restrict__ onw,
    __nv_bfloat16* __restrict__ A2)
{
    int t = blockIdx.x;
    int tid = threadIdx.x;
    int lane = tid & 31, wid = tid >> 5;
    int h = tid >> 6;
    int cin = (tid & 63) * 4;          // channel within head

    size_t base = (size_t)t*1024 + h*256 + cin;
    float4 xs0 = *(const float4*)&LS [base];
    float4 xs1 = *(const float4*)&LL [base];
    float4 xs2 = *(const float4*)&DEL[base];
    float4 xs3 = *(const float4*)&V  [base];

    // ---- stats: per warp partials (warps 2h,2h+1 cover head h) ----
    __shared__ float wstat[8][12];
    {
        float4 xs[4] = {xs0, xs1, xs2, xs3};
#pragma unroll
        for (int sig = 0; sig < 4; ++sig) {
            float4 x = xs[sig];
            float s1 = x.x + x.y + x.z + x.w;
            float s2 = x.x*x.x + x.y*x.y + x.z*x.z + x.w*x.w;
            float s3 = fabsf(x.x) + fabsf(x.y) + fabsf(x.z) + fabsf(x.w);
#pragma unroll
            for (int off = 16; off; off >>= 1) {
                s1 += __shfl_down_sync(0xffffffff, s1, off);
                s2 += __shfl_down_sync(0xffffffff, s2, off);
                s3 += __shfl_down_sync(0xffffffff, s3, off);
            }
            if (lane == 0) {
                wstat[wid][sig*3+0] = s1;
                wstat[wid][sig*3+1] = s2;
                wstat[wid][sig*3+2] = s3;
            }
        }
    }
    __syncthreads();

    __shared__ float st[4][16];
    if (tid < 64) {
        int hh = tid >> 4, idx = tid & 15, sig = idx >> 2, which = idx & 3;
        float s1 = wstat[hh*2][sig*3+0] + wstat[hh*2+1][sig*3+0];
        float s2 = wstat[hh*2][sig*3+1] + wstat[hh*2+1][sig*3+1];
        float s3 = wstat[hh*2][sig*3+2] + wstat[hh*2+1][sig*3+2];
        float mean = s1 / 256.f;
        float val;
        if (which == 0)      val = mean;
        else if (which == 1) val = s2 / 256.f - mean*mean;
        else if (which == 2) val = s3 / 256.f;
        else                 val = sqrtf(s2);
        st[hh][idx] = val;
    }
    __syncthreads();

    // ---- MLP (shared w1/w2/g1 loads across 4 heads) ----
    float p[4][4];
#pragma unroll
    for (int hh = 0; hh < 4; ++hh)
#pragma unroll
        for (int cc = 0; cc < 4; ++cc) p[hh][cc] = 0.f;

#pragma unroll
    for (int jj = 0; jj < 4; ++jj) {
        int j = jj*256 + tid;
        float xb = G1[(size_t)t*1024 + j] + b1[j];
        float w1v[16];
#pragma unroll
        for (int s = 0; s < 16; ++s) w1v[s] = w1[(size_t)(1024 + s)*1024 + j];
        float4 w2v = *(const float4*)&w2[j*4];
#pragma unroll
        for (int hh = 0; hh < 4; ++hh) {
            float x = xb;
#pragma unroll
            for (int s = 0; s < 16; ++s) x += st[hh][s] * w1v[s];
            float g = 0.5f * x * (1.f + erff(x * 0.70710678118654752f));
            p[hh][0] += g * w2v.x; p[hh][1] += g * w2v.y;
            p[hh][2] += g * w2v.z; p[hh][3] += g * w2v.w;
        }
    }
    // reduce 16 accumulators
#pragma unroll
    for (int hh = 0; hh < 4; ++hh)
#pragma unroll
        for (int cc = 0; cc < 4; ++cc) {
            float vsum = p[hh][cc];
#pragma unroll
            for (int off = 16; off; off >>= 1)
                vsum += __shfl_down_sync(0xffffffff, vsum, off);
            p[hh][cc] = vsum;
        }
    __shared__ float red[8][16];
    if (lane == 0) {
#pragma unroll
        for (int hh = 0; hh < 4; ++hh)
#pragma unroll
            for (int cc = 0; cc < 4; ++cc) red[wid][hh*4+cc] = p[hh][cc];
    }
    __syncthreads();

    __shared__ float probs[4][4];
    if (tid < 4) {
        float l[4];
#pragma unroll
        for (int cc = 0; cc < 4; ++cc) {
            float s = 0.f;
#pragma unroll
            for (int wdx = 0; wdx < 8; ++wdx) s += red[wdx][tid*4+cc];
            l[cc] = s + b2[cc];
        }
        float inv_t = expf(-lt[tid]);
#pragma unroll
        for (int cc = 0; cc < 4; ++cc) l[cc] *= inv_t;
        float m = fmaxf(fmaxf(l[0], l[1]), fmaxf(l[2], l[3]));
        float e[4], ssum = 0.f;
#pragma unroll
        for (int cc = 0; cc < 4; ++cc) { e[cc] = expf(l[cc] - m); ssum += e[cc]; }
#pragma unroll
        for (int cc = 0; cc < 4; ++cc) probs[tid][cc] = 0.05f + 0.8f * (e[cc] / ssum);
    }
    __syncthreads();

    // ---- mix + RMSNorm + bf16 split ----
    float p0 = probs[h][0], p1 = probs[h][1], p2 = probs[h][2], p3 = probs[h][3];
    float4 o;
    o.x = p0*xs0.x + p1*xs1.x + p2*xs2.x + p3*xs3.x;
    o.y = p0*xs0.y + p1*xs1.y + p2*xs2.y + p3*xs3.y;
    o.z = p0*xs0.z + p1*xs1.z + p2*xs2.z + p3*xs3.z;
    o.w = p0*xs0.w + p1*xs1.w + p2*xs2.w + p3*xs3.w;
    float sq = o.x*o.x + o.y*o.y + o.z*o.z + o.w*o.w;
#pragma unroll
    for (int off = 16; off; off >>= 1) sq += __shfl_down_sync(0xffffffff, sq, off);
    __shared__ float psq[8];
    if (lane == 0) psq[wid] = sq;
    __syncthreads();
    float ms = (psq[h*2] + psq[h*2+1]) / 256.f;
    float r = rsqrtf(ms + 1e-5f);
    float4 ow = *(const float4*)&onw[cin];
    float ov[4] = {o.x*r*ow.x, o.y*r*ow.y, o.z*r*ow.z, o.w*r*ow.w};

    int kk = h*256 + cin;
    __nv_bfloat16 hib[4]; float lob[4];
#pragma unroll
    for (int i = 0; i < 4; ++i) {
        hib[i] = __float2bfloat16(ov[i]);
        lob[i] = ov[i] - __bfloat162float(hib[i]);
    }
    *(uint2*)&A2[(size_t)t*2048 + kk] = *(uint2*)hib;
    __nv_bfloat16 lo16[4];
#pragma unroll
    for (int i = 0; i < 4; ++i) lo16[i] = __float2bfloat16(lob[i]);
    *(uint2*)&A2[(size_t)t*2048 + 1024 + kk] = *(uint2*)lo16;
}

// ---------------- launch ----------------------------------------------------------
extern "C" void kernel_launch(void* const* d_in, const int* in_sizes, int n_in,
                              void* d_out, int out_size)
{
    const float* hs = (const float*)d_in[0];
    const float* Wq = (const float*)d_in[1];
    const float* Wk = (const float*)d_in[2];
    const float* Wv = (const float*)d_in[3];
    const float* Wb = (const float*)d_in[4];
    const float* cq = (const float*)d_in[5];
    const float* ck = (const float*)d_in[6];
    const float* cv = (const float*)d_in[7];
    const float* fs = (const float*)d_in[8];
    const float* fl = (const float*)d_in[9];
    const float* w1 = (const float*)d_in[10];
    const float* b1 = (const float*)d_in[11];
    const float* w2 = (const float*)d_in[12];
    const float* b2 = (const float*)d_in[13];
    const float* lt = (const float*)d_in[14];
    const float* onw= (const float*)d_in[15];
    const float* Wo = (const float*)d_in[16];

    const int T = in_sizes[0] / HID;
    const int B = 2;
    const int L = T / B;

    float *tmp3, *q, *k, *v, *kb, *u, *w, *del, *ls, *ll, *g1, *aloc, *beta;
    __nv_bfloat16 *a2, *bth, *btl, *bthg, *btlg, *btho, *btlo;
    cudaGetSymbolAddress((void**)&tmp3, g_tmp3);
    cudaGetSymbolAddress((void**)&q,    g_q);
    cudaGetSymbolAddress((void**)&k,    g_k);
    cudaGetSymbolAddress((void**)&v,    g_v);
    cudaGetSymbolAddress((void**)&kb,   g_kb);
    cudaGetSymbolAddress((void**)&u,    g_u);
    cudaGetSymbolAddress((void**)&w,    g_w);
    cudaGetSymbolAddress((void**)&del,  g_del);
    cudaGetSymbolAddress((void**)&ls,   g_ls);
    cudaGetSymbolAddress((void**)&ll,   g_ll);
    cudaGetSymbolAddress((void**)&g1,   g_g1);
    cudaGetSymbolAddress((void**)&aloc, g_aloc);
    cudaGetSymbolAddress((void**)&beta, g_beta);
    cudaGetSymbolAddress((void**)&a2,   g_a2);
    cudaGetSymbolAddress((void**)&bth,  g_bth);
    cudaGetSymbolAddress((void**)&btl,  g_btl);
    cudaGetSymbolAddress((void**)&bthg, g_bthg);
    cudaGetSymbolAddress((void**)&btlg, g_btlg);
    cudaGetSymbolAddress((void**)&btho, g_btho);
    cudaGetSymbolAddress((void**)&btlo, g_btlo);

    static cudaStream_t s1 = 0, s2 = 0, s3 = 0;
    static cudaEvent_t evS = 0, evA = 0, evQ = 0, evB = 0, evF = 0, evG = 0, evW = 0;
    if (!s1) {
        cudaStreamCreateWithFlags(&s1, cudaStreamNonBlocking);
        cudaStreamCreateWithFlags(&s2, cudaStreamNonBlocking);
        cudaStreamCreateWithFlags(&s3, cudaStreamNonBlocking);
        cudaEventCreateWithFlags(&evS, cudaEventDisableTiming);
        cudaEventCreateWithFlags(&evA, cudaEventDisableTiming);
        cudaEventCreateWithFlags(&evQ, cudaEventDisableTiming);
        cudaEventCreateWithFlags(&evB, cudaEventDisableTiming);
        cudaEventCreateWithFlags(&evF, cudaEventDisableTiming);
        cudaEventCreateWithFlags(&evG, cudaEventDisableTiming);
        cudaEventCreateWithFlags(&evW, cudaEventDisableTiming);
    }

    dim3 bt_grid(HID/32, HID/32);
    dim3 bt_blk(32, 8);
    int nsplit = (T*HID + 255) / 256;

    const int GEMM_SMEM = SST * GSTAGE;
    cudaFuncSetAttribute(gemm_mma, cudaFuncAttributeMaxDynamicSharedMemorySize, GEMM_SMEM);
    size_t chunk_smem = (size_t)(3*32*QP + 32*KTP) * 4;
    size_t scan_smem  = (size_t)(NC*QP + 2*32*QP + 256*KTP + 32*KTP + NC*KTP) * 4;
    cudaFuncSetAttribute(chunk_kernel, cudaFuncAttributeMaxDynamicSharedMemorySize, (int)chunk_smem);
    cudaFuncSetAttribute(scan_kernel,  cudaFuncAttributeMaxDynamicSharedMemorySize, (int)scan_smem);

    // ---- fork point at graph start ----
    cudaEventRecord(evS, 0);

    // ---- s3: beta (needs only hs) ----
    cudaStreamWaitEvent(s3, evS, 0);
    beta_kernel<<<(T*NH + 7) / 8, 256, 0, s3>>>(hs, Wb, beta, T);
    cudaEventRecord(evB, s3);

    // ---- s2: QKV weight splits (independent of asplit) ----
    cudaStreamWaitEvent(s2, evS, 0);
    bsplit_kernel<<<bt_grid, bt_blk, 0, s2>>>(Wq, bth,             btl,             HID, HID);
    bsplit_kernel<<<bt_grid, bt_blk, 0, s2>>>(Wk, bth + HID*HID,   btl + HID*HID,   HID, HID);
    bsplit_kernel<<<bt_grid, bt_blk, 0, s2>>>(Wv, bth + 2*HID*HID, btl + 2*HID*HID, HID, HID);
    cudaEventRecord(evW, s2);

    // ---- stream0: split hs ----
    asplit_kernel<<<nsplit, 256>>>(hs, a2, HID, T*HID);
    cudaEventRecord(evA, 0);

    // ---- s1: gate GEMM chain + Wo split ----
    cudaStreamWaitEvent(s1, evS, 0);
    bsplit_kernel<<<bt_grid, bt_blk, 0, s1>>>(w1, bthg, btlg, HID, HID);
    cudaStreamWaitEvent(s1, evA, 0);
    {
        dim3 gg(HID/BN, T/BM);
        gemm_mma<<<gg, 256, GEMM_SMEM, s1>>>(a2, bthg, btlg, g1, T, HID, HID);
    }
    bsplit_kernel<<<bt_grid, bt_blk, 0, s1>>>(Wo, btho, btlo, HID, HID);
    cudaEventRecord(evG, s1);

    // ---- stream0: QKV GEMM + fused conv/norm ----
    cudaStreamWaitEvent(0, evW, 0);
    {
        dim3 gg(3*HID/BN, T/BM);
        gemm_mma<<<gg, 256, GEMM_SMEM>>>(a2, bth, btl, tmp3, T, 3*HID, HID);
    }
    cudaStreamWaitEvent(0, evB, 0);
    conv_qkvn_kernel<<<T, 256>>>(tmp3, cq, ck, cv, beta, q, k, kb, v, L);
    cudaEventRecord(evQ, 0);

    // ---- s2: FIR (needs v) ----
    cudaStreamWaitEvent(s2, evQ, 0);
    fir_kernel<<<dim3(HID/64, T/64), 256, 0, s2>>>(v, fs, fl, ls, ll, L);
    cudaEventRecord(evF, s2);

    // ---- stream0: delta path ----
    chunk_kernel<<<B*NH*(L/CHUNK), 256, chunk_smem>>>(q, k, kb, v, beta, u, w, aloc, L);
    scan_kernel<<<dim3(DV/NC, B*NH), 256, scan_smem>>>(q, k, u, w, aloc, del, L);

    // ---- join + fused epilogue ----
    cudaStreamWaitEvent(0, evF, 0);
    cudaStreamWaitEvent(0, evG, 0);
    gsm_kernel<<<T, 256>>>(ls, ll, del, v, g1, w1, b1, w2, b2, lt, onw, a2);
    {
        dim3 gg(HID/BN, T/BM);
        gemm_mma<<<gg, 256, GEMM_SMEM>>>(a2, btho, btlo, (float*)d_out, T, HID, HID);
    }
}